// round 6
// baseline (speedup 1.0000x reference)
#include <cuda_runtime.h>
#include <cuda_bf16.h>
#include <math.h>
#include <stdint.h>

// ---------------- problem constants ----------------
#define Bc 4
#define Sc 4096
#define Dc 1024
#define Hc 16
#define Dhc 64
#define Ec 256
#define Fc 4096
#define NBc 64
#define CHUNKc 128
#define Mrows (Bc * Sc)          // 16384
#define QKVW (3 * Hc * Dhc)      // 3072
#define NCHUNK (Sc / CHUNKc)     // 32

// ---------------- scratch (device globals; no allocations allowed) ----------------
__device__ float g_bufH[(size_t)Mrows * Dc];
__device__ float g_bufE[(size_t)Mrows * Ec];
__device__ float g_bufG[(size_t)Mrows * Dc];
__device__ float g_bufXA[(size_t)Mrows * Dc];
__device__ float g_bufQKV[(size_t)Mrows * QKVW];
__device__ float g_bufATT[(size_t)Mrows * Dc];
__device__ float g_bufT[(size_t)Mrows * Dc];
__device__ float g_bufX1[(size_t)Mrows * Dc];
__device__ float g_bufF[(size_t)Mrows * Fc];
__device__ int g_buckets[Bc * Hc * Sc];
__device__ int g_idx[Bc * Hc * Sc];
__device__ int g_bsort[Bc * Hc * Sc];

// ---------------- activations ----------------
enum { ACT_NONE = 0, ACT_SILU = 1, ACT_GELU = 2, ACT_SIGMOID = 3 };

template <int ACT>
__device__ __forceinline__ float apply_act(float x) {
    if (ACT == ACT_SILU) return x / (1.f + __expf(-x));
    if (ACT == ACT_GELU) {
        float t = tanhf(0.7978845608028654f * (x + 0.044715f * x * x * x));
        return 0.5f * x * (1.f + t);
    }
    if (ACT == ACT_SIGMOID) return 1.f / (1.f + __expf(-x));
    return x;
}

// ---------------- mma.sync m16n8k16 bf16 (base-target legal; no tcgen05) ----------------
__device__ __forceinline__ void mma16816(float* c, const uint32_t* a, const uint32_t* b) {
    asm volatile(
        "mma.sync.aligned.m16n8k16.row.col.f32.bf16.bf16.f32 "
        "{%0,%1,%2,%3}, {%4,%5,%6,%7}, {%8,%9}, {%0,%1,%2,%3};"
        : "+f"(c[0]), "+f"(c[1]), "+f"(c[2]), "+f"(c[3])
        : "r"(a[0]), "r"(a[1]), "r"(a[2]), "r"(a[3]), "r"(b[0]), "r"(b[1]));
}

// ============ bf16x3 tensor GEMM: C[M,N] = act(A @ B + bias) ============
// Block tile 128x128, BK=32. 256 threads = 8 warps, warp tile 64x32.
// A[row-major, lda=K], B[K x N row-major, ldb]. fp32 operands split hi/lo bf16;
// per logical mma we issue 3 HMMAs: aH*bH + aH*bL + aL*bH (err ~1.5e-5).
#define BG_SK 40  // smem k-stride in bf16 elems (padded; conflict-free frags)

template <int ACT>
__global__ __launch_bounds__(256, 2) void bgemm_kernel(
    const float* __restrict__ A, const float* __restrict__ B,
    const float* __restrict__ bias, float* __restrict__ C,
    int K, int ldb, int ldc)
{
    __shared__ __align__(16) __nv_bfloat16 As_hi[128][BG_SK];
    __shared__ __align__(16) __nv_bfloat16 As_lo[128][BG_SK];
    __shared__ __align__(16) __nv_bfloat16 Bs_hi[128][BG_SK];
    __shared__ __align__(16) __nv_bfloat16 Bs_lo[128][BG_SK];

    int tid = threadIdx.x;
    int wid = tid >> 5, lane = tid & 31;
    int n0 = blockIdx.x * 128;
    int row0 = blockIdx.y * 128;
    int wm = (wid & 1) * 64;   // warp m offset
    int wn = (wid >> 1) * 32;  // warp n offset
    int lr = lane >> 2;        // fragment row within 8
    int lc = (lane & 3) * 2;   // fragment k/col pair base

    float acc[4][4][4];
#pragma unroll
    for (int mt = 0; mt < 4; mt++)
#pragma unroll
        for (int nt = 0; nt < 4; nt++)
#pragma unroll
            for (int e = 0; e < 4; e++) acc[mt][nt][e] = 0.f;

    const float* Ab = A + (size_t)row0 * K;
    const float* Bb = B + n0;

    for (int k0 = 0; k0 < K; k0 += 32) {
        // ---- stage A: 128 rows x 32 k, fp32 -> hi/lo bf16 ----
#pragma unroll
        for (int it = 0; it < 4; it++) {
            int idx = it * 256 + tid;          // 1024 float4 slots
            int r = idx >> 3, c4 = (idx & 7) << 2;
            float4 v = *(const float4*)(Ab + (size_t)r * K + k0 + c4);
            float vv[4] = {v.x, v.y, v.z, v.w};
            __nv_bfloat16 h[4], l[4];
#pragma unroll
            for (int j = 0; j < 4; j++) {
                h[j] = __float2bfloat16(vv[j]);
                l[j] = __float2bfloat16(vv[j] - __bfloat162float(h[j]));
            }
            *(uint2*)&As_hi[r][c4] = *(uint2*)h;
            *(uint2*)&As_lo[r][c4] = *(uint2*)l;
        }
        // ---- stage B transposed: smem[n][k] from global [k][n] ----
#pragma unroll
        for (int it = 0; it < 4; it++) {
            int idx = it * 256 + tid;
            int k = idx >> 5, n4 = (idx & 31) << 2;
            float4 v = *(const float4*)(Bb + (size_t)(k0 + k) * ldb + n4);
            float vv[4] = {v.x, v.y, v.z, v.w};
#pragma unroll
            for (int j = 0; j < 4; j++) {
                __nv_bfloat16 h = __float2bfloat16(vv[j]);
                __nv_bfloat16 l = __float2bfloat16(vv[j] - __bfloat162float(h));
                Bs_hi[n4 + j][k] = h;
                Bs_lo[n4 + j][k] = l;
            }
        }
        __syncthreads();

        // ---- compute: 2 k16 steps ----
#pragma unroll
        for (int kt = 0; kt < 32; kt += 16) {
            uint32_t bh[4][2], bl[4][2];
#pragma unroll
            for (int nt = 0; nt < 4; nt++) {
                int n = wn + nt * 8 + lr;
                bh[nt][0] = *(const uint32_t*)&Bs_hi[n][kt + lc];
                bh[nt][1] = *(const uint32_t*)&Bs_hi[n][kt + lc + 8];
                bl[nt][0] = *(const uint32_t*)&Bs_lo[n][kt + lc];
                bl[nt][1] = *(const uint32_t*)&Bs_lo[n][kt + lc + 8];
            }
#pragma unroll
            for (int mt = 0; mt < 4; mt++) {
                int r = wm + mt * 16 + lr;
                uint32_t ah[4], al[4];
                ah[0] = *(const uint32_t*)&As_hi[r][kt + lc];
                ah[1] = *(const uint32_t*)&As_hi[r + 8][kt + lc];
                ah[2] = *(const uint32_t*)&As_hi[r][kt + lc + 8];
                ah[3] = *(const uint32_t*)&As_hi[r + 8][kt + lc + 8];
                al[0] = *(const uint32_t*)&As_lo[r][kt + lc];
                al[1] = *(const uint32_t*)&As_lo[r + 8][kt + lc];
                al[2] = *(const uint32_t*)&As_lo[r][kt + lc + 8];
                al[3] = *(const uint32_t*)&As_lo[r + 8][kt + lc + 8];
#pragma unroll
                for (int nt = 0; nt < 4; nt++) {
                    mma16816(acc[mt][nt], ah, bh[nt]);
                    mma16816(acc[mt][nt], ah, bl[nt]);
                    mma16816(acc[mt][nt], al, bh[nt]);
                }
            }
        }
        __syncthreads();
    }

    // ---- epilogue ----
#pragma unroll
    for (int mt = 0; mt < 4; mt++) {
        int row = row0 + wm + mt * 16 + lr;
#pragma unroll
        for (int nt = 0; nt < 4; nt++) {
            int col = n0 + wn + nt * 8 + lc;
            float b0 = bias[col], b1 = bias[col + 1];
            float2 o0, o1;
            o0.x = apply_act<ACT>(acc[mt][nt][0] + b0);
            o0.y = apply_act<ACT>(acc[mt][nt][1] + b1);
            o1.x = apply_act<ACT>(acc[mt][nt][2] + b0);
            o1.y = apply_act<ACT>(acc[mt][nt][3] + b1);
            *(float2*)(C + (size_t)row * ldc + col) = o0;
            *(float2*)(C + (size_t)(row + 8) * ldc + col) = o1;
        }
    }
}

// ---------------- fp32 SGEMM (bucket-exact path): C = act(A @ B + bias) ----------------
template <int ACT>
__global__ __launch_bounds__(256, 2) void sgemm_kernel(
    const float* __restrict__ A, const float* __restrict__ B,
    const float* __restrict__ bias, float* __restrict__ C,
    int M, int N, int K, int ldb, int ldc)
{
    __shared__ __align__(16) float As[16][132];
    __shared__ __align__(16) float Bs[16][128];
    int tid = threadIdx.x;
    int col0 = blockIdx.x * 128;
    int row0 = blockIdx.y * 128;
    int ty = tid >> 4, tx = tid & 15;

    float acc[8][8];
#pragma unroll
    for (int i = 0; i < 8; i++)
#pragma unroll
        for (int j = 0; j < 8; j++) acc[i][j] = 0.f;

    const float* Ablk = A + (size_t)row0 * K;
    const float* Bblk = B + col0;

    for (int k0 = 0; k0 < K; k0 += 16) {
#pragma unroll
        for (int t = 0; t < 2; t++) {
            int la = tid + t * 256;
            int ar = la >> 2, ac = (la & 3) << 2;
            float4 av = *(const float4*)(Ablk + (size_t)ar * K + k0 + ac);
            As[ac + 0][ar] = av.x;
            As[ac + 1][ar] = av.y;
            As[ac + 2][ar] = av.z;
            As[ac + 3][ar] = av.w;
            int br = la >> 5, bc = (la & 31) << 2;
            *(float4*)&Bs[br][bc] = *(const float4*)(Bblk + (size_t)(k0 + br) * ldb + bc);
        }
        __syncthreads();
#pragma unroll
        for (int kk = 0; kk < 16; kk++) {
            float ra[8], rb[8];
            *(float4*)(ra) = *(const float4*)&As[kk][ty * 8];
            *(float4*)(ra + 4) = *(const float4*)&As[kk][ty * 8 + 4];
            *(float4*)(rb) = *(const float4*)&Bs[kk][tx * 8];
            *(float4*)(rb + 4) = *(const float4*)&Bs[kk][tx * 8 + 4];
#pragma unroll
            for (int i = 0; i < 8; i++)
#pragma unroll
                for (int j = 0; j < 8; j++) acc[i][j] += ra[i] * rb[j];
        }
        __syncthreads();
    }

#pragma unroll
    for (int i = 0; i < 8; i++) {
        size_t r = (size_t)row0 + ty * 8 + i;
#pragma unroll
        for (int j = 0; j < 8; j += 4) {
            int c = col0 + tx * 8 + j;
            float4 o;
            o.x = apply_act<ACT>(acc[i][j + 0] + bias[c + 0]);
            o.y = apply_act<ACT>(acc[i][j + 1] + bias[c + 1]);
            o.z = apply_act<ACT>(acc[i][j + 2] + bias[c + 2]);
            o.w = apply_act<ACT>(acc[i][j + 3] + bias[c + 3]);
            *(float4*)(C + r * ldc + c) = o;
        }
    }
}

// ---------------- time_elapsic helpers ----------------
__global__ void build_h_kernel(const float* __restrict__ x,
                               const float* __restrict__ premix,
                               float* __restrict__ out)
{
    size_t i4 = (size_t)blockIdx.x * blockDim.x + threadIdx.x;
    size_t base = i4 * 4;
    int d = (int)(base & (Dc - 1));
    int row = (int)(base >> 10);
    int s = row & (Sc - 1);
    float4 xv = *(const float4*)(x + base);
    float4 pv = (s > 0) ? *(const float4*)(x + base - Dc) : make_float4(0.f, 0.f, 0.f, 0.f);
    float4 pm = *(const float4*)(premix + d);
    float4 o;
    o.x = xv.x + (pv.x - xv.x) * pm.x;
    o.y = xv.y + (pv.y - xv.y) * pm.y;
    o.z = xv.z + (pv.z - xv.z) * pm.z;
    o.w = xv.w + (pv.w - xv.w) * pm.w;
    *(float4*)(out + base) = o;
}

__global__ void combine_kernel(const float* __restrict__ x,
                               const float* __restrict__ gate,
                               float* __restrict__ out)
{
    size_t i4 = (size_t)blockIdx.x * blockDim.x + threadIdx.x;
    size_t base = i4 * 4;
    int row = (int)(base >> 10);
    int s = row & (Sc - 1);
    float4 xv = *(const float4*)(x + base);
    float4 pv = (s > 0) ? *(const float4*)(x + base - Dc) : make_float4(0.f, 0.f, 0.f, 0.f);
    float4 gv = *(const float4*)(gate + base);
    float4 o;
    o.x = xv.x + (pv.x - xv.x) * gv.x;
    o.y = xv.y + (pv.y - xv.y) * gv.y;
    o.z = xv.z + (pv.z - xv.z) * gv.z;
    o.w = xv.w + (pv.w - xv.w) * gv.w;
    *(float4*)(out + base) = o;
}

// ---------------- LSH hashing ----------------
__global__ void hash_kernel(const float* __restrict__ qkv,
                            const float* __restrict__ rot,
                            int* __restrict__ buckets)
{
    int bh = blockIdx.y;
    int b = bh >> 4, h = bh & 15;
    int s = blockIdx.x * 128 + threadIdx.x;
    __shared__ float rotS[Dhc * 32];
    for (int i = threadIdx.x; i < Dhc * 32; i += 128) rotS[i] = rot[h * (Dhc * 32) + i];
    __syncthreads();
    const float* kp = qkv + ((size_t)(b * Sc + s) * QKVW) + (Hc + h) * Dhc;
    float r[32];
#pragma unroll
    for (int n = 0; n < 32; n++) r[n] = 0.f;
    for (int d = 0; d < Dhc; d++) {
        float kd = kp[d];
#pragma unroll
        for (int n = 0; n < 32; n++) r[n] += kd * rotS[d * 32 + n];
    }
    float best = r[0];
    int bi = 0;
#pragma unroll
    for (int n = 1; n < 32; n++)
        if (r[n] > best) { best = r[n]; bi = n; }
#pragma unroll
    for (int n = 0; n < 32; n++)
        if (-r[n] > best) { best = -r[n]; bi = 32 + n; }
    buckets[(size_t)bh * Sc + s] = bi;
}

// ---------------- stable counting sort per (b,h) row ----------------
__global__ void sort_kernel(const int* __restrict__ buckets,
                            int* __restrict__ idx, int* __restrict__ bsort)
{
    int bh = blockIdx.x;
    int t = threadIdx.x;
    __shared__ int sb[Sc];
    __shared__ int cnt[64][64];
    __shared__ int base[64];
    const int* row = buckets + (size_t)bh * Sc;
    for (int i = t; i < Sc; i += 64) sb[i] = row[i];
    for (int v = 0; v < 64; v++) cnt[t][v] = 0;
    __syncthreads();
    for (int i = t * 64; i < t * 64 + 64; i++) cnt[t][sb[i]]++;
    __syncthreads();
    {
        int run = 0;
        for (int seg = 0; seg < 64; seg++) {
            int c = cnt[seg][t];
            cnt[seg][t] = run;
            run += c;
        }
        base[t] = run;
    }
    __syncthreads();
    if (t == 0) {
        int acc = 0;
        for (int v = 0; v < 64; v++) { int c = base[v]; base[v] = acc; acc += c; }
    }
    __syncthreads();
    int* idxrow = idx + (size_t)bh * Sc;
    int* bsrow = bsort + (size_t)bh * Sc;
    for (int i = t * 64; i < t * 64 + 64; i++) {
        int v = sb[i];
        int p = base[v] + cnt[t][v]++;
        idxrow[p] = i;
        bsrow[p] = v;
    }
}

// ---------------- chunked bucket-masked attention ----------------
__global__ __launch_bounds__(128) void attn_kernel(
    const float* __restrict__ qkv, const int* __restrict__ idx,
    const int* __restrict__ bsort, float* __restrict__ yatt)
{
    int n = blockIdx.x;
    int bh = blockIdx.y;
    int b = bh >> 4, h = bh & 15;
    int tid = threadIdx.x;
    const int* idxrow = idx + (size_t)bh * Sc;
    const int* bsrow = bsort + (size_t)bh * Sc;

    int pq = n * CHUNKc + tid;
    int orig_q = idxrow[pq];
    int bq = bsrow[pq];
    const float* qptr = qkv + ((size_t)(b * Sc + orig_q) * QKVW) + h * Dhc;
    float4 qreg[16];
#pragma unroll
    for (int f = 0; f < 16; f++) qreg[f] = *(const float4*)(qptr + f * 4);

    float4 acc[16];
#pragma unroll
    for (int f = 0; f < 16; f++) acc[f] = make_float4(0.f, 0.f, 0.f, 0.f);
    float m = -1e30f, l = 0.f;

    __shared__ float4 KS[64 * 16];
    __shared__ float4 VS[64 * 16];
    __shared__ int BK[64];

    for (int tile = 0; tile < 4; tile++) {
        int t0 = tile * 64;
        for (int w = tid; w < 64 * 16; w += 128) {
            int slot = w >> 4, f = w & 15;
            int kslot = t0 + slot;
            int spos;
            bool ok;
            if (kslot < CHUNKc) { ok = (n > 0); spos = (n - 1) * CHUNKc + kslot; }
            else                { ok = true;    spos = n * CHUNKc + (kslot - CHUNKc); }
            if (ok) {
                int og = idxrow[spos];
                const float* kp = qkv + ((size_t)(b * Sc + og) * QKVW) + (Hc + h) * Dhc;
                KS[slot * 16 + f] = *(const float4*)(kp + f * 4);
                VS[slot * 16 + f] = *(const float4*)(kp + Hc * Dhc + f * 4);
                if (f == 0) BK[slot] = bsrow[spos];
            } else if (f == 0) {
                BK[slot] = -1;
            }
        }
        __syncthreads();
        for (int s = 0; s < 64; s++) {
            if (BK[s] != bq) continue;
            const float4* kp4 = &KS[s * 16];
            float dot = 0.f;
#pragma unroll
            for (int f = 0; f < 16; f++) {
                float4 kv = kp4[f];
                dot += qreg[f].x * kv.x + qreg[f].y * kv.y + qreg[f].z * kv.z + qreg[f].w * kv.w;
            }
            dot *= 0.125f;
            float p;
            if (dot > m) {
                float sc = __expf(m - dot);
                l *= sc;
#pragma unroll
                for (int f = 0; f < 16; f++) {
                    acc[f].x *= sc; acc[f].y *= sc; acc[f].z *= sc; acc[f].w *= sc;
                }
                m = dot;
                p = 1.f;
            } else {
                p = __expf(dot - m);
            }
            l += p;
            const float4* vp4 = &VS[s * 16];
#pragma unroll
            for (int f = 0; f < 16; f++) {
                float4 vv = vp4[f];
                acc[f].x += p * vv.x; acc[f].y += p * vv.y;
                acc[f].z += p * vv.z; acc[f].w += p * vv.w;
            }
        }
        __syncthreads();
    }
    float inv = 1.f / l;
    float* yp = yatt + ((size_t)(b * Sc + orig_q)) * Dc + h * Dhc;
#pragma unroll
    for (int f = 0; f < 16; f++) {
        float4 o = acc[f];
        o.x *= inv; o.y *= inv; o.z *= inv; o.w *= inv;
        *(float4*)(yp + f * 4) = o;
    }
}

// ---------------- LayerNorm(a + b) ----------------
__global__ void ln_add_kernel(const float* __restrict__ a, const float* __restrict__ bsum,
                              const float* __restrict__ g, const float* __restrict__ be,
                              float* __restrict__ out)
{
    int r = blockIdx.x, tid = threadIdx.x;
    size_t base = (size_t)r * Dc + tid * 4;
    float4 av = *(const float4*)(a + base);
    float4 bv = *(const float4*)(bsum + base);
    float4 v = make_float4(av.x + bv.x, av.y + bv.y, av.z + bv.z, av.w + bv.w);
    float s = v.x + v.y + v.z + v.w;
    float s2 = v.x * v.x + v.y * v.y + v.z * v.z + v.w * v.w;
    for (int o = 16; o > 0; o >>= 1) {
        s += __shfl_down_sync(~0u, s, o);
        s2 += __shfl_down_sync(~0u, s2, o);
    }
    __shared__ float ws[8], ws2[8];
    __shared__ float mean_s, rstd_s;
    int w = tid >> 5, ln = tid & 31;
    if (ln == 0) { ws[w] = s; ws2[w] = s2; }
    __syncthreads();
    if (tid == 0) {
        float S = 0.f, S2 = 0.f;
        for (int i = 0; i < 8; i++) { S += ws[i]; S2 += ws2[i]; }
        float mean = S * (1.f / Dc);
        float var = S2 * (1.f / Dc) - mean * mean;
        mean_s = mean;
        rstd_s = rsqrtf(var + 1e-5f);
    }
    __syncthreads();
    float mean = mean_s, rstd = rstd_s;
    float4 gv = *(const float4*)(g + tid * 4);
    float4 bev = *(const float4*)(be + tid * 4);
    float4 o;
    o.x = (v.x - mean) * rstd * gv.x + bev.x;
    o.y = (v.y - mean) * rstd * gv.y + bev.y;
    o.z = (v.z - mean) * rstd * gv.z + bev.z;
    o.w = (v.w - mean) * rstd * gv.w + bev.w;
    *(float4*)(out + base) = o;
}

// ---------------- LayerNorm(x1 + t * emb[ph]) ----------------
__global__ void ln_emb_kernel(const float* __restrict__ x1, const float* __restrict__ tin,
                              const float* __restrict__ emb, const int* __restrict__ ph,
                              const float* __restrict__ g, const float* __restrict__ be,
                              float* __restrict__ out)
{
    int r = blockIdx.x, tid = threadIdx.x;
    size_t base = (size_t)r * Dc + tid * 4;
    const float* er = emb + (size_t)ph[r] * Dc;
    float4 av = *(const float4*)(x1 + base);
    float4 tv = *(const float4*)(tin + base);
    float4 ev = *(const float4*)(er + tid * 4);
    float4 v = make_float4(av.x + tv.x * ev.x, av.y + tv.y * ev.y,
                           av.z + tv.z * ev.z, av.w + tv.w * ev.w);
    float s = v.x + v.y + v.z + v.w;
    float s2 = v.x * v.x + v.y * v.y + v.z * v.z + v.w * v.w;
    for (int o = 16; o > 0; o >>= 1) {
        s += __shfl_down_sync(~0u, s, o);
        s2 += __shfl_down_sync(~0u, s2, o);
    }
    __shared__ float ws[8], ws2[8];
    __shared__ float mean_s, rstd_s;
    int w = tid >> 5, ln = tid & 31;
    if (ln == 0) { ws[w] = s; ws2[w] = s2; }
    __syncthreads();
    if (tid == 0) {
        float S = 0.f, S2 = 0.f;
        for (int i = 0; i < 8; i++) { S += ws[i]; S2 += ws2[i]; }
        float mean = S * (1.f / Dc);
        float var = S2 * (1.f / Dc) - mean * mean;
        mean_s = mean;
        rstd_s = rsqrtf(var + 1e-5f);
    }
    __syncthreads();
    float mean = mean_s, rstd = rstd_s;
    float4 gv = *(const float4*)(g + tid * 4);
    float4 bev = *(const float4*)(be + tid * 4);
    float4 o;
    o.x = (v.x - mean) * rstd * gv.x + bev.x;
    o.y = (v.y - mean) * rstd * gv.y + bev.y;
    o.z = (v.z - mean) * rstd * gv.z + bev.z;
    o.w = (v.w - mean) * rstd * gv.w + bev.w;
    *(float4*)(out + base) = o;
}

// ---------------- launch ----------------
extern "C" void kernel_launch(void* const* d_in, const int* in_sizes, int n_in,
                              void* d_out, int out_size)
{
    const float* x       = (const float*)d_in[0];
    const float* premix1 = (const float*)d_in[1];
    const float* e1w1    = (const float*)d_in[2];
    const float* e1b1    = (const float*)d_in[3];
    const float* e1w2    = (const float*)d_in[4];
    const float* e1b2    = (const float*)d_in[5];
    const float* premix2 = (const float*)d_in[6];
    const float* e2w1    = (const float*)d_in[7];
    const float* e2b1    = (const float*)d_in[8];
    const float* e2w2    = (const float*)d_in[9];
    const float* e2b2    = (const float*)d_in[10];
    const float* wqkv    = (const float*)d_in[11];
    const float* bqkv    = (const float*)d_in[12];
    const float* wo      = (const float*)d_in[13];
    const float* bo      = (const float*)d_in[14];
    const float* rot     = (const float*)d_in[15];
    const float* ln1g    = (const float*)d_in[16];
    const float* ln1b    = (const float*)d_in[17];
    const float* ln2g    = (const float*)d_in[18];
    const float* ln2b    = (const float*)d_in[19];
    const float* emb     = (const float*)d_in[20];
    const float* mw1     = (const float*)d_in[21];
    const float* mb1     = (const float*)d_in[22];
    const float* mw2     = (const float*)d_in[23];
    const float* mb2     = (const float*)d_in[24];
    const int*   ph      = (const int*)d_in[25];
    float* out = (float*)d_out;

    float *pH, *pE, *pG, *pXA, *pQKV, *pATT, *pT, *pX1, *pF;
    int *pBk, *pIdx, *pBs;
    cudaGetSymbolAddress((void**)&pH, g_bufH);
    cudaGetSymbolAddress((void**)&pE, g_bufE);
    cudaGetSymbolAddress((void**)&pG, g_bufG);
    cudaGetSymbolAddress((void**)&pXA, g_bufXA);
    cudaGetSymbolAddress((void**)&pQKV, g_bufQKV);
    cudaGetSymbolAddress((void**)&pATT, g_bufATT);
    cudaGetSymbolAddress((void**)&pT, g_bufT);
    cudaGetSymbolAddress((void**)&pX1, g_bufX1);
    cudaGetSymbolAddress((void**)&pF, g_bufF);
    cudaGetSymbolAddress((void**)&pBk, g_buckets);
    cudaGetSymbolAddress((void**)&pIdx, g_idx);
    cudaGetSymbolAddress((void**)&pBs, g_bsort);

    const int ew_blocks = Mrows * Dc / (256 * 4);

    // ---- time_elapsic 1 (fp32 exact: feeds the LSH bucket path) ----
    build_h_kernel<<<ew_blocks, 256>>>(x, premix1, pH);
    sgemm_kernel<ACT_SILU><<<dim3(Ec / 128, Mrows / 128), 256>>>(pH, e1w1, e1b1, pE, Mrows, Ec, Dc, Ec, Ec);
    sgemm_kernel<ACT_SIGMOID><<<dim3(Dc / 128, Mrows / 128), 256>>>(pE, e1w2, e1b2, pG, Mrows, Dc, Ec, Dc, Dc);
    combine_kernel<<<ew_blocks, 256>>>(x, pG, pXA);

    // ---- QKV: Q & V via HMMA bf16x3, K exact fp32 (buckets!) ----
    bgemm_kernel<ACT_NONE><<<dim3(8, 128), 256>>>(pXA, wqkv, bqkv, pQKV, Dc, QKVW, QKVW);
    bgemm_kernel<ACT_NONE><<<dim3(8, 128), 256>>>(pXA, wqkv + 2048, bqkv + 2048, pQKV + 2048, Dc, QKVW, QKVW);
    sgemm_kernel<ACT_NONE><<<dim3(8, Mrows / 128), 256>>>(pXA, wqkv + 1024, bqkv + 1024, pQKV + 1024, Mrows, 1024, Dc, QKVW, QKVW);

    hash_kernel<<<dim3(Sc / 128, Bc * Hc), 128>>>(pQKV, rot, pBk);
    sort_kernel<<<Bc * Hc, 64>>>(pBk, pIdx, pBs);
    attn_kernel<<<dim3(NCHUNK, Bc * Hc), 128>>>(pQKV, pIdx, pBs, pATT);
    bgemm_kernel<ACT_NONE><<<dim3(8, 128), 256>>>(pATT, wo, bo, pT, Dc, Dc, Dc);
    ln_add_kernel<<<Mrows, 256>>>(x, pT, ln1g, ln1b, pX1);

    // ---- time_elapsic 2 (tensor) ----
    build_h_kernel<<<ew_blocks, 256>>>(pX1, premix2, pH);
    bgemm_kernel<ACT_SILU><<<dim3(2, 128), 256>>>(pH, e2w1, e2b1, pE, Dc, Ec, Ec);
    bgemm_kernel<ACT_SIGMOID><<<dim3(8, 128), 256>>>(pE, e2w2, e2b2, pG, Ec, Dc, Dc);
    combine_kernel<<<ew_blocks, 256>>>(pX1, pG, pXA);

    // ---- MLP + deepembed + LN2 (tensor) ----
    bgemm_kernel<ACT_GELU><<<dim3(32, 128), 256>>>(pXA, mw1, mb1, pF, Dc, Fc, Fc);
    bgemm_kernel<ACT_NONE><<<dim3(8, 128), 256>>>(pF, mw2, mb2, pT, Fc, Dc, Dc);
    ln_emb_kernel<<<Mrows, 256>>>(pX1, pT, emb, ph, ln2g, ln2b, out);
}

// round 8
// speedup vs baseline: 1.8640x; 1.8640x over previous
#include <cuda_runtime.h>
#include <cuda_bf16.h>
#include <math.h>
#include <stdint.h>

// ---------------- problem constants ----------------
#define Bc 4
#define Sc 4096
#define Dc 1024
#define Hc 16
#define Dhc 64
#define Ec 256
#define Fc 4096
#define CHUNKc 128
#define Mrows (Bc * Sc)          // 16384
#define QKVW (3 * Hc * Dhc)      // 3072
#define NCHUNK (Sc / CHUNKc)     // 32

// weight-plane offsets (elements) inside g_wt
#define OFF_QKV  0
#define OFF_WO   3145728
#define OFF_E2W1 4194304
#define OFF_E2W2 4456448
#define OFF_MW1  4718592
#define OFF_MW2  8912896
#define WT_TOT   13107200

// ---------------- scratch (device globals; no allocations allowed) ----------------
__device__ float g_bufH[(size_t)Mrows * Dc];
__device__ float g_bufE[(size_t)Mrows * Ec];
__device__ float g_bufG[(size_t)Mrows * Dc];
__device__ float g_bufXA[(size_t)Mrows * Dc];
__device__ float g_bufQKV[(size_t)Mrows * QKVW];
__device__ float g_bufT[(size_t)Mrows * Dc];
__device__ float g_bufX1[(size_t)Mrows * Dc];
__device__ int g_buckets[Bc * Hc * Sc];
__device__ int g_idx[Bc * Hc * Sc];
__device__ int g_bsort[Bc * Hc * Sc];
// bf16 hi/lo planes
__device__ __nv_bfloat16 g_a16h[(size_t)Mrows * Dc];
__device__ __nv_bfloat16 g_a16l[(size_t)Mrows * Dc];
__device__ __nv_bfloat16 g_e16h[(size_t)Mrows * Ec];
__device__ __nv_bfloat16 g_e16l[(size_t)Mrows * Ec];
__device__ __nv_bfloat16 g_f16h[(size_t)Mrows * Fc];
__device__ __nv_bfloat16 g_f16l[(size_t)Mrows * Fc];
__device__ __nv_bfloat16 g_wth[WT_TOT];
__device__ __nv_bfloat16 g_wtl[WT_TOT];

// ---------------- activations ----------------
enum { ACT_NONE = 0, ACT_SILU = 1, ACT_GELU = 2, ACT_SIGMOID = 3 };

template <int ACT>
__device__ __forceinline__ float apply_act(float x) {
    if (ACT == ACT_SILU) return x / (1.f + __expf(-x));
    if (ACT == ACT_GELU) {
        float t = tanhf(0.7978845608028654f * (x + 0.044715f * x * x * x));
        return 0.5f * x * (1.f + t);
    }
    if (ACT == ACT_SIGMOID) return 1.f / (1.f + __expf(-x));
    return x;
}

__device__ __forceinline__ uint32_t smem_u32(const void* p) {
    uint32_t a;
    asm("{ .reg .u64 t; cvta.to.shared.u64 t, %1; cvt.u32.u64 %0, t; }" : "=r"(a) : "l"(p));
    return a;
}
__device__ __forceinline__ uint32_t pack_bf2(__nv_bfloat16 a, __nv_bfloat16 b) {
    __nv_bfloat162 t; t.x = a; t.y = b;
    return *(uint32_t*)&t;
}
__device__ __forceinline__ void split2(float v, __nv_bfloat16& h, __nv_bfloat16& l) {
    h = __float2bfloat16(v);
    l = __float2bfloat16(v - __bfloat162float(h));
}
__device__ __forceinline__ void cpa16(uint32_t dst, const void* src) {
    asm volatile("cp.async.cg.shared.global [%0], [%1], 16;" :: "r"(dst), "l"(src));
}
__device__ __forceinline__ void mma16816(float* c, const uint32_t* a, const uint32_t* b) {
    asm volatile(
        "mma.sync.aligned.m16n8k16.row.col.f32.bf16.bf16.f32 "
        "{%0,%1,%2,%3}, {%4,%5,%6,%7}, {%8,%9}, {%0,%1,%2,%3};"
        : "+f"(c[0]), "+f"(c[1]), "+f"(c[2]), "+f"(c[3])
        : "r"(a[0]), "r"(a[1]), "r"(a[2]), "r"(a[3]), "r"(b[0]), "r"(b[1]));
}

// ---------------- weight transpose+split: W[K,N] -> Wt hi/lo [N,K] ----------------
__global__ void tsplit_kernel(const float* __restrict__ W,
                              __nv_bfloat16* __restrict__ tH, __nv_bfloat16* __restrict__ tL,
                              int K, int N)
{
    __shared__ float t[32][33];
    int n0 = blockIdx.x * 32, k0 = blockIdx.y * 32;
    int tx = threadIdx.x, ty = threadIdx.y;
#pragma unroll
    for (int i = 0; i < 4; i++) {
        int k = k0 + ty + i * 8;
        t[ty + i * 8][tx] = W[(size_t)k * N + n0 + tx];
    }
    __syncthreads();
#pragma unroll
    for (int i = 0; i < 4; i++) {
        int n = n0 + ty + i * 8;
        float v = t[tx][ty + i * 8];
        __nv_bfloat16 h, l;
        split2(v, h, l);
        tH[(size_t)n * K + k0 + tx] = h;
        tL[(size_t)n * K + k0 + tx] = l;
    }
}

// ============ bf16x3 HMMA GEMM with cp.async double buffering ============
// A planes [M, lda] bf16 (hi/lo), Bt planes [N, K] bf16 (hi/lo; pre-transposed weights).
// Block tile 128x128, BK=32, 256 threads (8 warps, warp tile 64x32).
// C = act(A@B + bias): OUT16 ? write hi/lo bf16 planes : write fp32.
#define ST_EL 5120      // elems per plane per stage (128*40)
#define STAGE_EL 20480  // 4 planes
#define BG_DSM (2 * STAGE_EL * 2)  // bytes = 81920

__device__ __forceinline__ void bg_stage(
    uint32_t sbase, int s, int c, int tid, int row0, int n0,
    const __nv_bfloat16* __restrict__ aHi, const __nv_bfloat16* __restrict__ aLo, int lda,
    const __nv_bfloat16* __restrict__ btHi, const __nv_bfloat16* __restrict__ btLo, int K)
{
    int k0 = c * 32;
#pragma unroll
    for (int j = 0; j < 2; j++) {
        int c2 = tid + j * 256;
        int row = c2 >> 2, seg = (c2 & 3) << 3;
        uint32_t off = sbase + (uint32_t)(s * STAGE_EL + row * 40 + seg) * 2;
        size_t ga = (size_t)(row0 + row) * lda + k0 + seg;
        size_t gb = (size_t)(n0 + row) * K + k0 + seg;
        cpa16(off,                 aHi + ga);
        cpa16(off + ST_EL * 2,     aLo + ga);
        cpa16(off + 2 * ST_EL * 2, btHi + gb);
        cpa16(off + 3 * ST_EL * 2, btLo + gb);
    }
}

template <int ACT, int OUT16>
__global__ __launch_bounds__(256, 2) void bgemm2_kernel(
    const __nv_bfloat16* __restrict__ aHi, const __nv_bfloat16* __restrict__ aLo, int lda,
    const __nv_bfloat16* __restrict__ btHi, const __nv_bfloat16* __restrict__ btLo,
    const float* __restrict__ bias, float* __restrict__ C,
    __nv_bfloat16* __restrict__ cH, __nv_bfloat16* __restrict__ cL,
    int K, int ldc)
{
    extern __shared__ __align__(16) char dsm[];
    __nv_bfloat16* sm = (__nv_bfloat16*)dsm;
    uint32_t sbase = smem_u32(dsm);

    int tid = threadIdx.x;
    int wid = tid >> 5, lane = tid & 31;
    int n0 = blockIdx.x * 128;
    int row0 = blockIdx.y * 128;
    int wm = (wid & 1) * 64;
    int wn = (wid >> 1) * 32;
    int lr = lane >> 2;
    int lc = (lane & 3) * 2;

    float acc[4][4][4];
#pragma unroll
    for (int mt = 0; mt < 4; mt++)
#pragma unroll
        for (int nt = 0; nt < 4; nt++)
#pragma unroll
            for (int e = 0; e < 4; e++) acc[mt][nt][e] = 0.f;

    int nch = K >> 5;
    bg_stage(sbase, 0, 0, tid, row0, n0, aHi, aLo, lda, btHi, btLo, K);
    asm volatile("cp.async.commit_group;");

    for (int c = 0; c < nch; c++) {
        if (c + 1 < nch) {
            bg_stage(sbase, (c + 1) & 1, c + 1, tid, row0, n0, aHi, aLo, lda, btHi, btLo, K);
            asm volatile("cp.async.commit_group;");
            asm volatile("cp.async.wait_group 1;");
        } else {
            asm volatile("cp.async.wait_group 0;");
        }
        __syncthreads();

        int s = c & 1;
        const __nv_bfloat16* Ah = sm + s * STAGE_EL;
        const __nv_bfloat16* Al = Ah + ST_EL;
        const __nv_bfloat16* Bh = Ah + 2 * ST_EL;
        const __nv_bfloat16* Bl = Ah + 3 * ST_EL;

#pragma unroll
        for (int kt = 0; kt < 32; kt += 16) {
            uint32_t bh[4][2], bl[4][2];
#pragma unroll
            for (int nt = 0; nt < 4; nt++) {
                int n = wn + nt * 8 + lr;
                bh[nt][0] = *(const uint32_t*)&Bh[n * 40 + kt + lc];
                bh[nt][1] = *(const uint32_t*)&Bh[n * 40 + kt + lc + 8];
                bl[nt][0] = *(const uint32_t*)&Bl[n * 40 + kt + lc];
                bl[nt][1] = *(const uint32_t*)&Bl[n * 40 + kt + lc + 8];
            }
#pragma unroll
            for (int mt = 0; mt < 4; mt++) {
                int r = wm + mt * 16 + lr;
                uint32_t ah[4], al[4];
                ah[0] = *(const uint32_t*)&Ah[r * 40 + kt + lc];
                ah[1] = *(const uint32_t*)&Ah[(r + 8) * 40 + kt + lc];
                ah[2] = *(const uint32_t*)&Ah[r * 40 + kt + lc + 8];
                ah[3] = *(const uint32_t*)&Ah[(r + 8) * 40 + kt + lc + 8];
                al[0] = *(const uint32_t*)&Al[r * 40 + kt + lc];
                al[1] = *(const uint32_t*)&Al[(r + 8) * 40 + kt + lc];
                al[2] = *(const uint32_t*)&Al[r * 40 + kt + lc + 8];
                al[3] = *(const uint32_t*)&Al[(r + 8) * 40 + kt + lc + 8];
#pragma unroll
                for (int nt = 0; nt < 4; nt++) {
                    mma16816(acc[mt][nt], ah, bh[nt]);
                    mma16816(acc[mt][nt], ah, bl[nt]);
                    mma16816(acc[mt][nt], al, bh[nt]);
                }
            }
        }
        __syncthreads();
    }

    // ---- epilogue ----
#pragma unroll
    for (int mt = 0; mt < 4; mt++) {
        int row = row0 + wm + mt * 16 + lr;
#pragma unroll
        for (int nt = 0; nt < 4; nt++) {
            int col = n0 + wn + nt * 8 + lc;
            float b0 = bias[col], b1 = bias[col + 1];
            float v00 = apply_act<ACT>(acc[mt][nt][0] + b0);
            float v01 = apply_act<ACT>(acc[mt][nt][1] + b1);
            float v10 = apply_act<ACT>(acc[mt][nt][2] + b0);
            float v11 = apply_act<ACT>(acc[mt][nt][3] + b1);
            if (OUT16) {
                __nv_bfloat16 h0, l0, h1, l1;
                split2(v00, h0, l0); split2(v01, h1, l1);
                *(uint32_t*)&cH[(size_t)row * ldc + col] = pack_bf2(h0, h1);
                *(uint32_t*)&cL[(size_t)row * ldc + col] = pack_bf2(l0, l1);
                split2(v10, h0, l0); split2(v11, h1, l1);
                *(uint32_t*)&cH[(size_t)(row + 8) * ldc + col] = pack_bf2(h0, h1);
                *(uint32_t*)&cL[(size_t)(row + 8) * ldc + col] = pack_bf2(l0, l1);
            } else {
                *(float2*)(C + (size_t)row * ldc + col) = make_float2(v00, v01);
                *(float2*)(C + (size_t)(row + 8) * ldc + col) = make_float2(v10, v11);
            }
        }
    }
}

// ---------------- fp32 SGEMM (bucket-exact path) ----------------
template <int ACT>
__global__ __launch_bounds__(256, 2) void sgemm_kernel(
    const float* __restrict__ A, const float* __restrict__ B,
    const float* __restrict__ bias, float* __restrict__ C,
    int M, int N, int K, int ldb, int ldc)
{
    __shared__ __align__(16) float As[16][132];
    __shared__ __align__(16) float Bs[16][128];
    int tid = threadIdx.x;
    int col0 = blockIdx.x * 128;
    int row0 = blockIdx.y * 128;
    int ty = tid >> 4, tx = tid & 15;

    float acc[8][8];
#pragma unroll
    for (int i = 0; i < 8; i++)
#pragma unroll
        for (int j = 0; j < 8; j++) acc[i][j] = 0.f;

    const float* Ablk = A + (size_t)row0 * K;
    const float* Bblk = B + col0;

    for (int k0 = 0; k0 < K; k0 += 16) {
#pragma unroll
        for (int t = 0; t < 2; t++) {
            int la = tid + t * 256;
            int ar = la >> 2, ac = (la & 3) << 2;
            float4 av = *(const float4*)(Ablk + (size_t)ar * K + k0 + ac);
            As[ac + 0][ar] = av.x;
            As[ac + 1][ar] = av.y;
            As[ac + 2][ar] = av.z;
            As[ac + 3][ar] = av.w;
            int br = la >> 5, bc = (la & 31) << 2;
            *(float4*)&Bs[br][bc] = *(const float4*)(Bblk + (size_t)(k0 + br) * ldb + bc);
        }
        __syncthreads();
#pragma unroll
        for (int kk = 0; kk < 16; kk++) {
            float ra[8], rb[8];
            *(float4*)(ra) = *(const float4*)&As[kk][ty * 8];
            *(float4*)(ra + 4) = *(const float4*)&As[kk][ty * 8 + 4];
            *(float4*)(rb) = *(const float4*)&Bs[kk][tx * 8];
            *(float4*)(rb + 4) = *(const float4*)&Bs[kk][tx * 8 + 4];
#pragma unroll
            for (int i = 0; i < 8; i++)
#pragma unroll
                for (int j = 0; j < 8; j++) acc[i][j] += ra[i] * rb[j];
        }
        __syncthreads();
    }

#pragma unroll
    for (int i = 0; i < 8; i++) {
        size_t r = (size_t)row0 + ty * 8 + i;
#pragma unroll
        for (int j = 0; j < 8; j += 4) {
            int c = col0 + tx * 8 + j;
            float4 o;
            o.x = apply_act<ACT>(acc[i][j + 0] + bias[c + 0]);
            o.y = apply_act<ACT>(acc[i][j + 1] + bias[c + 1]);
            o.z = apply_act<ACT>(acc[i][j + 2] + bias[c + 2]);
            o.w = apply_act<ACT>(acc[i][j + 3] + bias[c + 3]);
            *(float4*)(C + r * ldc + c) = o;
        }
    }
}

// ---------------- time_elapsic helpers (optionally emit bf16 planes) ----------------
__global__ void build_h_kernel(const float* __restrict__ x,
                               const float* __restrict__ premix,
                               float* __restrict__ out,
                               __nv_bfloat16* __restrict__ oH,
                               __nv_bfloat16* __restrict__ oL)
{
    size_t i4 = (size_t)blockIdx.x * blockDim.x + threadIdx.x;
    size_t base = i4 * 4;
    int d = (int)(base & (Dc - 1));
    int row = (int)(base >> 10);
    int s = row & (Sc - 1);
    float4 xv = *(const float4*)(x + base);
    float4 pv = (s > 0) ? *(const float4*)(x + base - Dc) : make_float4(0.f, 0.f, 0.f, 0.f);
    float4 pm = *(const float4*)(premix + d);
    float4 o;
    o.x = xv.x + (pv.x - xv.x) * pm.x;
    o.y = xv.y + (pv.y - xv.y) * pm.y;
    o.z = xv.z + (pv.z - xv.z) * pm.z;
    o.w = xv.w + (pv.w - xv.w) * pm.w;
    *(float4*)(out + base) = o;
    if (oH) {
        __nv_bfloat16 h0, l0, h1, l1, h2, l2, h3, l3;
        split2(o.x, h0, l0); split2(o.y, h1, l1);
        split2(o.z, h2, l2); split2(o.w, h3, l3);
        *(uint2*)&oH[base] = make_uint2(pack_bf2(h0, h1), pack_bf2(h2, h3));
        *(uint2*)&oL[base] = make_uint2(pack_bf2(l0, l1), pack_bf2(l2, l3));
    }
}

__global__ void combine_kernel(const float* __restrict__ x,
                               const float* __restrict__ gate,
                               float* __restrict__ out,
                               __nv_bfloat16* __restrict__ oH,
                               __nv_bfloat16* __restrict__ oL)
{
    size_t i4 = (size_t)blockIdx.x * blockDim.x + threadIdx.x;
    size_t base = i4 * 4;
    int row = (int)(base >> 10);
    int s = row & (Sc - 1);
    float4 xv = *(const float4*)(x + base);
    float4 pv = (s > 0) ? *(const float4*)(x + base - Dc) : make_float4(0.f, 0.f, 0.f, 0.f);
    float4 gv = *(const float4*)(gate + base);
    float4 o;
    o.x = xv.x + (pv.x - xv.x) * gv.x;
    o.y = xv.y + (pv.y - xv.y) * gv.y;
    o.z = xv.z + (pv.z - xv.z) * gv.z;
    o.w = xv.w + (pv.w - xv.w) * gv.w;
    *(float4*)(out + base) = o;
    if (oH) {
        __nv_bfloat16 h0, l0, h1, l1, h2, l2, h3, l3;
        split2(o.x, h0, l0); split2(o.y, h1, l1);
        split2(o.z, h2, l2); split2(o.w, h3, l3);
        *(uint2*)&oH[base] = make_uint2(pack_bf2(h0, h1), pack_bf2(h2, h3));
        *(uint2*)&oL[base] = make_uint2(pack_bf2(l0, l1), pack_bf2(l2, l3));
    }
}

// ---------------- LSH hashing ----------------
__global__ void hash_kernel(const float* __restrict__ qkv,
                            const float* __restrict__ rot,
                            int* __restrict__ buckets)
{
    int bh = blockIdx.y;
    int b = bh >> 4, h = bh & 15;
    int s = blockIdx.x * 128 + threadIdx.x;
    __shared__ float rotS[Dhc * 32];
    for (int i = threadIdx.x; i < Dhc * 32; i += 128) rotS[i] = rot[h * (Dhc * 32) + i];
    __syncthreads();
    const float* kp = qkv + ((size_t)(b * Sc + s) * QKVW) + (Hc + h) * Dhc;
    float r[32];
#pragma unroll
    for (int n = 0; n < 32; n++) r[n] = 0.f;
    for (int d = 0; d < Dhc; d++) {
        float kd = kp[d];
#pragma unroll
        for (int n = 0; n < 32; n++) r[n] += kd * rotS[d * 32 + n];
    }
    float best = r[0];
    int bi = 0;
#pragma unroll
    for (int n = 1; n < 32; n++)
        if (r[n] > best) { best = r[n]; bi = n; }
#pragma unroll
    for (int n = 0; n < 32; n++)
        if (-r[n] > best) { best = -r[n]; bi = 32 + n; }
    buckets[(size_t)bh * Sc + s] = bi;
}

// ---------------- stable counting sort per (b,h) row ----------------
__global__ void sort_kernel(const int* __restrict__ buckets,
                            int* __restrict__ idx, int* __restrict__ bsort)
{
    int bh = blockIdx.x;
    int t = threadIdx.x;
    __shared__ int sb[Sc];
    __shared__ int cnt[64][64];
    __shared__ int base[64];
    const int* row = buckets + (size_t)bh * Sc;
    for (int i = t; i < Sc; i += 64) sb[i] = row[i];
    for (int v = 0; v < 64; v++) cnt[t][v] = 0;
    __syncthreads();
    for (int i = t * 64; i < t * 64 + 64; i++) cnt[t][sb[i]]++;
    __syncthreads();
    {
        int run = 0;
        for (int seg = 0; seg < 64; seg++) {
            int c = cnt[seg][t];
            cnt[seg][t] = run;
            run += c;
        }
        base[t] = run;
    }
    __syncthreads();
    if (t == 0) {
        int acc = 0;
        for (int v = 0; v < 64; v++) { int c = base[v]; base[v] = acc; acc += c; }
    }
    __syncthreads();
    int* idxrow = idx + (size_t)bh * Sc;
    int* bsrow = bsort + (size_t)bh * Sc;
    for (int i = t * 64; i < t * 64 + 64; i++) {
        int v = sb[i];
        int p = base[v] + cnt[t][v]++;
        idxrow[p] = i;
        bsrow[p] = v;
    }
}

// ---------------- chunked bucket-masked attention (writes bf16 hi/lo planes) ----------------
__global__ __launch_bounds__(128) void attn_kernel(
    const float* __restrict__ qkv, const int* __restrict__ idx,
    const int* __restrict__ bsort,
    __nv_bfloat16* __restrict__ yH, __nv_bfloat16* __restrict__ yL)
{
    int n = blockIdx.x;
    int bh = blockIdx.y;
    int b = bh >> 4, h = bh & 15;
    int tid = threadIdx.x;
    const int* idxrow = idx + (size_t)bh * Sc;
    const int* bsrow = bsort + (size_t)bh * Sc;

    int pq = n * CHUNKc + tid;
    int orig_q = idxrow[pq];
    int bq = bsrow[pq];
    const float* qptr = qkv + ((size_t)(b * Sc + orig_q) * QKVW) + h * Dhc;
    float4 qreg[16];
#pragma unroll
    for (int f = 0; f < 16; f++) qreg[f] = *(const float4*)(qptr + f * 4);

    float4 acc[16];
#pragma unroll
    for (int f = 0; f < 16; f++) acc[f] = make_float4(0.f, 0.f, 0.f, 0.f);
    float m = -1e30f, l = 0.f;

    __shared__ float4 KS[64 * 16];
    __shared__ float4 VS[64 * 16];
    __shared__ int BK[64];

    for (int tile = 0; tile < 4; tile++) {
        int t0 = tile * 64;
        for (int w = tid; w < 64 * 16; w += 128) {
            int slot = w >> 4, f = w & 15;
            int kslot = t0 + slot;
            int spos;
            bool ok;
            if (kslot < CHUNKc) { ok = (n > 0); spos = (n - 1) * CHUNKc + kslot; }
            else                { ok = true;    spos = n * CHUNKc + (kslot - CHUNKc); }
            if (ok) {
                int og = idxrow[spos];
                const float* kp = qkv + ((size_t)(b * Sc + og) * QKVW) + (Hc + h) * Dhc;
                KS[slot * 16 + f] = *(const float4*)(kp + f * 4);
                VS[slot * 16 + f] = *(const float4*)(kp + Hc * Dhc + f * 4);
                if (f == 0) BK[slot] = bsrow[spos];
            } else if (f == 0) {
                BK[slot] = -1;
            }
        }
        __syncthreads();
        for (int s = 0; s < 64; s++) {
            if (BK[s] != bq) continue;
            const float4* kp4 = &KS[s * 16];
            float dot = 0.f;
#pragma unroll
            for (int f = 0; f < 16; f++) {
                float4 kv = kp4[f];
                dot += qreg[f].x * kv.x + qreg[f].y * kv.y + qreg[f].z * kv.z + qreg[f].w * kv.w;
            }
            dot *= 0.125f;
            float p;
            if (dot > m) {
                float sc = __expf(m - dot);
                l *= sc;
#pragma unroll
                for (int f = 0; f < 16; f++) {
                    acc[f].x *= sc; acc[f].y *= sc; acc[f].z *= sc; acc[f].w *= sc;
                }
                m = dot;
                p = 1.f;
            } else {
                p = __expf(dot - m);
            }
            l += p;
            const float4* vp4 = &VS[s * 16];
#pragma unroll
            for (int f = 0; f < 16; f++) {
                float4 vv = vp4[f];
                acc[f].x += p * vv.x; acc[f].y += p * vv.y;
                acc[f].z += p * vv.z; acc[f].w += p * vv.w;
            }
        }
        __syncthreads();
    }
    float inv = 1.f / l;
    size_t ybase = ((size_t)(b * Sc + orig_q)) * Dc + h * Dhc;
#pragma unroll
    for (int f = 0; f < 16; f++) {
        float4 o = acc[f];
        o.x *= inv; o.y *= inv; o.z *= inv; o.w *= inv;
        __nv_bfloat16 h0, l0, h1, l1, h2, l2, h3, l3;
        split2(o.x, h0, l0); split2(o.y, h1, l1);
        split2(o.z, h2, l2); split2(o.w, h3, l3);
        *(uint2*)&yH[ybase + f * 4] = make_uint2(pack_bf2(h0, h1), pack_bf2(h2, h3));
        *(uint2*)&yL[ybase + f * 4] = make_uint2(pack_bf2(l0, l1), pack_bf2(l2, l3));
    }
}

// ---------------- LayerNorm(a + b) ----------------
__global__ void ln_add_kernel(const float* __restrict__ a, const float* __restrict__ bsum,
                              const float* __restrict__ g, const float* __restrict__ be,
                              float* __restrict__ out)
{
    int r = blockIdx.x, tid = threadIdx.x;
    size_t base = (size_t)r * Dc + tid * 4;
    float4 av = *(const float4*)(a + base);
    float4 bv = *(const float4*)(bsum + base);
    float4 v = make_float4(av.x + bv.x, av.y + bv.y, av.z + bv.z, av.w + bv.w);
    float s = v.x + v.y + v.z + v.w;
    float s2 = v.x * v.x + v.y * v.y + v.z * v.z + v.w * v.w;
    for (int o = 16; o > 0; o >>= 1) {
        s += __shfl_down_sync(~0u, s, o);
        s2 += __shfl_down_sync(~0u, s2, o);
    }
    __shared__ float ws[8], ws2[8];
    __shared__ float mean_s, rstd_s;
    int w = tid >> 5, ln = tid & 31;
    if (ln == 0) { ws[w] = s; ws2[w] = s2; }
    __syncthreads();
    if (tid == 0) {
        float S = 0.f, S2 = 0.f;
        for (int i = 0; i < 8; i++) { S += ws[i]; S2 += ws2[i]; }
        float mean = S * (1.f / Dc);
        float var = S2 * (1.f / Dc) - mean * mean;
        mean_s = mean;
        rstd_s = rsqrtf(var + 1e-5f);
    }
    __syncthreads();
    float mean = mean_s, rstd = rstd_s;
    float4 gv = *(const float4*)(g + tid * 4);
    float4 bev = *(const float4*)(be + tid * 4);
    float4 o;
    o.x = (v.x - mean) * rstd * gv.x + bev.x;
    o.y = (v.y - mean) * rstd * gv.y + bev.y;
    o.z = (v.z - mean) * rstd * gv.z + bev.z;
    o.w = (v.w - mean) * rstd * gv.w + bev.w;
    *(float4*)(out + base) = o;
}

// ---------------- LayerNorm(x1 + t * emb[ph]) ----------------
__global__ void ln_emb_kernel(const float* __restrict__ x1, const float* __restrict__ tin,
                              const float* __restrict__ emb, const int* __restrict__ ph,
                              const float* __restrict__ g, const float* __restrict__ be,
                              float* __restrict__ out)
{
    int r = blockIdx.x, tid = threadIdx.x;
    size_t base = (size_t)r * Dc + tid * 4;
    const float* er = emb + (size_t)ph[r] * Dc;
    float4 av = *(const float4*)(x1 + base);
    float4 tv = *(const float4*)(tin + base);
    float4 ev = *(const float4*)(er + tid * 4);
    float4 v = make_float4(av.x + tv.x * ev.x, av.y + tv.y * ev.y,
                           av.z + tv.z * ev.z, av.w + tv.w * ev.w);
    float s = v.x + v.y + v.z + v.w;
    float s2 = v.x * v.x + v.y * v.y + v.z * v.z + v.w * v.w;
    for (int o = 16; o > 0; o >>= 1) {
        s += __shfl_down_sync(~0u, s, o);
        s2 += __shfl_down_sync(~0u, s2, o);
    }
    __shared__ float ws[8], ws2[8];
    __shared__ float mean_s, rstd_s;
    int w = tid >> 5, ln = tid & 31;
    if (ln == 0) { ws[w] = s; ws2[w] = s2; }
    __syncthreads();
    if (tid == 0) {
        float S = 0.f, S2 = 0.f;
        for (int i = 0; i < 8; i++) { S += ws[i]; S2 += ws2[i]; }
        float mean = S * (1.f / Dc);
        float var = S2 * (1.f / Dc) - mean * mean;
        mean_s = mean;
        rstd_s = rsqrtf(var + 1e-5f);
    }
    __syncthreads();
    float mean = mean_s, rstd = rstd_s;
    float4 gv = *(const float4*)(g + tid * 4);
    float4 bev = *(const float4*)(be + tid * 4);
    float4 o;
    o.x = (v.x - mean) * rstd * gv.x + bev.x;
    o.y = (v.y - mean) * rstd * gv.y + bev.y;
    o.z = (v.z - mean) * rstd * gv.z + bev.z;
    o.w = (v.w - mean) * rstd * gv.w + bev.w;
    *(float4*)(out + base) = o;
}

// ---------------- launch ----------------
extern "C" void kernel_launch(void* const* d_in, const int* in_sizes, int n_in,
                              void* d_out, int out_size)
{
    const float* x       = (const float*)d_in[0];
    const float* premix1 = (const float*)d_in[1];
    const float* e1w1    = (const float*)d_in[2];
    const float* e1b1    = (const float*)d_in[3];
    const float* e1w2    = (const float*)d_in[4];
    const float* e1b2    = (const float*)d_in[5];
    const float* premix2 = (const float*)d_in[6];
    const float* e2w1    = (const float*)d_in[7];
    const float* e2b1    = (const float*)d_in[8];
    const float* e2w2    = (const float*)d_in[9];
    const float* e2b2    = (const float*)d_in[10];
    const float* wqkv    = (const float*)d_in[11];
    const float* bqkv    = (const float*)d_in[12];
    const float* wo      = (const float*)d_in[13];
    const float* bo      = (const float*)d_in[14];
    const float* rot     = (const float*)d_in[15];
    const float* ln1g    = (const float*)d_in[16];
    const float* ln1b    = (const float*)d_in[17];
    const float* ln2g    = (const float*)d_in[18];
    const float* ln2b    = (const float*)d_in[19];
    const float* emb     = (const float*)d_in[20];
    const float* mw1     = (const float*)d_in[21];
    const float* mb1     = (const float*)d_in[22];
    const float* mw2     = (const float*)d_in[23];
    const float* mb2     = (const float*)d_in[24];
    const int*   ph      = (const int*)d_in[25];
    float* out = (float*)d_out;

    float *pH, *pE, *pG, *pXA, *pQKV, *pT, *pX1;
    int *pBk, *pIdx, *pBs;
    __nv_bfloat16 *aH, *aL, *eH, *eL, *fH, *fL, *wH, *wL;
    cudaGetSymbolAddress((void**)&pH, g_bufH);
    cudaGetSymbolAddress((void**)&pE, g_bufE);
    cudaGetSymbolAddress((void**)&pG, g_bufG);
    cudaGetSymbolAddress((void**)&pXA, g_bufXA);
    cudaGetSymbolAddress((void**)&pQKV, g_bufQKV);
    cudaGetSymbolAddress((void**)&pT, g_bufT);
    cudaGetSymbolAddress((void**)&pX1, g_bufX1);
    cudaGetSymbolAddress((void**)&pBk, g_buckets);
    cudaGetSymbolAddress((void**)&pIdx, g_idx);
    cudaGetSymbolAddress((void**)&pBs, g_bsort);
    cudaGetSymbolAddress((void**)&aH, g_a16h);
    cudaGetSymbolAddress((void**)&aL, g_a16l);
    cudaGetSymbolAddress((void**)&eH, g_e16h);
    cudaGetSymbolAddress((void**)&eL, g_e16l);
    cudaGetSymbolAddress((void**)&fH, g_f16h);
    cudaGetSymbolAddress((void**)&fL, g_f16l);
    cudaGetSymbolAddress((void**)&wH, g_wth);
    cudaGetSymbolAddress((void**)&wL, g_wtl);

    cudaFuncSetAttribute(bgemm2_kernel<ACT_NONE, 0>, cudaFuncAttributeMaxDynamicSharedMemorySize, BG_DSM);
    cudaFuncSetAttribute(bgemm2_kernel<ACT_SILU, 1>, cudaFuncAttributeMaxDynamicSharedMemorySize, BG_DSM);
    cudaFuncSetAttribute(bgemm2_kernel<ACT_SIGMOID, 0>, cudaFuncAttributeMaxDynamicSharedMemorySize, BG_DSM);
    cudaFuncSetAttribute(bgemm2_kernel<ACT_GELU, 1>, cudaFuncAttributeMaxDynamicSharedMemorySize, BG_DSM);

    const int ew_blocks = Mrows * Dc / (256 * 4);
    dim3 tsb(32, 8);

    // ---- weight transpose + hi/lo split (bf16 planes) ----
    tsplit_kernel<<<dim3(QKVW / 32, Dc / 32), tsb>>>(wqkv, wH + OFF_QKV, wL + OFF_QKV, Dc, QKVW);
    tsplit_kernel<<<dim3(Dc / 32, Dc / 32), tsb>>>(wo, wH + OFF_WO, wL + OFF_WO, Dc, Dc);
    tsplit_kernel<<<dim3(Ec / 32, Dc / 32), tsb>>>(e2w1, wH + OFF_E2W1, wL + OFF_E2W1, Dc, Ec);
    tsplit_kernel<<<dim3(Dc / 32, Ec / 32), tsb>>>(e2w2, wH + OFF_E2W2, wL + OFF_E2W2, Ec, Dc);
    tsplit_kernel<<<dim3(Fc / 32, Dc / 32), tsb>>>(mw1, wH + OFF_MW1, wL + OFF_MW1, Dc, Fc);
    tsplit_kernel<<<dim3(Dc / 32, Fc / 32), tsb>>>(mw2, wH + OFF_MW2, wL + OFF_MW2, Fc, Dc);

    // ---- time_elapsic 1 (fp32 exact: feeds the LSH bucket path) ----
    build_h_kernel<<<ew_blocks, 256>>>(x, premix1, pH, nullptr, nullptr);
    sgemm_kernel<ACT_SILU><<<dim3(Ec / 128, Mrows / 128), 256>>>(pH, e1w1, e1b1, pE, Mrows, Ec, Dc, Ec, Ec);
    sgemm_kernel<ACT_SIGMOID><<<dim3(Dc / 128, Mrows / 128), 256>>>(pE, e1w2, e1b2, pG, Mrows, Dc, Ec, Dc, Dc);
    combine_kernel<<<ew_blocks, 256>>>(x, pG, pXA, aH, aL);

    // ---- QKV: K exact fp32 (buckets!), Q & V via HMMA bf16x3 ----
    sgemm_kernel<ACT_NONE><<<dim3(8, Mrows / 128), 256>>>(pXA, wqkv + 1024, bqkv + 1024, pQKV + 1024, Mrows, 1024, Dc, QKVW, QKVW);
    bgemm2_kernel<ACT_NONE, 0><<<dim3(8, 128), 256, BG_DSM>>>(aH, aL, Dc, wH + OFF_QKV, wL + OFF_QKV, bqkv, pQKV, nullptr, nullptr, Dc, QKVW);
    bgemm2_kernel<ACT_NONE, 0><<<dim3(8, 128), 256, BG_DSM>>>(aH, aL, Dc, wH + OFF_QKV + (size_t)2048 * Dc, wL + OFF_QKV + (size_t)2048 * Dc, bqkv + 2048, pQKV + 2048, nullptr, nullptr, Dc, QKVW);

    hash_kernel<<<dim3(Sc / 128, Bc * Hc), 128>>>(pQKV, rot, pBk);
    sort_kernel<<<Bc * Hc, 64>>>(pBk, pIdx, pBs);
    attn_kernel<<<dim3(NCHUNK, Bc * Hc), 128>>>(pQKV, pIdx, pBs, aH, aL);  // ATT planes overwrite XA planes
    bgemm2_kernel<ACT_NONE, 0><<<dim3(8, 128), 256, BG_DSM>>>(aH, aL, Dc, wH + OFF_WO, wL + OFF_WO, bo, pT, nullptr, nullptr, Dc, Dc);
    ln_add_kernel<<<Mrows, 256>>>(x, pT, ln1g, ln1b, pX1);

    // ---- time_elapsic 2 (tensor) ----
    build_h_kernel<<<ew_blocks, 256>>>(pX1, premix2, pH, aH, aL);
    bgemm2_kernel<ACT_SILU, 1><<<dim3(2, 128), 256, BG_DSM>>>(aH, aL, Dc, wH + OFF_E2W1, wL + OFF_E2W1, e2b1, nullptr, eH, eL, Dc, Ec);
    bgemm2_kernel<ACT_SIGMOID, 0><<<dim3(8, 128), 256, BG_DSM>>>(eH, eL, Ec, wH + OFF_E2W2, wL + OFF_E2W2, e2b2, pG, nullptr, nullptr, Ec, Dc);
    combine_kernel<<<ew_blocks, 256>>>(pX1, pG, pXA, aH, aL);

    // ---- MLP + deepembed + LN2 (tensor; F kept bf16-planes only) ----
    bgemm2_kernel<ACT_GELU, 1><<<dim3(32, 128), 256, BG_DSM>>>(aH, aL, Dc, wH + OFF_MW1, wL + OFF_MW1, mb1, nullptr, fH, fL, Dc, Fc);
    bgemm2_kernel<ACT_NONE, 0><<<dim3(8, 128), 256, BG_DSM>>>(fH, fL, Fc, wH + OFF_MW2, wL + OFF_MW2, mb2, pT, nullptr, nullptr, Fc, Dc);
    ln_emb_kernel<<<Mrows, 256>>>(pX1, pT, emb, ph, ln2g, ln2b, out);
}

// round 9
// speedup vs baseline: 2.0154x; 1.0812x over previous
#include <cuda_runtime.h>
#include <cuda_bf16.h>
#include <math.h>
#include <stdint.h>

// ---------------- problem constants ----------------
#define Bc 4
#define Sc 4096
#define Dc 1024
#define Hc 16
#define Dhc 64
#define Ec 256
#define Fc 4096
#define CHUNKc 128
#define Mrows (Bc * Sc)          // 16384
#define QKVW (3 * Hc * Dhc)      // 3072
#define NCHUNK (Sc / CHUNKc)     // 32

// weight-plane offsets (elements) inside g_wt
#define OFF_QKV  0
#define OFF_WO   3145728
#define OFF_E2W1 4194304
#define OFF_E2W2 4456448
#define OFF_MW1  4718592
#define OFF_MW2  8912896
#define WT_TOT   13107200

// ---------------- scratch (device globals; no allocations allowed) ----------------
__device__ float g_bufH[(size_t)Mrows * Dc];
__device__ float g_bufE[(size_t)Mrows * Ec];
__device__ float g_bufG[(size_t)Mrows * Dc];
__device__ float g_bufXA[(size_t)Mrows * Dc];
__device__ float g_bufQKV[(size_t)Mrows * QKVW];
__device__ float g_bufT[(size_t)Mrows * Dc];
__device__ float g_bufX1[(size_t)Mrows * Dc];
__device__ int g_buckets[Bc * Hc * Sc];
__device__ int g_idx[Bc * Hc * Sc];
__device__ int g_bsort[Bc * Hc * Sc];
// bf16 hi/lo planes
__device__ __nv_bfloat16 g_a16h[(size_t)Mrows * Dc];
__device__ __nv_bfloat16 g_a16l[(size_t)Mrows * Dc];
__device__ __nv_bfloat16 g_e16h[(size_t)Mrows * Ec];
__device__ __nv_bfloat16 g_e16l[(size_t)Mrows * Ec];
__device__ __nv_bfloat16 g_f16h[(size_t)Mrows * Fc];
__device__ __nv_bfloat16 g_f16l[(size_t)Mrows * Fc];
__device__ __nv_bfloat16 g_wth[WT_TOT];
__device__ __nv_bfloat16 g_wtl[WT_TOT];

// ---------------- activations ----------------
enum { ACT_NONE = 0, ACT_SILU = 1, ACT_GELU = 2, ACT_SIGMOID = 3 };

template <int ACT>
__device__ __forceinline__ float apply_act(float x) {
    if (ACT == ACT_SILU) return x / (1.f + __expf(-x));
    if (ACT == ACT_GELU) {
        float t = tanhf(0.7978845608028654f * (x + 0.044715f * x * x * x));
        return 0.5f * x * (1.f + t);
    }
    if (ACT == ACT_SIGMOID) return 1.f / (1.f + __expf(-x));
    return x;
}

__device__ __forceinline__ uint32_t smem_u32(const void* p) {
    uint32_t a;
    asm("{ .reg .u64 t; cvta.to.shared.u64 t, %1; cvt.u32.u64 %0, t; }" : "=r"(a) : "l"(p));
    return a;
}
__device__ __forceinline__ uint32_t pack_bf2(__nv_bfloat16 a, __nv_bfloat16 b) {
    __nv_bfloat162 t; t.x = a; t.y = b;
    return *(uint32_t*)&t;
}
__device__ __forceinline__ void split2(float v, __nv_bfloat16& h, __nv_bfloat16& l) {
    h = __float2bfloat16(v);
    l = __float2bfloat16(v - __bfloat162float(h));
}
__device__ __forceinline__ void cpa16(uint32_t dst, const void* src) {
    asm volatile("cp.async.cg.shared.global [%0], [%1], 16;" :: "r"(dst), "l"(src));
}
__device__ __forceinline__ void mma16816(float* c, const uint32_t* a, const uint32_t* b) {
    asm volatile(
        "mma.sync.aligned.m16n8k16.row.col.f32.bf16.bf16.f32 "
        "{%0,%1,%2,%3}, {%4,%5,%6,%7}, {%8,%9}, {%0,%1,%2,%3};"
        : "+f"(c[0]), "+f"(c[1]), "+f"(c[2]), "+f"(c[3])
        : "r"(a[0]), "r"(a[1]), "r"(a[2]), "r"(a[3]), "r"(b[0]), "r"(b[1]));
}
__device__ __forceinline__ void ldm4(uint32_t* d, uint32_t addr) {
    asm volatile("ldmatrix.sync.aligned.m8n8.x4.shared.b16 {%0,%1,%2,%3}, [%4];"
                 : "=r"(d[0]), "=r"(d[1]), "=r"(d[2]), "=r"(d[3]) : "r"(addr));
}

// ---------------- weight transpose+split: W[K,N] -> Wt hi/lo [N,K] ----------------
__global__ void tsplit_kernel(const float* __restrict__ W,
                              __nv_bfloat16* __restrict__ tH, __nv_bfloat16* __restrict__ tL,
                              int K, int N)
{
    __shared__ float t[32][33];
    int n0 = blockIdx.x * 32, k0 = blockIdx.y * 32;
    int tx = threadIdx.x, ty = threadIdx.y;
#pragma unroll
    for (int i = 0; i < 4; i++) {
        int k = k0 + ty + i * 8;
        t[ty + i * 8][tx] = W[(size_t)k * N + n0 + tx];
    }
    __syncthreads();
#pragma unroll
    for (int i = 0; i < 4; i++) {
        int n = n0 + ty + i * 8;
        float v = t[tx][ty + i * 8];
        __nv_bfloat16 h, l;
        split2(v, h, l);
        tH[(size_t)n * K + k0 + tx] = h;
        tL[(size_t)n * K + k0 + tx] = l;
    }
}

// ============ bf16x3 HMMA GEMM: cp.async double buffering + ldmatrix frags ============
// A planes [M, lda] bf16 (hi/lo), Bt planes [N, K] bf16 (hi/lo; pre-transposed weights).
// Block tile 128x128, BK=32, 256 threads (8 warps, warp tile 64x32).
#define ST_EL 5120      // elems per plane per stage (128*40)
#define STAGE_EL 20480  // 4 planes
#define BG_DSM (2 * STAGE_EL * 2)  // bytes = 81920

__device__ __forceinline__ void bg_stage(
    uint32_t sbase, int s, int c, int tid, int row0, int n0,
    const __nv_bfloat16* __restrict__ aHi, const __nv_bfloat16* __restrict__ aLo, int lda,
    const __nv_bfloat16* __restrict__ btHi, const __nv_bfloat16* __restrict__ btLo, int K)
{
    int k0 = c * 32;
#pragma unroll
    for (int j = 0; j < 2; j++) {
        int c2 = tid + j * 256;
        int row = c2 >> 2, seg = (c2 & 3) << 3;
        uint32_t off = sbase + (uint32_t)(s * STAGE_EL + row * 40 + seg) * 2;
        size_t ga = (size_t)(row0 + row) * lda + k0 + seg;
        size_t gb = (size_t)(n0 + row) * K + k0 + seg;
        cpa16(off,                 aHi + ga);
        cpa16(off + ST_EL * 2,     aLo + ga);
        cpa16(off + 2 * ST_EL * 2, btHi + gb);
        cpa16(off + 3 * ST_EL * 2, btLo + gb);
    }
}

template <int ACT, int OUT16>
__global__ __launch_bounds__(256, 2) void bgemm2_kernel(
    const __nv_bfloat16* __restrict__ aHi, const __nv_bfloat16* __restrict__ aLo, int lda,
    const __nv_bfloat16* __restrict__ btHi, const __nv_bfloat16* __restrict__ btLo,
    const float* __restrict__ bias, float* __restrict__ C,
    __nv_bfloat16* __restrict__ cH, __nv_bfloat16* __restrict__ cL,
    int K, int ldc)
{
    extern __shared__ __align__(16) char dsm[];
    uint32_t sbase = smem_u32(dsm);

    int tid = threadIdx.x;
    int wid = tid >> 5, lane = tid & 31;
    int n0 = blockIdx.x * 128;
    int row0 = blockIdx.y * 128;
    int wm = (wid & 1) * 64;
    int wn = (wid >> 1) * 32;
    int lr = lane >> 2;
    int lc = (lane & 3) * 2;

    // ldmatrix per-lane address components (element offsets within a plane)
    int a_row_off = (lane & 15);            // row within 16-row tile
    int a_col_off = (lane >> 4) * 8;        // k-half select
    int b_row_off = (lane & 7) + (lane >> 4) * 8;   // n within 16-n pair-block
    int b_col_off = ((lane >> 3) & 1) * 8;  // k-half select

    float acc[4][4][4];
#pragma unroll
    for (int mt = 0; mt < 4; mt++)
#pragma unroll
        for (int nt = 0; nt < 4; nt++)
#pragma unroll
            for (int e = 0; e < 4; e++) acc[mt][nt][e] = 0.f;

    int nch = K >> 5;
    bg_stage(sbase, 0, 0, tid, row0, n0, aHi, aLo, lda, btHi, btLo, K);
    asm volatile("cp.async.commit_group;");

    for (int c = 0; c < nch; c++) {
        if (c + 1 < nch) {
            bg_stage(sbase, (c + 1) & 1, c + 1, tid, row0, n0, aHi, aLo, lda, btHi, btLo, K);
            asm volatile("cp.async.commit_group;");
            asm volatile("cp.async.wait_group 1;");
        } else {
            asm volatile("cp.async.wait_group 0;");
        }
        __syncthreads();

        int s = c & 1;
        uint32_t pAh = sbase + (uint32_t)(s * STAGE_EL) * 2;
        uint32_t pAl = pAh + ST_EL * 2;
        uint32_t pBh = pAh + 2 * ST_EL * 2;
        uint32_t pBl = pAh + 3 * ST_EL * 2;

#pragma unroll
        for (int kt = 0; kt < 32; kt += 16) {
            uint32_t bh[4][2], bl[4][2];
#pragma unroll
            for (int np = 0; np < 2; np++) {
                uint32_t off = (uint32_t)((wn + np * 16 + b_row_off) * 40 + kt + b_col_off) * 2;
                uint32_t d[4];
                ldm4(d, pBh + off);
                bh[np * 2][0] = d[0]; bh[np * 2][1] = d[1];
                bh[np * 2 + 1][0] = d[2]; bh[np * 2 + 1][1] = d[3];
                ldm4(d, pBl + off);
                bl[np * 2][0] = d[0]; bl[np * 2][1] = d[1];
                bl[np * 2 + 1][0] = d[2]; bl[np * 2 + 1][1] = d[3];
            }
#pragma unroll
            for (int mt = 0; mt < 4; mt++) {
                uint32_t off = (uint32_t)((wm + mt * 16 + a_row_off) * 40 + kt + a_col_off) * 2;
                uint32_t ah[4], al[4];
                ldm4(ah, pAh + off);
                ldm4(al, pAl + off);
#pragma unroll
                for (int nt = 0; nt < 4; nt++) {
                    mma16816(acc[mt][nt], ah, bh[nt]);
                    mma16816(acc[mt][nt], ah, bl[nt]);
                    mma16816(acc[mt][nt], al, bh[nt]);
                }
            }
        }
        __syncthreads();
    }

    // ---- epilogue ----
#pragma unroll
    for (int mt = 0; mt < 4; mt++) {
        int row = row0 + wm + mt * 16 + lr;
#pragma unroll
        for (int nt = 0; nt < 4; nt++) {
            int col = n0 + wn + nt * 8 + lc;
            float b0 = bias[col], b1 = bias[col + 1];
            float v00 = apply_act<ACT>(acc[mt][nt][0] + b0);
            float v01 = apply_act<ACT>(acc[mt][nt][1] + b1);
            float v10 = apply_act<ACT>(acc[mt][nt][2] + b0);
            float v11 = apply_act<ACT>(acc[mt][nt][3] + b1);
            if (OUT16) {
                __nv_bfloat16 h0, l0, h1, l1;
                split2(v00, h0, l0); split2(v01, h1, l1);
                *(uint32_t*)&cH[(size_t)row * ldc + col] = pack_bf2(h0, h1);
                *(uint32_t*)&cL[(size_t)row * ldc + col] = pack_bf2(l0, l1);
                split2(v10, h0, l0); split2(v11, h1, l1);
                *(uint32_t*)&cH[(size_t)(row + 8) * ldc + col] = pack_bf2(h0, h1);
                *(uint32_t*)&cL[(size_t)(row + 8) * ldc + col] = pack_bf2(l0, l1);
            } else {
                *(float2*)(C + (size_t)row * ldc + col) = make_float2(v00, v01);
                *(float2*)(C + (size_t)(row + 8) * ldc + col) = make_float2(v10, v11);
            }
        }
    }
}

// ---------------- fp32 SGEMM (bucket-exact path) ----------------
template <int ACT>
__global__ __launch_bounds__(256, 2) void sgemm_kernel(
    const float* __restrict__ A, const float* __restrict__ B,
    const float* __restrict__ bias, float* __restrict__ C,
    int M, int N, int K, int ldb, int ldc)
{
    __shared__ __align__(16) float As[16][132];
    __shared__ __align__(16) float Bs[16][128];
    int tid = threadIdx.x;
    int col0 = blockIdx.x * 128;
    int row0 = blockIdx.y * 128;
    int ty = tid >> 4, tx = tid & 15;

    float acc[8][8];
#pragma unroll
    for (int i = 0; i < 8; i++)
#pragma unroll
        for (int j = 0; j < 8; j++) acc[i][j] = 0.f;

    const float* Ablk = A + (size_t)row0 * K;
    const float* Bblk = B + col0;

    for (int k0 = 0; k0 < K; k0 += 16) {
#pragma unroll
        for (int t = 0; t < 2; t++) {
            int la = tid + t * 256;
            int ar = la >> 2, ac = (la & 3) << 2;
            float4 av = *(const float4*)(Ablk + (size_t)ar * K + k0 + ac);
            As[ac + 0][ar] = av.x;
            As[ac + 1][ar] = av.y;
            As[ac + 2][ar] = av.z;
            As[ac + 3][ar] = av.w;
            int br = la >> 5, bc = (la & 31) << 2;
            *(float4*)&Bs[br][bc] = *(const float4*)(Bblk + (size_t)(k0 + br) * ldb + bc);
        }
        __syncthreads();
#pragma unroll
        for (int kk = 0; kk < 16; kk++) {
            float ra[8], rb[8];
            *(float4*)(ra) = *(const float4*)&As[kk][ty * 8];
            *(float4*)(ra + 4) = *(const float4*)&As[kk][ty * 8 + 4];
            *(float4*)(rb) = *(const float4*)&Bs[kk][tx * 8];
            *(float4*)(rb + 4) = *(const float4*)&Bs[kk][tx * 8 + 4];
#pragma unroll
            for (int i = 0; i < 8; i++)
#pragma unroll
                for (int j = 0; j < 8; j++) acc[i][j] += ra[i] * rb[j];
        }
        __syncthreads();
    }

#pragma unroll
    for (int i = 0; i < 8; i++) {
        size_t r = (size_t)row0 + ty * 8 + i;
#pragma unroll
        for (int j = 0; j < 8; j += 4) {
            int c = col0 + tx * 8 + j;
            float4 o;
            o.x = apply_act<ACT>(acc[i][j + 0] + bias[c + 0]);
            o.y = apply_act<ACT>(acc[i][j + 1] + bias[c + 1]);
            o.z = apply_act<ACT>(acc[i][j + 2] + bias[c + 2]);
            o.w = apply_act<ACT>(acc[i][j + 3] + bias[c + 3]);
            *(float4*)(C + r * ldc + c) = o;
        }
    }
}

// ---------------- time_elapsic helpers (optionally emit bf16 planes) ----------------
__global__ void build_h_kernel(const float* __restrict__ x,
                               const float* __restrict__ premix,
                               float* __restrict__ out,
                               __nv_bfloat16* __restrict__ oH,
                               __nv_bfloat16* __restrict__ oL)
{
    size_t i4 = (size_t)blockIdx.x * blockDim.x + threadIdx.x;
    size_t base = i4 * 4;
    int d = (int)(base & (Dc - 1));
    int row = (int)(base >> 10);
    int s = row & (Sc - 1);
    float4 xv = *(const float4*)(x + base);
    float4 pv = (s > 0) ? *(const float4*)(x + base - Dc) : make_float4(0.f, 0.f, 0.f, 0.f);
    float4 pm = *(const float4*)(premix + d);
    float4 o;
    o.x = xv.x + (pv.x - xv.x) * pm.x;
    o.y = xv.y + (pv.y - xv.y) * pm.y;
    o.z = xv.z + (pv.z - xv.z) * pm.z;
    o.w = xv.w + (pv.w - xv.w) * pm.w;
    *(float4*)(out + base) = o;
    if (oH) {
        __nv_bfloat16 h0, l0, h1, l1, h2, l2, h3, l3;
        split2(o.x, h0, l0); split2(o.y, h1, l1);
        split2(o.z, h2, l2); split2(o.w, h3, l3);
        *(uint2*)&oH[base] = make_uint2(pack_bf2(h0, h1), pack_bf2(h2, h3));
        *(uint2*)&oL[base] = make_uint2(pack_bf2(l0, l1), pack_bf2(l2, l3));
    }
}

__global__ void combine_kernel(const float* __restrict__ x,
                               const float* __restrict__ gate,
                               float* __restrict__ out,
                               __nv_bfloat16* __restrict__ oH,
                               __nv_bfloat16* __restrict__ oL)
{
    size_t i4 = (size_t)blockIdx.x * blockDim.x + threadIdx.x;
    size_t base = i4 * 4;
    int row = (int)(base >> 10);
    int s = row & (Sc - 1);
    float4 xv = *(const float4*)(x + base);
    float4 pv = (s > 0) ? *(const float4*)(x + base - Dc) : make_float4(0.f, 0.f, 0.f, 0.f);
    float4 gv = *(const float4*)(gate + base);
    float4 o;
    o.x = xv.x + (pv.x - xv.x) * gv.x;
    o.y = xv.y + (pv.y - xv.y) * gv.y;
    o.z = xv.z + (pv.z - xv.z) * gv.z;
    o.w = xv.w + (pv.w - xv.w) * gv.w;
    *(float4*)(out + base) = o;
    if (oH) {
        __nv_bfloat16 h0, l0, h1, l1, h2, l2, h3, l3;
        split2(o.x, h0, l0); split2(o.y, h1, l1);
        split2(o.z, h2, l2); split2(o.w, h3, l3);
        *(uint2*)&oH[base] = make_uint2(pack_bf2(h0, h1), pack_bf2(h2, h3));
        *(uint2*)&oL[base] = make_uint2(pack_bf2(l0, l1), pack_bf2(l2, l3));
    }
}

// ---------------- LSH hashing ----------------
__global__ void hash_kernel(const float* __restrict__ qkv,
                            const float* __restrict__ rot,
                            int* __restrict__ buckets)
{
    int bh = blockIdx.y;
    int b = bh >> 4, h = bh & 15;
    int s = blockIdx.x * 128 + threadIdx.x;
    __shared__ float rotS[Dhc * 32];
    for (int i = threadIdx.x; i < Dhc * 32; i += 128) rotS[i] = rot[h * (Dhc * 32) + i];
    __syncthreads();
    const float* kp = qkv + ((size_t)(b * Sc + s) * QKVW) + (Hc + h) * Dhc;
    float r[32];
#pragma unroll
    for (int n = 0; n < 32; n++) r[n] = 0.f;
    for (int d = 0; d < Dhc; d++) {
        float kd = kp[d];
#pragma unroll
        for (int n = 0; n < 32; n++) r[n] += kd * rotS[d * 32 + n];
    }
    float best = r[0];
    int bi = 0;
#pragma unroll
    for (int n = 1; n < 32; n++)
        if (r[n] > best) { best = r[n]; bi = n; }
#pragma unroll
    for (int n = 0; n < 32; n++)
        if (-r[n] > best) { best = -r[n]; bi = 32 + n; }
    buckets[(size_t)bh * Sc + s] = bi;
}

// ---------------- stable counting sort per (b,h) row ----------------
__global__ void sort_kernel(const int* __restrict__ buckets,
                            int* __restrict__ idx, int* __restrict__ bsort)
{
    int bh = blockIdx.x;
    int t = threadIdx.x;
    __shared__ int sb[Sc];
    __shared__ int cnt[64][64];
    __shared__ int base[64];
    const int* row = buckets + (size_t)bh * Sc;
    for (int i = t; i < Sc; i += 64) sb[i] = row[i];
    for (int v = 0; v < 64; v++) cnt[t][v] = 0;
    __syncthreads();
    for (int i = t * 64; i < t * 64 + 64; i++) cnt[t][sb[i]]++;
    __syncthreads();
    {
        int run = 0;
        for (int seg = 0; seg < 64; seg++) {
            int c = cnt[seg][t];
            cnt[seg][t] = run;
            run += c;
        }
        base[t] = run;
    }
    __syncthreads();
    if (t == 0) {
        int acc = 0;
        for (int v = 0; v < 64; v++) { int c = base[v]; base[v] = acc; acc += c; }
    }
    __syncthreads();
    int* idxrow = idx + (size_t)bh * Sc;
    int* bsrow = bsort + (size_t)bh * Sc;
    for (int i = t * 64; i < t * 64 + 64; i++) {
        int v = sb[i];
        int p = base[v] + cnt[t][v]++;
        idxrow[p] = i;
        bsrow[p] = v;
    }
}

// ---------------- chunked bucket-masked attention (writes bf16 hi/lo planes) ----------------
__global__ __launch_bounds__(128) void attn_kernel(
    const float* __restrict__ qkv, const int* __restrict__ idx,
    const int* __restrict__ bsort,
    __nv_bfloat16* __restrict__ yH, __nv_bfloat16* __restrict__ yL)
{
    int n = blockIdx.x;
    int bh = blockIdx.y;
    int b = bh >> 4, h = bh & 15;
    int tid = threadIdx.x;
    const int* idxrow = idx + (size_t)bh * Sc;
    const int* bsrow = bsort + (size_t)bh * Sc;

    int pq = n * CHUNKc + tid;
    int orig_q = idxrow[pq];
    int bq = bsrow[pq];
    const float* qptr = qkv + ((size_t)(b * Sc + orig_q) * QKVW) + h * Dhc;
    float4 qreg[16];
#pragma unroll
    for (int f = 0; f < 16; f++) qreg[f] = *(const float4*)(qptr + f * 4);

    float4 acc[16];
#pragma unroll
    for (int f = 0; f < 16; f++) acc[f] = make_float4(0.f, 0.f, 0.f, 0.f);
    float m = -1e30f, l = 0.f;

    __shared__ float4 KS[64 * 16];
    __shared__ float4 VS[64 * 16];
    __shared__ int BK[64];

    for (int tile = 0; tile < 4; tile++) {
        int t0 = tile * 64;
        for (int w = tid; w < 64 * 16; w += 128) {
            int slot = w >> 4, f = w & 15;
            int kslot = t0 + slot;
            int spos;
            bool ok;
            if (kslot < CHUNKc) { ok = (n > 0); spos = (n - 1) * CHUNKc + kslot; }
            else                { ok = true;    spos = n * CHUNKc + (kslot - CHUNKc); }
            if (ok) {
                int og = idxrow[spos];
                const float* kp = qkv + ((size_t)(b * Sc + og) * QKVW) + (Hc + h) * Dhc;
                KS[slot * 16 + f] = *(const float4*)(kp + f * 4);
                VS[slot * 16 + f] = *(const float4*)(kp + Hc * Dhc + f * 4);
                if (f == 0) BK[slot] = bsrow[spos];
            } else if (f == 0) {
                BK[slot] = -1;
            }
        }
        __syncthreads();
        for (int s = 0; s < 64; s++) {
            if (BK[s] != bq) continue;
            const float4* kp4 = &KS[s * 16];
            float dot = 0.f;
#pragma unroll
            for (int f = 0; f < 16; f++) {
                float4 kv = kp4[f];
                dot += qreg[f].x * kv.x + qreg[f].y * kv.y + qreg[f].z * kv.z + qreg[f].w * kv.w;
            }
            dot *= 0.125f;
            float p;
            if (dot > m) {
                float sc = __expf(m - dot);
                l *= sc;
#pragma unroll
                for (int f = 0; f < 16; f++) {
                    acc[f].x *= sc; acc[f].y *= sc; acc[f].z *= sc; acc[f].w *= sc;
                }
                m = dot;
                p = 1.f;
            } else {
                p = __expf(dot - m);
            }
            l += p;
            const float4* vp4 = &VS[s * 16];
#pragma unroll
            for (int f = 0; f < 16; f++) {
                float4 vv = vp4[f];
                acc[f].x += p * vv.x; acc[f].y += p * vv.y;
                acc[f].z += p * vv.z; acc[f].w += p * vv.w;
            }
        }
        __syncthreads();
    }
    float inv = 1.f / l;
    size_t ybase = ((size_t)(b * Sc + orig_q)) * Dc + h * Dhc;
#pragma unroll
    for (int f = 0; f < 16; f++) {
        float4 o = acc[f];
        o.x *= inv; o.y *= inv; o.z *= inv; o.w *= inv;
        __nv_bfloat16 h0, l0, h1, l1, h2, l2, h3, l3;
        split2(o.x, h0, l0); split2(o.y, h1, l1);
        split2(o.z, h2, l2); split2(o.w, h3, l3);
        *(uint2*)&yH[ybase + f * 4] = make_uint2(pack_bf2(h0, h1), pack_bf2(h2, h3));
        *(uint2*)&yL[ybase + f * 4] = make_uint2(pack_bf2(l0, l1), pack_bf2(l2, l3));
    }
}

// ---------------- LayerNorm(a + b) ----------------
__global__ void ln_add_kernel(const float* __restrict__ a, const float* __restrict__ bsum,
                              const float* __restrict__ g, const float* __restrict__ be,
                              float* __restrict__ out)
{
    int r = blockIdx.x, tid = threadIdx.x;
    size_t base = (size_t)r * Dc + tid * 4;
    float4 av = *(const float4*)(a + base);
    float4 bv = *(const float4*)(bsum + base);
    float4 v = make_float4(av.x + bv.x, av.y + bv.y, av.z + bv.z, av.w + bv.w);
    float s = v.x + v.y + v.z + v.w;
    float s2 = v.x * v.x + v.y * v.y + v.z * v.z + v.w * v.w;
    for (int o = 16; o > 0; o >>= 1) {
        s += __shfl_down_sync(~0u, s, o);
        s2 += __shfl_down_sync(~0u, s2, o);
    }
    __shared__ float ws[8], ws2[8];
    __shared__ float mean_s, rstd_s;
    int w = tid >> 5, ln = tid & 31;
    if (ln == 0) { ws[w] = s; ws2[w] = s2; }
    __syncthreads();
    if (tid == 0) {
        float S = 0.f, S2 = 0.f;
        for (int i = 0; i < 8; i++) { S += ws[i]; S2 += ws2[i]; }
        float mean = S * (1.f / Dc);
        float var = S2 * (1.f / Dc) - mean * mean;
        mean_s = mean;
        rstd_s = rsqrtf(var + 1e-5f);
    }
    __syncthreads();
    float mean = mean_s, rstd = rstd_s;
    float4 gv = *(const float4*)(g + tid * 4);
    float4 bev = *(const float4*)(be + tid * 4);
    float4 o;
    o.x = (v.x - mean) * rstd * gv.x + bev.x;
    o.y = (v.y - mean) * rstd * gv.y + bev.y;
    o.z = (v.z - mean) * rstd * gv.z + bev.z;
    o.w = (v.w - mean) * rstd * gv.w + bev.w;
    *(float4*)(out + base) = o;
}

// ---------------- LayerNorm(x1 + t * emb[ph]) ----------------
__global__ void ln_emb_kernel(const float* __restrict__ x1, const float* __restrict__ tin,
                              const float* __restrict__ emb, const int* __restrict__ ph,
                              const float* __restrict__ g, const float* __restrict__ be,
                              float* __restrict__ out)
{
    int r = blockIdx.x, tid = threadIdx.x;
    size_t base = (size_t)r * Dc + tid * 4;
    const float* er = emb + (size_t)ph[r] * Dc;
    float4 av = *(const float4*)(x1 + base);
    float4 tv = *(const float4*)(tin + base);
    float4 ev = *(const float4*)(er + tid * 4);
    float4 v = make_float4(av.x + tv.x * ev.x, av.y + tv.y * ev.y,
                           av.z + tv.z * ev.z, av.w + tv.w * ev.w);
    float s = v.x + v.y + v.z + v.w;
    float s2 = v.x * v.x + v.y * v.y + v.z * v.z + v.w * v.w;
    for (int o = 16; o > 0; o >>= 1) {
        s += __shfl_down_sync(~0u, s, o);
        s2 += __shfl_down_sync(~0u, s2, o);
    }
    __shared__ float ws[8], ws2[8];
    __shared__ float mean_s, rstd_s;
    int w = tid >> 5, ln = tid & 31;
    if (ln == 0) { ws[w] = s; ws2[w] = s2; }
    __syncthreads();
    if (tid == 0) {
        float S = 0.f, S2 = 0.f;
        for (int i = 0; i < 8; i++) { S += ws[i]; S2 += ws2[i]; }
        float mean = S * (1.f / Dc);
        float var = S2 * (1.f / Dc) - mean * mean;
        mean_s = mean;
        rstd_s = rsqrtf(var + 1e-5f);
    }
    __syncthreads();
    float mean = mean_s, rstd = rstd_s;
    float4 gv = *(const float4*)(g + tid * 4);
    float4 bev = *(const float4*)(be + tid * 4);
    float4 o;
    o.x = (v.x - mean) * rstd * gv.x + bev.x;
    o.y = (v.y - mean) * rstd * gv.y + bev.y;
    o.z = (v.z - mean) * rstd * gv.z + bev.z;
    o.w = (v.w - mean) * rstd * gv.w + bev.w;
    *(float4*)(out + base) = o;
}

// ---------------- launch ----------------
extern "C" void kernel_launch(void* const* d_in, const int* in_sizes, int n_in,
                              void* d_out, int out_size)
{
    const float* x       = (const float*)d_in[0];
    const float* premix1 = (const float*)d_in[1];
    const float* e1w1    = (const float*)d_in[2];
    const float* e1b1    = (const float*)d_in[3];
    const float* e1w2    = (const float*)d_in[4];
    const float* e1b2    = (const float*)d_in[5];
    const float* premix2 = (const float*)d_in[6];
    const float* e2w1    = (const float*)d_in[7];
    const float* e2b1    = (const float*)d_in[8];
    const float* e2w2    = (const float*)d_in[9];
    const float* e2b2    = (const float*)d_in[10];
    const float* wqkv    = (const float*)d_in[11];
    const float* bqkv    = (const float*)d_in[12];
    const float* wo      = (const float*)d_in[13];
    const float* bo      = (const float*)d_in[14];
    const float* rot     = (const float*)d_in[15];
    const float* ln1g    = (const float*)d_in[16];
    const float* ln1b    = (const float*)d_in[17];
    const float* ln2g    = (const float*)d_in[18];
    const float* ln2b    = (const float*)d_in[19];
    const float* emb     = (const float*)d_in[20];
    const float* mw1     = (const float*)d_in[21];
    const float* mb1     = (const float*)d_in[22];
    const float* mw2     = (const float*)d_in[23];
    const float* mb2     = (const float*)d_in[24];
    const int*   ph      = (const int*)d_in[25];
    float* out = (float*)d_out;

    float *pH, *pE, *pG, *pXA, *pQKV, *pT, *pX1;
    int *pBk, *pIdx, *pBs;
    __nv_bfloat16 *aH, *aL, *eH, *eL, *fH, *fL, *wH, *wL;
    cudaGetSymbolAddress((void**)&pH, g_bufH);
    cudaGetSymbolAddress((void**)&pE, g_bufE);
    cudaGetSymbolAddress((void**)&pG, g_bufG);
    cudaGetSymbolAddress((void**)&pXA, g_bufXA);
    cudaGetSymbolAddress((void**)&pQKV, g_bufQKV);
    cudaGetSymbolAddress((void**)&pT, g_bufT);
    cudaGetSymbolAddress((void**)&pX1, g_bufX1);
    cudaGetSymbolAddress((void**)&pBk, g_buckets);
    cudaGetSymbolAddress((void**)&pIdx, g_idx);
    cudaGetSymbolAddress((void**)&pBs, g_bsort);
    cudaGetSymbolAddress((void**)&aH, g_a16h);
    cudaGetSymbolAddress((void**)&aL, g_a16l);
    cudaGetSymbolAddress((void**)&eH, g_e16h);
    cudaGetSymbolAddress((void**)&eL, g_e16l);
    cudaGetSymbolAddress((void**)&fH, g_f16h);
    cudaGetSymbolAddress((void**)&fL, g_f16l);
    cudaGetSymbolAddress((void**)&wH, g_wth);
    cudaGetSymbolAddress((void**)&wL, g_wtl);

    cudaFuncSetAttribute(bgemm2_kernel<ACT_NONE, 0>, cudaFuncAttributeMaxDynamicSharedMemorySize, BG_DSM);
    cudaFuncSetAttribute(bgemm2_kernel<ACT_SILU, 1>, cudaFuncAttributeMaxDynamicSharedMemorySize, BG_DSM);
    cudaFuncSetAttribute(bgemm2_kernel<ACT_SIGMOID, 0>, cudaFuncAttributeMaxDynamicSharedMemorySize, BG_DSM);
    cudaFuncSetAttribute(bgemm2_kernel<ACT_GELU, 1>, cudaFuncAttributeMaxDynamicSharedMemorySize, BG_DSM);

    const int ew_blocks = Mrows * Dc / (256 * 4);
    dim3 tsb(32, 8);

    // ---- weight transpose + hi/lo split (bf16 planes) ----
    tsplit_kernel<<<dim3(QKVW / 32, Dc / 32), tsb>>>(wqkv, wH + OFF_QKV, wL + OFF_QKV, Dc, QKVW);
    tsplit_kernel<<<dim3(Dc / 32, Dc / 32), tsb>>>(wo, wH + OFF_WO, wL + OFF_WO, Dc, Dc);
    tsplit_kernel<<<dim3(Ec / 32, Dc / 32), tsb>>>(e2w1, wH + OFF_E2W1, wL + OFF_E2W1, Dc, Ec);
    tsplit_kernel<<<dim3(Dc / 32, Ec / 32), tsb>>>(e2w2, wH + OFF_E2W2, wL + OFF_E2W2, Ec, Dc);
    tsplit_kernel<<<dim3(Fc / 32, Dc / 32), tsb>>>(mw1, wH + OFF_MW1, wL + OFF_MW1, Dc, Fc);
    tsplit_kernel<<<dim3(Dc / 32, Fc / 32), tsb>>>(mw2, wH + OFF_MW2, wL + OFF_MW2, Fc, Dc);

    // ---- time_elapsic 1 (fp32 exact: feeds the LSH bucket path) ----
    build_h_kernel<<<ew_blocks, 256>>>(x, premix1, pH, nullptr, nullptr);
    sgemm_kernel<ACT_SILU><<<dim3(Ec / 128, Mrows / 128), 256>>>(pH, e1w1, e1b1, pE, Mrows, Ec, Dc, Ec, Ec);
    sgemm_kernel<ACT_SIGMOID><<<dim3(Dc / 128, Mrows / 128), 256>>>(pE, e1w2, e1b2, pG, Mrows, Dc, Ec, Dc, Dc);
    combine_kernel<<<ew_blocks, 256>>>(x, pG, pXA, aH, aL);

    // ---- QKV: K exact fp32 (buckets!), Q & V via HMMA bf16x3 ----
    sgemm_kernel<ACT_NONE><<<dim3(8, Mrows / 128), 256>>>(pXA, wqkv + 1024, bqkv + 1024, pQKV + 1024, Mrows, 1024, Dc, QKVW, QKVW);
    bgemm2_kernel<ACT_NONE, 0><<<dim3(8, 128), 256, BG_DSM>>>(aH, aL, Dc, wH + OFF_QKV, wL + OFF_QKV, bqkv, pQKV, nullptr, nullptr, Dc, QKVW);
    bgemm2_kernel<ACT_NONE, 0><<<dim3(8, 128), 256, BG_DSM>>>(aH, aL, Dc, wH + OFF_QKV + (size_t)2048 * Dc, wL + OFF_QKV + (size_t)2048 * Dc, bqkv + 2048, pQKV + 2048, nullptr, nullptr, Dc, QKVW);

    hash_kernel<<<dim3(Sc / 128, Bc * Hc), 128>>>(pQKV, rot, pBk);
    sort_kernel<<<Bc * Hc, 64>>>(pBk, pIdx, pBs);
    attn_kernel<<<dim3(NCHUNK, Bc * Hc), 128>>>(pQKV, pIdx, pBs, aH, aL);  // ATT planes overwrite XA planes
    bgemm2_kernel<ACT_NONE, 0><<<dim3(8, 128), 256, BG_DSM>>>(aH, aL, Dc, wH + OFF_WO, wL + OFF_WO, bo, pT, nullptr, nullptr, Dc, Dc);
    ln_add_kernel<<<Mrows, 256>>>(x, pT, ln1g, ln1b, pX1);

    // ---- time_elapsic 2 (tensor) ----
    build_h_kernel<<<ew_blocks, 256>>>(pX1, premix2, pH, aH, aL);
    bgemm2_kernel<ACT_SILU, 1><<<dim3(2, 128), 256, BG_DSM>>>(aH, aL, Dc, wH + OFF_E2W1, wL + OFF_E2W1, e2b1, nullptr, eH, eL, Dc, Ec);
    bgemm2_kernel<ACT_SIGMOID, 0><<<dim3(8, 128), 256, BG_DSM>>>(eH, eL, Ec, wH + OFF_E2W2, wL + OFF_E2W2, e2b2, pG, nullptr, nullptr, Ec, Dc);
    combine_kernel<<<ew_blocks, 256>>>(pX1, pG, pXA, aH, aL);

    // ---- MLP + deepembed + LN2 (tensor; F kept bf16-planes only) ----
    bgemm2_kernel<ACT_GELU, 1><<<dim3(32, 128), 256, BG_DSM>>>(aH, aL, Dc, wH + OFF_MW1, wL + OFF_MW1, mb1, nullptr, fH, fL, Dc, Fc);
    bgemm2_kernel<ACT_NONE, 0><<<dim3(8, 128), 256, BG_DSM>>>(fH, fL, Fc, wH + OFF_MW2, wL + OFF_MW2, mb2, pT, nullptr, nullptr, Fc, Dc);
    ln_emb_kernel<<<Mrows, 256>>>(pX1, pT, emb, ph, ln2g, ln2b, out);
}

// round 10
// speedup vs baseline: 2.0528x; 1.0186x over previous
#include <cuda_runtime.h>
#include <cuda_bf16.h>
#include <math.h>
#include <stdint.h>

// ---------------- problem constants ----------------
#define Bc 4
#define Sc 4096
#define Dc 1024
#define Hc 16
#define Dhc 64
#define Ec 256
#define Fc 4096
#define CHUNKc 128
#define Mrows (Bc * Sc)          // 16384
#define QKVW (3 * Hc * Dhc)      // 3072
#define NCHUNK (Sc / CHUNKc)     // 32

// weight-plane offsets (elements) inside g_wt
#define OFF_QKV  0
#define OFF_WO   3145728
#define OFF_E2W1 4194304
#define OFF_E2W2 4456448
#define OFF_MW1  4718592
#define OFF_MW2  8912896
#define WT_TOT   13107200

// ---------------- scratch (device globals; no allocations allowed) ----------------
__device__ float g_bufH[(size_t)Mrows * Dc];
__device__ float g_bufE[(size_t)Mrows * Ec];
__device__ float g_bufG[(size_t)Mrows * Dc];
__device__ float g_bufXA[(size_t)Mrows * Dc];
__device__ float g_bufQKV[(size_t)Mrows * QKVW];
__device__ float g_bufT[(size_t)Mrows * Dc];
__device__ float g_bufX1[(size_t)Mrows * Dc];
__device__ int g_buckets[Bc * Hc * Sc];
__device__ int g_idx[Bc * Hc * Sc];
__device__ int g_bsort[Bc * Hc * Sc];
// bf16 hi/lo planes
__device__ __nv_bfloat16 g_a16h[(size_t)Mrows * Dc];
__device__ __nv_bfloat16 g_a16l[(size_t)Mrows * Dc];
__device__ __nv_bfloat16 g_e16h[(size_t)Mrows * Ec];
__device__ __nv_bfloat16 g_e16l[(size_t)Mrows * Ec];
__device__ __nv_bfloat16 g_f16h[(size_t)Mrows * Fc];
__device__ __nv_bfloat16 g_f16l[(size_t)Mrows * Fc];
__device__ __nv_bfloat16 g_wth[WT_TOT];
__device__ __nv_bfloat16 g_wtl[WT_TOT];

// ---------------- activations ----------------
enum { ACT_NONE = 0, ACT_SILU = 1, ACT_GELU = 2, ACT_SIGMOID = 3 };

template <int ACT>
__device__ __forceinline__ float apply_act(float x) {
    if (ACT == ACT_SILU) return x / (1.f + __expf(-x));
    if (ACT == ACT_GELU) {
        float t = tanhf(0.7978845608028654f * (x + 0.044715f * x * x * x));
        return 0.5f * x * (1.f + t);
    }
    if (ACT == ACT_SIGMOID) return 1.f / (1.f + __expf(-x));
    return x;
}

__device__ __forceinline__ uint32_t smem_u32(const void* p) {
    uint32_t a;
    asm("{ .reg .u64 t; cvta.to.shared.u64 t, %1; cvt.u32.u64 %0, t; }" : "=r"(a) : "l"(p));
    return a;
}
__device__ __forceinline__ uint32_t pack_bf2(__nv_bfloat16 a, __nv_bfloat16 b) {
    __nv_bfloat162 t; t.x = a; t.y = b;
    return *(uint32_t*)&t;
}
__device__ __forceinline__ void split2(float v, __nv_bfloat16& h, __nv_bfloat16& l) {
    h = __float2bfloat16(v);
    l = __float2bfloat16(v - __bfloat162float(h));
}
__device__ __forceinline__ void cpa16(uint32_t dst, const void* src) {
    asm volatile("cp.async.cg.shared.global [%0], [%1], 16;" :: "r"(dst), "l"(src));
}
__device__ __forceinline__ void mma16816(float* c, const uint32_t* a, const uint32_t* b) {
    asm volatile(
        "mma.sync.aligned.m16n8k16.row.col.f32.bf16.bf16.f32 "
        "{%0,%1,%2,%3}, {%4,%5,%6,%7}, {%8,%9}, {%0,%1,%2,%3};"
        : "+f"(c[0]), "+f"(c[1]), "+f"(c[2]), "+f"(c[3])
        : "r"(a[0]), "r"(a[1]), "r"(a[2]), "r"(a[3]), "r"(b[0]), "r"(b[1]));
}
__device__ __forceinline__ void ldm4(uint32_t* d, uint32_t addr) {
    asm volatile("ldmatrix.sync.aligned.m8n8.x4.shared.b16 {%0,%1,%2,%3}, [%4];"
                 : "=r"(d[0]), "=r"(d[1]), "=r"(d[2]), "=r"(d[3]) : "r"(addr));
}

// ---------------- weight transpose+split: W[K,N] -> Wt hi/lo [N,K] ----------------
__global__ void tsplit_kernel(const float* __restrict__ W,
                              __nv_bfloat16* __restrict__ tH, __nv_bfloat16* __restrict__ tL,
                              int K, int N)
{
    __shared__ float t[32][33];
    int n0 = blockIdx.x * 32, k0 = blockIdx.y * 32;
    int tx = threadIdx.x, ty = threadIdx.y;
#pragma unroll
    for (int i = 0; i < 4; i++) {
        int k = k0 + ty + i * 8;
        t[ty + i * 8][tx] = W[(size_t)k * N + n0 + tx];
    }
    __syncthreads();
#pragma unroll
    for (int i = 0; i < 4; i++) {
        int n = n0 + ty + i * 8;
        float v = t[tx][ty + i * 8];
        __nv_bfloat16 h, l;
        split2(v, h, l);
        tH[(size_t)n * K + k0 + tx] = h;
        tL[(size_t)n * K + k0 + tx] = l;
    }
}

// ============ bf16x3 HMMA GEMM: cp.async double buffering + ldmatrix frags ============
#define ST_EL 5120      // elems per plane per stage (128*40)
#define STAGE_EL 20480  // 4 planes
#define BG_DSM (2 * STAGE_EL * 2)  // bytes = 81920

__device__ __forceinline__ void bg_stage(
    uint32_t sbase, int s, int c, int tid, int row0, int n0,
    const __nv_bfloat16* __restrict__ aHi, const __nv_bfloat16* __restrict__ aLo, int lda,
    const __nv_bfloat16* __restrict__ btHi, const __nv_bfloat16* __restrict__ btLo, int K)
{
    int k0 = c * 32;
#pragma unroll
    for (int j = 0; j < 2; j++) {
        int c2 = tid + j * 256;
        int row = c2 >> 2, seg = (c2 & 3) << 3;
        uint32_t off = sbase + (uint32_t)(s * STAGE_EL + row * 40 + seg) * 2;
        size_t ga = (size_t)(row0 + row) * lda + k0 + seg;
        size_t gb = (size_t)(n0 + row) * K + k0 + seg;
        cpa16(off,                 aHi + ga);
        cpa16(off + ST_EL * 2,     aLo + ga);
        cpa16(off + 2 * ST_EL * 2, btHi + gb);
        cpa16(off + 3 * ST_EL * 2, btLo + gb);
    }
}

template <int ACT, int OUT16>
__global__ __launch_bounds__(256, 2) void bgemm2_kernel(
    const __nv_bfloat16* __restrict__ aHi, const __nv_bfloat16* __restrict__ aLo, int lda,
    const __nv_bfloat16* __restrict__ btHi, const __nv_bfloat16* __restrict__ btLo,
    const float* __restrict__ bias, float* __restrict__ C,
    __nv_bfloat16* __restrict__ cH, __nv_bfloat16* __restrict__ cL,
    int K, int ldc)
{
    extern __shared__ __align__(16) char dsm[];
    uint32_t sbase = smem_u32(dsm);

    int tid = threadIdx.x;
    int wid = tid >> 5, lane = tid & 31;
    int n0 = blockIdx.x * 128;
    int row0 = blockIdx.y * 128;
    int wm = (wid & 1) * 64;
    int wn = (wid >> 1) * 32;
    int lr = lane >> 2;
    int lc = (lane & 3) * 2;

    int a_row_off = (lane & 15);
    int a_col_off = (lane >> 4) * 8;
    int b_row_off = (lane & 7) + (lane >> 4) * 8;
    int b_col_off = ((lane >> 3) & 1) * 8;

    float acc[4][4][4];
#pragma unroll
    for (int mt = 0; mt < 4; mt++)
#pragma unroll
        for (int nt = 0; nt < 4; nt++)
#pragma unroll
            for (int e = 0; e < 4; e++) acc[mt][nt][e] = 0.f;

    int nch = K >> 5;
    bg_stage(sbase, 0, 0, tid, row0, n0, aHi, aLo, lda, btHi, btLo, K);
    asm volatile("cp.async.commit_group;");

    for (int c = 0; c < nch; c++) {
        if (c + 1 < nch) {
            bg_stage(sbase, (c + 1) & 1, c + 1, tid, row0, n0, aHi, aLo, lda, btHi, btLo, K);
            asm volatile("cp.async.commit_group;");
            asm volatile("cp.async.wait_group 1;");
        } else {
            asm volatile("cp.async.wait_group 0;");
        }
        __syncthreads();

        int s = c & 1;
        uint32_t pAh = sbase + (uint32_t)(s * STAGE_EL) * 2;
        uint32_t pAl = pAh + ST_EL * 2;
        uint32_t pBh = pAh + 2 * ST_EL * 2;
        uint32_t pBl = pAh + 3 * ST_EL * 2;

#pragma unroll
        for (int kt = 0; kt < 32; kt += 16) {
            uint32_t bh[4][2], bl[4][2];
#pragma unroll
            for (int np = 0; np < 2; np++) {
                uint32_t off = (uint32_t)((wn + np * 16 + b_row_off) * 40 + kt + b_col_off) * 2;
                uint32_t d[4];
                ldm4(d, pBh + off);
                bh[np * 2][0] = d[0]; bh[np * 2][1] = d[1];
                bh[np * 2 + 1][0] = d[2]; bh[np * 2 + 1][1] = d[3];
                ldm4(d, pBl + off);
                bl[np * 2][0] = d[0]; bl[np * 2][1] = d[1];
                bl[np * 2 + 1][0] = d[2]; bl[np * 2 + 1][1] = d[3];
            }
#pragma unroll
            for (int mt = 0; mt < 4; mt++) {
                uint32_t off = (uint32_t)((wm + mt * 16 + a_row_off) * 40 + kt + a_col_off) * 2;
                uint32_t ah[4], al[4];
                ldm4(ah, pAh + off);
                ldm4(al, pAl + off);
#pragma unroll
                for (int nt = 0; nt < 4; nt++) {
                    mma16816(acc[mt][nt], ah, bh[nt]);
                    mma16816(acc[mt][nt], ah, bl[nt]);
                    mma16816(acc[mt][nt], al, bh[nt]);
                }
            }
        }
        __syncthreads();
    }

    // ---- epilogue ----
#pragma unroll
    for (int mt = 0; mt < 4; mt++) {
        int row = row0 + wm + mt * 16 + lr;
#pragma unroll
        for (int nt = 0; nt < 4; nt++) {
            int col = n0 + wn + nt * 8 + lc;
            float b0 = bias[col], b1 = bias[col + 1];
            float v00 = apply_act<ACT>(acc[mt][nt][0] + b0);
            float v01 = apply_act<ACT>(acc[mt][nt][1] + b1);
            float v10 = apply_act<ACT>(acc[mt][nt][2] + b0);
            float v11 = apply_act<ACT>(acc[mt][nt][3] + b1);
            if (OUT16) {
                __nv_bfloat16 h0, l0, h1, l1;
                split2(v00, h0, l0); split2(v01, h1, l1);
                *(uint32_t*)&cH[(size_t)row * ldc + col] = pack_bf2(h0, h1);
                *(uint32_t*)&cL[(size_t)row * ldc + col] = pack_bf2(l0, l1);
                split2(v10, h0, l0); split2(v11, h1, l1);
                *(uint32_t*)&cH[(size_t)(row + 8) * ldc + col] = pack_bf2(h0, h1);
                *(uint32_t*)&cL[(size_t)(row + 8) * ldc + col] = pack_bf2(l0, l1);
            } else {
                *(float2*)(C + (size_t)row * ldc + col) = make_float2(v00, v01);
                *(float2*)(C + (size_t)(row + 8) * ldc + col) = make_float2(v10, v11);
            }
        }
    }
}

// ---------------- fp32 SGEMM (bucket-exact path) ----------------
template <int ACT>
__global__ __launch_bounds__(256, 2) void sgemm_kernel(
    const float* __restrict__ A, const float* __restrict__ B,
    const float* __restrict__ bias, float* __restrict__ C,
    int M, int N, int K, int ldb, int ldc)
{
    __shared__ __align__(16) float As[16][132];
    __shared__ __align__(16) float Bs[16][128];
    int tid = threadIdx.x;
    int col0 = blockIdx.x * 128;
    int row0 = blockIdx.y * 128;
    int ty = tid >> 4, tx = tid & 15;

    float acc[8][8];
#pragma unroll
    for (int i = 0; i < 8; i++)
#pragma unroll
        for (int j = 0; j < 8; j++) acc[i][j] = 0.f;

    const float* Ablk = A + (size_t)row0 * K;
    const float* Bblk = B + col0;

    for (int k0 = 0; k0 < K; k0 += 16) {
#pragma unroll
        for (int t = 0; t < 2; t++) {
            int la = tid + t * 256;
            int ar = la >> 2, ac = (la & 3) << 2;
            float4 av = *(const float4*)(Ablk + (size_t)ar * K + k0 + ac);
            As[ac + 0][ar] = av.x;
            As[ac + 1][ar] = av.y;
            As[ac + 2][ar] = av.z;
            As[ac + 3][ar] = av.w;
            int br = la >> 5, bc = (la & 31) << 2;
            *(float4*)&Bs[br][bc] = *(const float4*)(Bblk + (size_t)(k0 + br) * ldb + bc);
        }
        __syncthreads();
#pragma unroll
        for (int kk = 0; kk < 16; kk++) {
            float ra[8], rb[8];
            *(float4*)(ra) = *(const float4*)&As[kk][ty * 8];
            *(float4*)(ra + 4) = *(const float4*)&As[kk][ty * 8 + 4];
            *(float4*)(rb) = *(const float4*)&Bs[kk][tx * 8];
            *(float4*)(rb + 4) = *(const float4*)&Bs[kk][tx * 8 + 4];
#pragma unroll
            for (int i = 0; i < 8; i++)
#pragma unroll
                for (int j = 0; j < 8; j++) acc[i][j] += ra[i] * rb[j];
        }
        __syncthreads();
    }

#pragma unroll
    for (int i = 0; i < 8; i++) {
        size_t r = (size_t)row0 + ty * 8 + i;
#pragma unroll
        for (int j = 0; j < 8; j += 4) {
            int c = col0 + tx * 8 + j;
            float4 o;
            o.x = apply_act<ACT>(acc[i][j + 0] + bias[c + 0]);
            o.y = apply_act<ACT>(acc[i][j + 1] + bias[c + 1]);
            o.z = apply_act<ACT>(acc[i][j + 2] + bias[c + 2]);
            o.w = apply_act<ACT>(acc[i][j + 3] + bias[c + 3]);
            *(float4*)(C + r * ldc + c) = o;
        }
    }
}

// ---------------- time_elapsic helpers (optionally emit bf16 planes) ----------------
__global__ void build_h_kernel(const float* __restrict__ x,
                               const float* __restrict__ premix,
                               float* __restrict__ out,
                               __nv_bfloat16* __restrict__ oH,
                               __nv_bfloat16* __restrict__ oL)
{
    size_t i4 = (size_t)blockIdx.x * blockDim.x + threadIdx.x;
    size_t base = i4 * 4;
    int d = (int)(base & (Dc - 1));
    int row = (int)(base >> 10);
    int s = row & (Sc - 1);
    float4 xv = *(const float4*)(x + base);
    float4 pv = (s > 0) ? *(const float4*)(x + base - Dc) : make_float4(0.f, 0.f, 0.f, 0.f);
    float4 pm = *(const float4*)(premix + d);
    float4 o;
    o.x = xv.x + (pv.x - xv.x) * pm.x;
    o.y = xv.y + (pv.y - xv.y) * pm.y;
    o.z = xv.z + (pv.z - xv.z) * pm.z;
    o.w = xv.w + (pv.w - xv.w) * pm.w;
    *(float4*)(out + base) = o;
    if (oH) {
        __nv_bfloat16 h0, l0, h1, l1, h2, l2, h3, l3;
        split2(o.x, h0, l0); split2(o.y, h1, l1);
        split2(o.z, h2, l2); split2(o.w, h3, l3);
        *(uint2*)&oH[base] = make_uint2(pack_bf2(h0, h1), pack_bf2(h2, h3));
        *(uint2*)&oL[base] = make_uint2(pack_bf2(l0, l1), pack_bf2(l2, l3));
    }
}

__global__ void combine_kernel(const float* __restrict__ x,
                               const float* __restrict__ gate,
                               float* __restrict__ out,
                               __nv_bfloat16* __restrict__ oH,
                               __nv_bfloat16* __restrict__ oL)
{
    size_t i4 = (size_t)blockIdx.x * blockDim.x + threadIdx.x;
    size_t base = i4 * 4;
    int row = (int)(base >> 10);
    int s = row & (Sc - 1);
    float4 xv = *(const float4*)(x + base);
    float4 pv = (s > 0) ? *(const float4*)(x + base - Dc) : make_float4(0.f, 0.f, 0.f, 0.f);
    float4 gv = *(const float4*)(gate + base);
    float4 o;
    o.x = xv.x + (pv.x - xv.x) * gv.x;
    o.y = xv.y + (pv.y - xv.y) * gv.y;
    o.z = xv.z + (pv.z - xv.z) * gv.z;
    o.w = xv.w + (pv.w - xv.w) * gv.w;
    *(float4*)(out + base) = o;
    if (oH) {
        __nv_bfloat16 h0, l0, h1, l1, h2, l2, h3, l3;
        split2(o.x, h0, l0); split2(o.y, h1, l1);
        split2(o.z, h2, l2); split2(o.w, h3, l3);
        *(uint2*)&oH[base] = make_uint2(pack_bf2(h0, h1), pack_bf2(h2, h3));
        *(uint2*)&oL[base] = make_uint2(pack_bf2(l0, l1), pack_bf2(l2, l3));
    }
}

// ---------------- LSH hashing ----------------
__global__ void hash_kernel(const float* __restrict__ qkv,
                            const float* __restrict__ rot,
                            int* __restrict__ buckets)
{
    int bh = blockIdx.y;
    int b = bh >> 4, h = bh & 15;
    int s = blockIdx.x * 128 + threadIdx.x;
    __shared__ float rotS[Dhc * 32];
    for (int i = threadIdx.x; i < Dhc * 32; i += 128) rotS[i] = rot[h * (Dhc * 32) + i];
    __syncthreads();
    const float* kp = qkv + ((size_t)(b * Sc + s) * QKVW) + (Hc + h) * Dhc;
    float r[32];
#pragma unroll
    for (int n = 0; n < 32; n++) r[n] = 0.f;
    for (int d = 0; d < Dhc; d++) {
        float kd = kp[d];
#pragma unroll
        for (int n = 0; n < 32; n++) r[n] += kd * rotS[d * 32 + n];
    }
    float best = r[0];
    int bi = 0;
#pragma unroll
    for (int n = 1; n < 32; n++)
        if (r[n] > best) { best = r[n]; bi = n; }
#pragma unroll
    for (int n = 0; n < 32; n++)
        if (-r[n] > best) { best = -r[n]; bi = 32 + n; }
    buckets[(size_t)bh * Sc + s] = bi;
}

// ---------------- stable counting sort per (b,h) row ----------------
__global__ void sort_kernel(const int* __restrict__ buckets,
                            int* __restrict__ idx, int* __restrict__ bsort)
{
    int bh = blockIdx.x;
    int t = threadIdx.x;
    __shared__ int sb[Sc];
    __shared__ int cnt[64][64];
    __shared__ int base[64];
    const int* row = buckets + (size_t)bh * Sc;
    for (int i = t; i < Sc; i += 64) sb[i] = row[i];
    for (int v = 0; v < 64; v++) cnt[t][v] = 0;
    __syncthreads();
    for (int i = t * 64; i < t * 64 + 64; i++) cnt[t][sb[i]]++;
    __syncthreads();
    {
        int run = 0;
        for (int seg = 0; seg < 64; seg++) {
            int c = cnt[seg][t];
            cnt[seg][t] = run;
            run += c;
        }
        base[t] = run;
    }
    __syncthreads();
    if (t == 0) {
        int acc = 0;
        for (int v = 0; v < 64; v++) { int c = base[v]; base[v] = acc; acc += c; }
    }
    __syncthreads();
    int* idxrow = idx + (size_t)bh * Sc;
    int* bsrow = bsort + (size_t)bh * Sc;
    for (int i = t * 64; i < t * 64 + 64; i++) {
        int v = sb[i];
        int p = base[v] + cnt[t][v]++;
        idxrow[p] = i;
        bsrow[p] = v;
    }
}

// ---------------- chunked bucket-masked attention (writes bf16 hi/lo planes) ----------------
__global__ __launch_bounds__(128) void attn_kernel(
    const float* __restrict__ qkv, const int* __restrict__ idx,
    const int* __restrict__ bsort,
    __nv_bfloat16* __restrict__ yH, __nv_bfloat16* __restrict__ yL)
{
    int n = blockIdx.x;
    int bh = blockIdx.y;
    int b = bh >> 4, h = bh & 15;
    int tid = threadIdx.x;
    const int* idxrow = idx + (size_t)bh * Sc;
    const int* bsrow = bsort + (size_t)bh * Sc;

    int pq = n * CHUNKc + tid;
    int orig_q = idxrow[pq];
    int bq = bsrow[pq];
    const float* qptr = qkv + ((size_t)(b * Sc + orig_q) * QKVW) + h * Dhc;
    float4 qreg[16];
#pragma unroll
    for (int f = 0; f < 16; f++) qreg[f] = *(const float4*)(qptr + f * 4);

    float4 acc[16];
#pragma unroll
    for (int f = 0; f < 16; f++) acc[f] = make_float4(0.f, 0.f, 0.f, 0.f);
    float m = -1e30f, l = 0.f;

    __shared__ float4 KS[64 * 16];
    __shared__ float4 VS[64 * 16];
    __shared__ int BK[64];

    for (int tile = 0; tile < 4; tile++) {
        int t0 = tile * 64;
        for (int w = tid; w < 64 * 16; w += 128) {
            int slot = w >> 4, f = w & 15;
            int kslot = t0 + slot;
            int spos;
            bool ok;
            if (kslot < CHUNKc) { ok = (n > 0); spos = (n - 1) * CHUNKc + kslot; }
            else                { ok = true;    spos = n * CHUNKc + (kslot - CHUNKc); }
            if (ok) {
                int og = idxrow[spos];
                const float* kp = qkv + ((size_t)(b * Sc + og) * QKVW) + (Hc + h) * Dhc;
                KS[slot * 16 + f] = *(const float4*)(kp + f * 4);
                VS[slot * 16 + f] = *(const float4*)(kp + Hc * Dhc + f * 4);
                if (f == 0) BK[slot] = bsrow[spos];
            } else if (f == 0) {
                BK[slot] = -1;
            }
        }
        __syncthreads();
        for (int s = 0; s < 64; s++) {
            if (BK[s] != bq) continue;
            const float4* kp4 = &KS[s * 16];
            float dot = 0.f;
#pragma unroll
            for (int f = 0; f < 16; f++) {
                float4 kv = kp4[f];
                dot += qreg[f].x * kv.x + qreg[f].y * kv.y + qreg[f].z * kv.z + qreg[f].w * kv.w;
            }
            dot *= 0.125f;
            float p;
            if (dot > m) {
                float sc = __expf(m - dot);
                l *= sc;
#pragma unroll
                for (int f = 0; f < 16; f++) {
                    acc[f].x *= sc; acc[f].y *= sc; acc[f].z *= sc; acc[f].w *= sc;
                }
                m = dot;
                p = 1.f;
            } else {
                p = __expf(dot - m);
            }
            l += p;
            const float4* vp4 = &VS[s * 16];
#pragma unroll
            for (int f = 0; f < 16; f++) {
                float4 vv = vp4[f];
                acc[f].x += p * vv.x; acc[f].y += p * vv.y;
                acc[f].z += p * vv.z; acc[f].w += p * vv.w;
            }
        }
        __syncthreads();
    }
    float inv = 1.f / l;
    size_t ybase = ((size_t)(b * Sc + orig_q)) * Dc + h * Dhc;
#pragma unroll
    for (int f = 0; f < 16; f++) {
        float4 o = acc[f];
        o.x *= inv; o.y *= inv; o.z *= inv; o.w *= inv;
        __nv_bfloat16 h0, l0, h1, l1, h2, l2, h3, l3;
        split2(o.x, h0, l0); split2(o.y, h1, l1);
        split2(o.z, h2, l2); split2(o.w, h3, l3);
        *(uint2*)&yH[ybase + f * 4] = make_uint2(pack_bf2(h0, h1), pack_bf2(h2, h3));
        *(uint2*)&yL[ybase + f * 4] = make_uint2(pack_bf2(l0, l1), pack_bf2(l2, l3));
    }
}

// ---------------- LayerNorm(a + b) ----------------
__global__ void ln_add_kernel(const float* __restrict__ a, const float* __restrict__ bsum,
                              const float* __restrict__ g, const float* __restrict__ be,
                              float* __restrict__ out)
{
    int r = blockIdx.x, tid = threadIdx.x;
    size_t base = (size_t)r * Dc + tid * 4;
    float4 av = *(const float4*)(a + base);
    float4 bv = *(const float4*)(bsum + base);
    float4 v = make_float4(av.x + bv.x, av.y + bv.y, av.z + bv.z, av.w + bv.w);
    float s = v.x + v.y + v.z + v.w;
    float s2 = v.x * v.x + v.y * v.y + v.z * v.z + v.w * v.w;
    for (int o = 16; o > 0; o >>= 1) {
        s += __shfl_down_sync(~0u, s, o);
        s2 += __shfl_down_sync(~0u, s2, o);
    }
    __shared__ float ws[8], ws2[8];
    __shared__ float mean_s, rstd_s;
    int w = tid >> 5, ln = tid & 31;
    if (ln == 0) { ws[w] = s; ws2[w] = s2; }
    __syncthreads();
    if (tid == 0) {
        float S = 0.f, S2 = 0.f;
        for (int i = 0; i < 8; i++) { S += ws[i]; S2 += ws2[i]; }
        float mean = S * (1.f / Dc);
        float var = S2 * (1.f / Dc) - mean * mean;
        mean_s = mean;
        rstd_s = rsqrtf(var + 1e-5f);
    }
    __syncthreads();
    float mean = mean_s, rstd = rstd_s;
    float4 gv = *(const float4*)(g + tid * 4);
    float4 bev = *(const float4*)(be + tid * 4);
    float4 o;
    o.x = (v.x - mean) * rstd * gv.x + bev.x;
    o.y = (v.y - mean) * rstd * gv.y + bev.y;
    o.z = (v.z - mean) * rstd * gv.z + bev.z;
    o.w = (v.w - mean) * rstd * gv.w + bev.w;
    *(float4*)(out + base) = o;
}

// ---------------- LayerNorm(x1 + t * emb[ph]) ----------------
__global__ void ln_emb_kernel(const float* __restrict__ x1, const float* __restrict__ tin,
                              const float* __restrict__ emb, const int* __restrict__ ph,
                              const float* __restrict__ g, const float* __restrict__ be,
                              float* __restrict__ out)
{
    int r = blockIdx.x, tid = threadIdx.x;
    size_t base = (size_t)r * Dc + tid * 4;
    const float* er = emb + (size_t)ph[r] * Dc;
    float4 av = *(const float4*)(x1 + base);
    float4 tv = *(const float4*)(tin + base);
    float4 ev = *(const float4*)(er + tid * 4);
    float4 v = make_float4(av.x + tv.x * ev.x, av.y + tv.y * ev.y,
                           av.z + tv.z * ev.z, av.w + tv.w * ev.w);
    float s = v.x + v.y + v.z + v.w;
    float s2 = v.x * v.x + v.y * v.y + v.z * v.z + v.w * v.w;
    for (int o = 16; o > 0; o >>= 1) {
        s += __shfl_down_sync(~0u, s, o);
        s2 += __shfl_down_sync(~0u, s2, o);
    }
    __shared__ float ws[8], ws2[8];
    __shared__ float mean_s, rstd_s;
    int w = tid >> 5, ln = tid & 31;
    if (ln == 0) { ws[w] = s; ws2[w] = s2; }
    __syncthreads();
    if (tid == 0) {
        float S = 0.f, S2 = 0.f;
        for (int i = 0; i < 8; i++) { S += ws[i]; S2 += ws2[i]; }
        float mean = S * (1.f / Dc);
        float var = S2 * (1.f / Dc) - mean * mean;
        mean_s = mean;
        rstd_s = rsqrtf(var + 1e-5f);
    }
    __syncthreads();
    float mean = mean_s, rstd = rstd_s;
    float4 gv = *(const float4*)(g + tid * 4);
    float4 bev = *(const float4*)(be + tid * 4);
    float4 o;
    o.x = (v.x - mean) * rstd * gv.x + bev.x;
    o.y = (v.y - mean) * rstd * gv.y + bev.y;
    o.z = (v.z - mean) * rstd * gv.z + bev.z;
    o.w = (v.w - mean) * rstd * gv.w + bev.w;
    *(float4*)(out + base) = o;
}

// ---------------- launch ----------------
extern "C" void kernel_launch(void* const* d_in, const int* in_sizes, int n_in,
                              void* d_out, int out_size)
{
    const float* x       = (const float*)d_in[0];
    const float* premix1 = (const float*)d_in[1];
    const float* e1w1    = (const float*)d_in[2];
    const float* e1b1    = (const float*)d_in[3];
    const float* e1w2    = (const float*)d_in[4];
    const float* e1b2    = (const float*)d_in[5];
    const float* premix2 = (const float*)d_in[6];
    const float* e2w1    = (const float*)d_in[7];
    const float* e2b1    = (const float*)d_in[8];
    const float* e2w2    = (const float*)d_in[9];
    const float* e2b2    = (const float*)d_in[10];
    const float* wqkv    = (const float*)d_in[11];
    const float* bqkv    = (const float*)d_in[12];
    const float* wo      = (const float*)d_in[13];
    const float* bo      = (const float*)d_in[14];
    const float* rot     = (const float*)d_in[15];
    const float* ln1g    = (const float*)d_in[16];
    const float* ln1b    = (const float*)d_in[17];
    const float* ln2g    = (const float*)d_in[18];
    const float* ln2b    = (const float*)d_in[19];
    const float* emb     = (const float*)d_in[20];
    const float* mw1     = (const float*)d_in[21];
    const float* mb1     = (const float*)d_in[22];
    const float* mw2     = (const float*)d_in[23];
    const float* mb2     = (const float*)d_in[24];
    const int*   ph      = (const int*)d_in[25];
    float* out = (float*)d_out;

    float *pH, *pE, *pG, *pXA, *pQKV, *pT, *pX1;
    int *pBk, *pIdx, *pBs;
    __nv_bfloat16 *aH, *aL, *eH, *eL, *fH, *fL, *wH, *wL;
    cudaGetSymbolAddress((void**)&pH, g_bufH);
    cudaGetSymbolAddress((void**)&pE, g_bufE);
    cudaGetSymbolAddress((void**)&pG, g_bufG);
    cudaGetSymbolAddress((void**)&pXA, g_bufXA);
    cudaGetSymbolAddress((void**)&pQKV, g_bufQKV);
    cudaGetSymbolAddress((void**)&pT, g_bufT);
    cudaGetSymbolAddress((void**)&pX1, g_bufX1);
    cudaGetSymbolAddress((void**)&pBk, g_buckets);
    cudaGetSymbolAddress((void**)&pIdx, g_idx);
    cudaGetSymbolAddress((void**)&pBs, g_bsort);
    cudaGetSymbolAddress((void**)&aH, g_a16h);
    cudaGetSymbolAddress((void**)&aL, g_a16l);
    cudaGetSymbolAddress((void**)&eH, g_e16h);
    cudaGetSymbolAddress((void**)&eL, g_e16l);
    cudaGetSymbolAddress((void**)&fH, g_f16h);
    cudaGetSymbolAddress((void**)&fL, g_f16l);
    cudaGetSymbolAddress((void**)&wH, g_wth);
    cudaGetSymbolAddress((void**)&wL, g_wtl);

    cudaFuncSetAttribute(bgemm2_kernel<ACT_NONE, 0>, cudaFuncAttributeMaxDynamicSharedMemorySize, BG_DSM);
    cudaFuncSetAttribute(bgemm2_kernel<ACT_SILU, 1>, cudaFuncAttributeMaxDynamicSharedMemorySize, BG_DSM);
    cudaFuncSetAttribute(bgemm2_kernel<ACT_SIGMOID, 0>, cudaFuncAttributeMaxDynamicSharedMemorySize, BG_DSM);
    cudaFuncSetAttribute(bgemm2_kernel<ACT_GELU, 1>, cudaFuncAttributeMaxDynamicSharedMemorySize, BG_DSM);

    // ---- side stream + events for graph-fork overlap (host infra, created once;
    //      first call is the eager correctness run, so creation happens outside capture) ----
    static cudaStream_t s_side = nullptr;
    static cudaEvent_t s_ev_fork = nullptr, s_ev_join = nullptr;
    static cudaEvent_t s_ev_fork2 = nullptr, s_ev_join2 = nullptr;
    if (s_side == nullptr) {
        cudaStreamCreateWithFlags(&s_side, cudaStreamNonBlocking);
        cudaEventCreateWithFlags(&s_ev_fork, cudaEventDisableTiming);
        cudaEventCreateWithFlags(&s_ev_join, cudaEventDisableTiming);
        cudaEventCreateWithFlags(&s_ev_fork2, cudaEventDisableTiming);
        cudaEventCreateWithFlags(&s_ev_join2, cudaEventDisableTiming);
    }

    const int ew_blocks = Mrows * Dc / (256 * 4);
    dim3 tsb(32, 8);

    // ---- fork #1: weight transpose/split on side stream, overlapped with elapsic1 ----
    cudaEventRecord(s_ev_fork, 0);
    cudaStreamWaitEvent(s_side, s_ev_fork, 0);
    tsplit_kernel<<<dim3(QKVW / 32, Dc / 32), tsb, 0, s_side>>>(wqkv, wH + OFF_QKV, wL + OFF_QKV, Dc, QKVW);
    tsplit_kernel<<<dim3(Dc / 32, Dc / 32), tsb, 0, s_side>>>(wo, wH + OFF_WO, wL + OFF_WO, Dc, Dc);
    tsplit_kernel<<<dim3(Ec / 32, Dc / 32), tsb, 0, s_side>>>(e2w1, wH + OFF_E2W1, wL + OFF_E2W1, Dc, Ec);
    tsplit_kernel<<<dim3(Dc / 32, Ec / 32), tsb, 0, s_side>>>(e2w2, wH + OFF_E2W2, wL + OFF_E2W2, Ec, Dc);
    tsplit_kernel<<<dim3(Fc / 32, Dc / 32), tsb, 0, s_side>>>(mw1, wH + OFF_MW1, wL + OFF_MW1, Dc, Fc);
    tsplit_kernel<<<dim3(Dc / 32, Fc / 32), tsb, 0, s_side>>>(mw2, wH + OFF_MW2, wL + OFF_MW2, Fc, Dc);
    cudaEventRecord(s_ev_join, s_side);

    // ---- time_elapsic 1 (fp32 exact: feeds the LSH bucket path) [main stream] ----
    build_h_kernel<<<ew_blocks, 256>>>(x, premix1, pH, nullptr, nullptr);
    sgemm_kernel<ACT_SILU><<<dim3(Ec / 128, Mrows / 128), 256>>>(pH, e1w1, e1b1, pE, Mrows, Ec, Dc, Ec, Ec);
    sgemm_kernel<ACT_SIGMOID><<<dim3(Dc / 128, Mrows / 128), 256>>>(pE, e1w2, e1b2, pG, Mrows, Dc, Ec, Dc, Dc);
    combine_kernel<<<ew_blocks, 256>>>(x, pG, pXA, aH, aL);

    // main stream must see split weights before Q/V bgemm
    cudaStreamWaitEvent(0, s_ev_join, 0);

    // ---- fork #2: fp32 K-projection on side stream, overlapped with Q/V bgemms ----
    cudaEventRecord(s_ev_fork2, 0);
    cudaStreamWaitEvent(s_side, s_ev_fork2, 0);
    sgemm_kernel<ACT_NONE><<<dim3(8, Mrows / 128), 256, 0, s_side>>>(pXA, wqkv + 1024, bqkv + 1024, pQKV + 1024, Mrows, 1024, Dc, QKVW, QKVW);
    cudaEventRecord(s_ev_join2, s_side);

    bgemm2_kernel<ACT_NONE, 0><<<dim3(8, 128), 256, BG_DSM>>>(aH, aL, Dc, wH + OFF_QKV, wL + OFF_QKV, bqkv, pQKV, nullptr, nullptr, Dc, QKVW);
    bgemm2_kernel<ACT_NONE, 0><<<dim3(8, 128), 256, BG_DSM>>>(aH, aL, Dc, wH + OFF_QKV + (size_t)2048 * Dc, wL + OFF_QKV + (size_t)2048 * Dc, bqkv + 2048, pQKV + 2048, nullptr, nullptr, Dc, QKVW);

    // join: hash needs K columns written by the side stream
    cudaStreamWaitEvent(0, s_ev_join2, 0);

    hash_kernel<<<dim3(Sc / 128, Bc * Hc), 128>>>(pQKV, rot, pBk);
    sort_kernel<<<Bc * Hc, 64>>>(pBk, pIdx, pBs);
    attn_kernel<<<dim3(NCHUNK, Bc * Hc), 128>>>(pQKV, pIdx, pBs, aH, aL);  // ATT planes overwrite XA planes
    bgemm2_kernel<ACT_NONE, 0><<<dim3(8, 128), 256, BG_DSM>>>(aH, aL, Dc, wH + OFF_WO, wL + OFF_WO, bo, pT, nullptr, nullptr, Dc, Dc);
    ln_add_kernel<<<Mrows, 256>>>(x, pT, ln1g, ln1b, pX1);

    // ---- time_elapsic 2 (tensor) ----
    build_h_kernel<<<ew_blocks, 256>>>(pX1, premix2, pH, aH, aL);
    bgemm2_kernel<ACT_SILU, 1><<<dim3(2, 128), 256, BG_DSM>>>(aH, aL, Dc, wH + OFF_E2W1, wL + OFF_E2W1, e2b1, nullptr, eH, eL, Dc, Ec);
    bgemm2_kernel<ACT_SIGMOID, 0><<<dim3(8, 128), 256, BG_DSM>>>(eH, eL, Ec, wH + OFF_E2W2, wL + OFF_E2W2, e2b2, pG, nullptr, nullptr, Ec, Dc);
    combine_kernel<<<ew_blocks, 256>>>(pX1, pG, pXA, aH, aL);

    // ---- MLP + deepembed + LN2 (tensor; F kept bf16-planes only) ----
    bgemm2_kernel<ACT_GELU, 1><<<dim3(32, 128), 256, BG_DSM>>>(aH, aL, Dc, wH + OFF_MW1, wL + OFF_MW1, mb1, nullptr, fH, fL, Dc, Fc);
    bgemm2_kernel<ACT_NONE, 0><<<dim3(8, 128), 256, BG_DSM>>>(fH, fL, Fc, wH + OFF_MW2, wL + OFF_MW2, mb2, pT, nullptr, nullptr, Fc, Dc);
    ln_emb_kernel<<<Mrows, 256>>>(pX1, pT, emb, ph, ln2g, ln2b, out);
}

// round 11
// speedup vs baseline: 2.0648x; 1.0059x over previous
#include <cuda_runtime.h>
#include <cuda_bf16.h>
#include <math.h>
#include <stdint.h>

// ---------------- problem constants ----------------
#define Bc 4
#define Sc 4096
#define Dc 1024
#define Hc 16
#define Dhc 64
#define Ec 256
#define Fc 4096
#define CHUNKc 128
#define Mrows (Bc * Sc)          // 16384
#define QKVW (3 * Hc * Dhc)      // 3072
#define NCHUNK (Sc / CHUNKc)     // 32

// weight-plane offsets (elements) inside g_wt
#define OFF_QKV  0
#define OFF_WO   3145728
#define OFF_E2W1 4194304
#define OFF_E2W2 4456448
#define OFF_MW1  4718592
#define OFF_MW2  8912896
#define WT_TOT   13107200

// ---------------- scratch (device globals; no allocations allowed) ----------------
__device__ float g_bufH[(size_t)Mrows * Dc];
__device__ float g_bufE[(size_t)Mrows * Ec];
__device__ float g_bufG[(size_t)Mrows * Dc];
__device__ float g_bufXA[(size_t)Mrows * Dc];
__device__ float g_bufQKV[(size_t)Mrows * QKVW];
__device__ float g_bufT[(size_t)Mrows * Dc];
__device__ float g_bufX1[(size_t)Mrows * Dc];
__device__ int g_buckets[Bc * Hc * Sc];
__device__ int g_idx[Bc * Hc * Sc];
__device__ int g_bsort[Bc * Hc * Sc];
// bf16 hi/lo planes
__device__ __nv_bfloat16 g_a16h[(size_t)Mrows * Dc];
__device__ __nv_bfloat16 g_a16l[(size_t)Mrows * Dc];
__device__ __nv_bfloat16 g_e16h[(size_t)Mrows * Ec];
__device__ __nv_bfloat16 g_e16l[(size_t)Mrows * Ec];
__device__ __nv_bfloat16 g_f16h[(size_t)Mrows * Fc];
__device__ __nv_bfloat16 g_f16l[(size_t)Mrows * Fc];
__device__ __nv_bfloat16 g_wth[WT_TOT];
__device__ __nv_bfloat16 g_wtl[WT_TOT];

// ---------------- activations ----------------
enum { ACT_NONE = 0, ACT_SILU = 1, ACT_GELU = 2, ACT_SIGMOID = 3 };

template <int ACT>
__device__ __forceinline__ float apply_act(float x) {
    if (ACT == ACT_SILU) return x / (1.f + __expf(-x));
    if (ACT == ACT_GELU) {
        float t = tanhf(0.7978845608028654f * (x + 0.044715f * x * x * x));
        return 0.5f * x * (1.f + t);
    }
    if (ACT == ACT_SIGMOID) return 1.f / (1.f + __expf(-x));
    return x;
}

__device__ __forceinline__ uint32_t smem_u32(const void* p) {
    uint32_t a;
    asm("{ .reg .u64 t; cvta.to.shared.u64 t, %1; cvt.u32.u64 %0, t; }" : "=r"(a) : "l"(p));
    return a;
}
__device__ __forceinline__ uint32_t pack_bf2(__nv_bfloat16 a, __nv_bfloat16 b) {
    __nv_bfloat162 t; t.x = a; t.y = b;
    return *(uint32_t*)&t;
}
__device__ __forceinline__ void split2(float v, __nv_bfloat16& h, __nv_bfloat16& l) {
    h = __float2bfloat16(v);
    l = __float2bfloat16(v - __bfloat162float(h));
}
__device__ __forceinline__ void cpa16(uint32_t dst, const void* src) {
    asm volatile("cp.async.cg.shared.global [%0], [%1], 16;" :: "r"(dst), "l"(src));
}
__device__ __forceinline__ void mma16816(float* c, const uint32_t* a, const uint32_t* b) {
    asm volatile(
        "mma.sync.aligned.m16n8k16.row.col.f32.bf16.bf16.f32 "
        "{%0,%1,%2,%3}, {%4,%5,%6,%7}, {%8,%9}, {%0,%1,%2,%3};"
        : "+f"(c[0]), "+f"(c[1]), "+f"(c[2]), "+f"(c[3])
        : "r"(a[0]), "r"(a[1]), "r"(a[2]), "r"(a[3]), "r"(b[0]), "r"(b[1]));
}
__device__ __forceinline__ void ldm4(uint32_t* d, uint32_t addr) {
    asm volatile("ldmatrix.sync.aligned.m8n8.x4.shared.b16 {%0,%1,%2,%3}, [%4];"
                 : "=r"(d[0]), "=r"(d[1]), "=r"(d[2]), "=r"(d[3]) : "r"(addr));
}

// ---------------- weight transpose+split: W[K,N] -> Wt hi/lo [N,K] ----------------
__global__ void tsplit_kernel(const float* __restrict__ W,
                              __nv_bfloat16* __restrict__ tH, __nv_bfloat16* __restrict__ tL,
                              int K, int N)
{
    __shared__ float t[32][33];
    int n0 = blockIdx.x * 32, k0 = blockIdx.y * 32;
    int tx = threadIdx.x, ty = threadIdx.y;
#pragma unroll
    for (int i = 0; i < 4; i++) {
        int k = k0 + ty + i * 8;
        t[ty + i * 8][tx] = W[(size_t)k * N + n0 + tx];
    }
    __syncthreads();
#pragma unroll
    for (int i = 0; i < 4; i++) {
        int n = n0 + ty + i * 8;
        float v = t[tx][ty + i * 8];
        __nv_bfloat16 h, l;
        split2(v, h, l);
        tH[(size_t)n * K + k0 + tx] = h;
        tL[(size_t)n * K + k0 + tx] = l;
    }
}

// ============ bf16x3 HMMA GEMM: cp.async double buffering + ldmatrix frags ============
#define ST_EL 5120      // elems per plane per stage (128*40)
#define STAGE_EL 20480  // 4 planes
#define BG_DSM (2 * STAGE_EL * 2)  // bytes = 81920

__device__ __forceinline__ void bg_stage(
    uint32_t sbase, int s, int c, int tid, int row0, int n0,
    const __nv_bfloat16* __restrict__ aHi, const __nv_bfloat16* __restrict__ aLo, int lda,
    const __nv_bfloat16* __restrict__ btHi, const __nv_bfloat16* __restrict__ btLo, int K)
{
    int k0 = c * 32;
#pragma unroll
    for (int j = 0; j < 2; j++) {
        int c2 = tid + j * 256;
        int row = c2 >> 2, seg = (c2 & 3) << 3;
        uint32_t off = sbase + (uint32_t)(s * STAGE_EL + row * 40 + seg) * 2;
        size_t ga = (size_t)(row0 + row) * lda + k0 + seg;
        size_t gb = (size_t)(n0 + row) * K + k0 + seg;
        cpa16(off,                 aHi + ga);
        cpa16(off + ST_EL * 2,     aLo + ga);
        cpa16(off + 2 * ST_EL * 2, btHi + gb);
        cpa16(off + 3 * ST_EL * 2, btLo + gb);
    }
}

template <int ACT, int OUT16>
__global__ __launch_bounds__(256, 2) void bgemm2_kernel(
    const __nv_bfloat16* __restrict__ aHi, const __nv_bfloat16* __restrict__ aLo, int lda,
    const __nv_bfloat16* __restrict__ btHi, const __nv_bfloat16* __restrict__ btLo,
    const float* __restrict__ bias, float* __restrict__ C,
    __nv_bfloat16* __restrict__ cH, __nv_bfloat16* __restrict__ cL,
    int K, int ldc)
{
    extern __shared__ __align__(16) char dsm[];
    uint32_t sbase = smem_u32(dsm);

    int tid = threadIdx.x;
    int wid = tid >> 5, lane = tid & 31;
    int n0 = blockIdx.x * 128;
    int row0 = blockIdx.y * 128;
    int wm = (wid & 1) * 64;
    int wn = (wid >> 1) * 32;
    int lr = lane >> 2;
    int lc = (lane & 3) * 2;

    int a_row_off = (lane & 15);
    int a_col_off = (lane >> 4) * 8;
    int b_row_off = (lane & 7) + (lane >> 4) * 8;
    int b_col_off = ((lane >> 3) & 1) * 8;

    float acc[4][4][4];
#pragma unroll
    for (int mt = 0; mt < 4; mt++)
#pragma unroll
        for (int nt = 0; nt < 4; nt++)
#pragma unroll
            for (int e = 0; e < 4; e++) acc[mt][nt][e] = 0.f;

    int nch = K >> 5;
    bg_stage(sbase, 0, 0, tid, row0, n0, aHi, aLo, lda, btHi, btLo, K);
    asm volatile("cp.async.commit_group;");

    for (int c = 0; c < nch; c++) {
        if (c + 1 < nch) {
            bg_stage(sbase, (c + 1) & 1, c + 1, tid, row0, n0, aHi, aLo, lda, btHi, btLo, K);
            asm volatile("cp.async.commit_group;");
            asm volatile("cp.async.wait_group 1;");
        } else {
            asm volatile("cp.async.wait_group 0;");
        }
        __syncthreads();

        int s = c & 1;
        uint32_t pAh = sbase + (uint32_t)(s * STAGE_EL) * 2;
        uint32_t pAl = pAh + ST_EL * 2;
        uint32_t pBh = pAh + 2 * ST_EL * 2;
        uint32_t pBl = pAh + 3 * ST_EL * 2;

#pragma unroll
        for (int kt = 0; kt < 32; kt += 16) {
            uint32_t bh[4][2], bl[4][2];
#pragma unroll
            for (int np = 0; np < 2; np++) {
                uint32_t off = (uint32_t)((wn + np * 16 + b_row_off) * 40 + kt + b_col_off) * 2;
                uint32_t d[4];
                ldm4(d, pBh + off);
                bh[np * 2][0] = d[0]; bh[np * 2][1] = d[1];
                bh[np * 2 + 1][0] = d[2]; bh[np * 2 + 1][1] = d[3];
                ldm4(d, pBl + off);
                bl[np * 2][0] = d[0]; bl[np * 2][1] = d[1];
                bl[np * 2 + 1][0] = d[2]; bl[np * 2 + 1][1] = d[3];
            }
#pragma unroll
            for (int mt = 0; mt < 4; mt++) {
                uint32_t off = (uint32_t)((wm + mt * 16 + a_row_off) * 40 + kt + a_col_off) * 2;
                uint32_t ah[4], al[4];
                ldm4(ah, pAh + off);
                ldm4(al, pAl + off);
#pragma unroll
                for (int nt = 0; nt < 4; nt++) {
                    mma16816(acc[mt][nt], ah, bh[nt]);
                    mma16816(acc[mt][nt], ah, bl[nt]);
                    mma16816(acc[mt][nt], al, bh[nt]);
                }
            }
        }
        __syncthreads();
    }

    // ---- epilogue ----
#pragma unroll
    for (int mt = 0; mt < 4; mt++) {
        int row = row0 + wm + mt * 16 + lr;
#pragma unroll
        for (int nt = 0; nt < 4; nt++) {
            int col = n0 + wn + nt * 8 + lc;
            float b0 = bias[col], b1 = bias[col + 1];
            float v00 = apply_act<ACT>(acc[mt][nt][0] + b0);
            float v01 = apply_act<ACT>(acc[mt][nt][1] + b1);
            float v10 = apply_act<ACT>(acc[mt][nt][2] + b0);
            float v11 = apply_act<ACT>(acc[mt][nt][3] + b1);
            if (OUT16) {
                __nv_bfloat16 h0, l0, h1, l1;
                split2(v00, h0, l0); split2(v01, h1, l1);
                *(uint32_t*)&cH[(size_t)row * ldc + col] = pack_bf2(h0, h1);
                *(uint32_t*)&cL[(size_t)row * ldc + col] = pack_bf2(l0, l1);
                split2(v10, h0, l0); split2(v11, h1, l1);
                *(uint32_t*)&cH[(size_t)(row + 8) * ldc + col] = pack_bf2(h0, h1);
                *(uint32_t*)&cL[(size_t)(row + 8) * ldc + col] = pack_bf2(l0, l1);
            } else {
                *(float2*)(C + (size_t)row * ldc + col) = make_float2(v00, v01);
                *(float2*)(C + (size_t)(row + 8) * ldc + col) = make_float2(v10, v11);
            }
        }
    }
}

// ---------------- fp32 SGEMM v2: cp.async double buffered (bucket-exact path) ----------------
// A untransposed [128][20] padded, B [16][128]. Same FFMA order as before -> bit-identical.
template <int ACT>
__global__ __launch_bounds__(256, 2) void sgemm_kernel(
    const float* __restrict__ A, const float* __restrict__ B,
    const float* __restrict__ bias, float* __restrict__ C,
    int M, int N, int K, int ldb, int ldc)
{
    __shared__ __align__(16) float As[2][128][20];
    __shared__ __align__(16) float Bs[2][16][128];
    int tid = threadIdx.x;
    int col0 = blockIdx.x * 128;
    int row0 = blockIdx.y * 128;
    int ty = tid >> 4, tx = tid & 15;

    float acc[8][8];
#pragma unroll
    for (int i = 0; i < 8; i++)
#pragma unroll
        for (int j = 0; j < 8; j++) acc[i][j] = 0.f;

    const float* Ablk = A + (size_t)row0 * K;
    const float* Bblk = B + col0;
    int nch = K >> 4;

    // stage helper inlined: chunk c into slot s
    auto stage = [&](int s, int c) {
        int k0 = c << 4;
#pragma unroll
        for (int j = 0; j < 2; j++) {
            int idx = tid + j * 256;
            int ar = idx >> 2, ac4 = (idx & 3) << 2;
            cpa16(smem_u32(&As[s][ar][ac4]), Ablk + (size_t)ar * K + k0 + ac4);
            int br = idx >> 5, bc = (idx & 31) << 2;
            cpa16(smem_u32(&Bs[s][br][bc]), Bblk + (size_t)(k0 + br) * ldb + bc);
        }
    };

    stage(0, 0);
    asm volatile("cp.async.commit_group;");

    for (int c = 0; c < nch; c++) {
        if (c + 1 < nch) {
            stage((c + 1) & 1, c + 1);
            asm volatile("cp.async.commit_group;");
            asm volatile("cp.async.wait_group 1;");
        } else {
            asm volatile("cp.async.wait_group 0;");
        }
        __syncthreads();
        int s = c & 1;
#pragma unroll
        for (int kk = 0; kk < 16; kk++) {
            float ra[8], rb[8];
#pragma unroll
            for (int i = 0; i < 8; i++) ra[i] = As[s][ty * 8 + i][kk];
            *(float4*)(rb) = *(const float4*)&Bs[s][kk][tx * 8];
            *(float4*)(rb + 4) = *(const float4*)&Bs[s][kk][tx * 8 + 4];
#pragma unroll
            for (int i = 0; i < 8; i++)
#pragma unroll
                for (int j = 0; j < 8; j++) acc[i][j] += ra[i] * rb[j];
        }
        __syncthreads();
    }

#pragma unroll
    for (int i = 0; i < 8; i++) {
        size_t r = (size_t)row0 + ty * 8 + i;
#pragma unroll
        for (int j = 0; j < 8; j += 4) {
            int c = col0 + tx * 8 + j;
            float4 o;
            o.x = apply_act<ACT>(acc[i][j + 0] + bias[c + 0]);
            o.y = apply_act<ACT>(acc[i][j + 1] + bias[c + 1]);
            o.z = apply_act<ACT>(acc[i][j + 2] + bias[c + 2]);
            o.w = apply_act<ACT>(acc[i][j + 3] + bias[c + 3]);
            *(float4*)(C + r * ldc + c) = o;
        }
    }
}

// ---------------- time_elapsic helpers (optionally emit bf16 planes) ----------------
__global__ void build_h_kernel(const float* __restrict__ x,
                               const float* __restrict__ premix,
                               float* __restrict__ out,
                               __nv_bfloat16* __restrict__ oH,
                               __nv_bfloat16* __restrict__ oL)
{
    size_t i4 = (size_t)blockIdx.x * blockDim.x + threadIdx.x;
    size_t base = i4 * 4;
    int d = (int)(base & (Dc - 1));
    int row = (int)(base >> 10);
    int s = row & (Sc - 1);
    float4 xv = *(const float4*)(x + base);
    float4 pv = (s > 0) ? *(const float4*)(x + base - Dc) : make_float4(0.f, 0.f, 0.f, 0.f);
    float4 pm = *(const float4*)(premix + d);
    float4 o;
    o.x = xv.x + (pv.x - xv.x) * pm.x;
    o.y = xv.y + (pv.y - xv.y) * pm.y;
    o.z = xv.z + (pv.z - xv.z) * pm.z;
    o.w = xv.w + (pv.w - xv.w) * pm.w;
    *(float4*)(out + base) = o;
    if (oH) {
        __nv_bfloat16 h0, l0, h1, l1, h2, l2, h3, l3;
        split2(o.x, h0, l0); split2(o.y, h1, l1);
        split2(o.z, h2, l2); split2(o.w, h3, l3);
        *(uint2*)&oH[base] = make_uint2(pack_bf2(h0, h1), pack_bf2(h2, h3));
        *(uint2*)&oL[base] = make_uint2(pack_bf2(l0, l1), pack_bf2(l2, l3));
    }
}

__global__ void combine_kernel(const float* __restrict__ x,
                               const float* __restrict__ gate,
                               float* __restrict__ out,
                               __nv_bfloat16* __restrict__ oH,
                               __nv_bfloat16* __restrict__ oL)
{
    size_t i4 = (size_t)blockIdx.x * blockDim.x + threadIdx.x;
    size_t base = i4 * 4;
    int row = (int)(base >> 10);
    int s = row & (Sc - 1);
    float4 xv = *(const float4*)(x + base);
    float4 pv = (s > 0) ? *(const float4*)(x + base - Dc) : make_float4(0.f, 0.f, 0.f, 0.f);
    float4 gv = *(const float4*)(gate + base);
    float4 o;
    o.x = xv.x + (pv.x - xv.x) * gv.x;
    o.y = xv.y + (pv.y - xv.y) * gv.y;
    o.z = xv.z + (pv.z - xv.z) * gv.z;
    o.w = xv.w + (pv.w - xv.w) * gv.w;
    *(float4*)(out + base) = o;
    if (oH) {
        __nv_bfloat16 h0, l0, h1, l1, h2, l2, h3, l3;
        split2(o.x, h0, l0); split2(o.y, h1, l1);
        split2(o.z, h2, l2); split2(o.w, h3, l3);
        *(uint2*)&oH[base] = make_uint2(pack_bf2(h0, h1), pack_bf2(h2, h3));
        *(uint2*)&oL[base] = make_uint2(pack_bf2(l0, l1), pack_bf2(l2, l3));
    }
}

// ---------------- LSH hashing ----------------
__global__ void hash_kernel(const float* __restrict__ qkv,
                            const float* __restrict__ rot,
                            int* __restrict__ buckets)
{
    int bh = blockIdx.y;
    int b = bh >> 4, h = bh & 15;
    int s = blockIdx.x * 128 + threadIdx.x;
    __shared__ float rotS[Dhc * 32];
    for (int i = threadIdx.x; i < Dhc * 32; i += 128) rotS[i] = rot[h * (Dhc * 32) + i];
    __syncthreads();
    const float* kp = qkv + ((size_t)(b * Sc + s) * QKVW) + (Hc + h) * Dhc;
    float r[32];
#pragma unroll
    for (int n = 0; n < 32; n++) r[n] = 0.f;
    for (int d = 0; d < Dhc; d++) {
        float kd = kp[d];
#pragma unroll
        for (int n = 0; n < 32; n++) r[n] += kd * rotS[d * 32 + n];
    }
    float best = r[0];
    int bi = 0;
#pragma unroll
    for (int n = 1; n < 32; n++)
        if (r[n] > best) { best = r[n]; bi = n; }
#pragma unroll
    for (int n = 0; n < 32; n++)
        if (-r[n] > best) { best = -r[n]; bi = 32 + n; }
    buckets[(size_t)bh * Sc + s] = bi;
}

// ---------------- stable counting sort per (b,h) row ----------------
__global__ void sort_kernel(const int* __restrict__ buckets,
                            int* __restrict__ idx, int* __restrict__ bsort)
{
    int bh = blockIdx.x;
    int t = threadIdx.x;
    __shared__ int sb[Sc];
    __shared__ int cnt[64][64];
    __shared__ int base[64];
    const int* row = buckets + (size_t)bh * Sc;
    for (int i = t; i < Sc; i += 64) sb[i] = row[i];
    for (int v = 0; v < 64; v++) cnt[t][v] = 0;
    __syncthreads();
    for (int i = t * 64; i < t * 64 + 64; i++) cnt[t][sb[i]]++;
    __syncthreads();
    {
        int run = 0;
        for (int seg = 0; seg < 64; seg++) {
            int c = cnt[seg][t];
            cnt[seg][t] = run;
            run += c;
        }
        base[t] = run;
    }
    __syncthreads();
    if (t == 0) {
        int acc = 0;
        for (int v = 0; v < 64; v++) { int c = base[v]; base[v] = acc; acc += c; }
    }
    __syncthreads();
    int* idxrow = idx + (size_t)bh * Sc;
    int* bsrow = bsort + (size_t)bh * Sc;
    for (int i = t * 64; i < t * 64 + 64; i++) {
        int v = sb[i];
        int p = base[v] + cnt[t][v]++;
        idxrow[p] = i;
        bsrow[p] = v;
    }
}

// ---------------- chunked bucket-masked attention (writes bf16 hi/lo planes) ----------------
__global__ __launch_bounds__(128) void attn_kernel(
    const float* __restrict__ qkv, const int* __restrict__ idx,
    const int* __restrict__ bsort,
    __nv_bfloat16* __restrict__ yH, __nv_bfloat16* __restrict__ yL)
{
    int n = blockIdx.x;
    int bh = blockIdx.y;
    int b = bh >> 4, h = bh & 15;
    int tid = threadIdx.x;
    const int* idxrow = idx + (size_t)bh * Sc;
    const int* bsrow = bsort + (size_t)bh * Sc;

    int pq = n * CHUNKc + tid;
    int orig_q = idxrow[pq];
    int bq = bsrow[pq];
    const float* qptr = qkv + ((size_t)(b * Sc + orig_q) * QKVW) + h * Dhc;
    float4 qreg[16];
#pragma unroll
    for (int f = 0; f < 16; f++) qreg[f] = *(const float4*)(qptr + f * 4);

    float4 acc[16];
#pragma unroll
    for (int f = 0; f < 16; f++) acc[f] = make_float4(0.f, 0.f, 0.f, 0.f);
    float m = -1e30f, l = 0.f;

    __shared__ float4 KS[64 * 16];
    __shared__ float4 VS[64 * 16];
    __shared__ int BK[64];

    for (int tile = 0; tile < 4; tile++) {
        int t0 = tile * 64;
        for (int w = tid; w < 64 * 16; w += 128) {
            int slot = w >> 4, f = w & 15;
            int kslot = t0 + slot;
            int spos;
            bool ok;
            if (kslot < CHUNKc) { ok = (n > 0); spos = (n - 1) * CHUNKc + kslot; }
            else                { ok = true;    spos = n * CHUNKc + (kslot - CHUNKc); }
            if (ok) {
                int og = idxrow[spos];
                const float* kp = qkv + ((size_t)(b * Sc + og) * QKVW) + (Hc + h) * Dhc;
                KS[slot * 16 + f] = *(const float4*)(kp + f * 4);
                VS[slot * 16 + f] = *(const float4*)(kp + Hc * Dhc + f * 4);
                if (f == 0) BK[slot] = bsrow[spos];
            } else if (f == 0) {
                BK[slot] = -1;
            }
        }
        __syncthreads();
        for (int s = 0; s < 64; s++) {
            if (BK[s] != bq) continue;
            const float4* kp4 = &KS[s * 16];
            float dot = 0.f;
#pragma unroll
            for (int f = 0; f < 16; f++) {
                float4 kv = kp4[f];
                dot += qreg[f].x * kv.x + qreg[f].y * kv.y + qreg[f].z * kv.z + qreg[f].w * kv.w;
            }
            dot *= 0.125f;
            float p;
            if (dot > m) {
                float sc = __expf(m - dot);
                l *= sc;
#pragma unroll
                for (int f = 0; f < 16; f++) {
                    acc[f].x *= sc; acc[f].y *= sc; acc[f].z *= sc; acc[f].w *= sc;
                }
                m = dot;
                p = 1.f;
            } else {
                p = __expf(dot - m);
            }
            l += p;
            const float4* vp4 = &VS[s * 16];
#pragma unroll
            for (int f = 0; f < 16; f++) {
                float4 vv = vp4[f];
                acc[f].x += p * vv.x; acc[f].y += p * vv.y;
                acc[f].z += p * vv.z; acc[f].w += p * vv.w;
            }
        }
        __syncthreads();
    }
    float inv = 1.f / l;
    size_t ybase = ((size_t)(b * Sc + orig_q)) * Dc + h * Dhc;
#pragma unroll
    for (int f = 0; f < 16; f++) {
        float4 o = acc[f];
        o.x *= inv; o.y *= inv; o.z *= inv; o.w *= inv;
        __nv_bfloat16 h0, l0, h1, l1, h2, l2, h3, l3;
        split2(o.x, h0, l0); split2(o.y, h1, l1);
        split2(o.z, h2, l2); split2(o.w, h3, l3);
        *(uint2*)&yH[ybase + f * 4] = make_uint2(pack_bf2(h0, h1), pack_bf2(h2, h3));
        *(uint2*)&yL[ybase + f * 4] = make_uint2(pack_bf2(l0, l1), pack_bf2(l2, l3));
    }
}

// ---------------- LayerNorm(a + b) ----------------
__global__ void ln_add_kernel(const float* __restrict__ a, const float* __restrict__ bsum,
                              const float* __restrict__ g, const float* __restrict__ be,
                              float* __restrict__ out)
{
    int r = blockIdx.x, tid = threadIdx.x;
    size_t base = (size_t)r * Dc + tid * 4;
    float4 av = *(const float4*)(a + base);
    float4 bv = *(const float4*)(bsum + base);
    float4 v = make_float4(av.x + bv.x, av.y + bv.y, av.z + bv.z, av.w + bv.w);
    float s = v.x + v.y + v.z + v.w;
    float s2 = v.x * v.x + v.y * v.y + v.z * v.z + v.w * v.w;
    for (int o = 16; o > 0; o >>= 1) {
        s += __shfl_down_sync(~0u, s, o);
        s2 += __shfl_down_sync(~0u, s2, o);
    }
    __shared__ float ws[8], ws2[8];
    __shared__ float mean_s, rstd_s;
    int w = tid >> 5, ln = tid & 31;
    if (ln == 0) { ws[w] = s; ws2[w] = s2; }
    __syncthreads();
    if (tid == 0) {
        float S = 0.f, S2 = 0.f;
        for (int i = 0; i < 8; i++) { S += ws[i]; S2 += ws2[i]; }
        float mean = S * (1.f / Dc);
        float var = S2 * (1.f / Dc) - mean * mean;
        mean_s = mean;
        rstd_s = rsqrtf(var + 1e-5f);
    }
    __syncthreads();
    float mean = mean_s, rstd = rstd_s;
    float4 gv = *(const float4*)(g + tid * 4);
    float4 bev = *(const float4*)(be + tid * 4);
    float4 o;
    o.x = (v.x - mean) * rstd * gv.x + bev.x;
    o.y = (v.y - mean) * rstd * gv.y + bev.y;
    o.z = (v.z - mean) * rstd * gv.z + bev.z;
    o.w = (v.w - mean) * rstd * gv.w + bev.w;
    *(float4*)(out + base) = o;
}

// ---------------- LayerNorm(x1 + t * emb[ph]) ----------------
__global__ void ln_emb_kernel(const float* __restrict__ x1, const float* __restrict__ tin,
                              const float* __restrict__ emb, const int* __restrict__ ph,
                              const float* __restrict__ g, const float* __restrict__ be,
                              float* __restrict__ out)
{
    int r = blockIdx.x, tid = threadIdx.x;
    size_t base = (size_t)r * Dc + tid * 4;
    const float* er = emb + (size_t)ph[r] * Dc;
    float4 av = *(const float4*)(x1 + base);
    float4 tv = *(const float4*)(tin + base);
    float4 ev = *(const float4*)(er + tid * 4);
    float4 v = make_float4(av.x + tv.x * ev.x, av.y + tv.y * ev.y,
                           av.z + tv.z * ev.z, av.w + tv.w * ev.w);
    float s = v.x + v.y + v.z + v.w;
    float s2 = v.x * v.x + v.y * v.y + v.z * v.z + v.w * v.w;
    for (int o = 16; o > 0; o >>= 1) {
        s += __shfl_down_sync(~0u, s, o);
        s2 += __shfl_down_sync(~0u, s2, o);
    }
    __shared__ float ws[8], ws2[8];
    __shared__ float mean_s, rstd_s;
    int w = tid >> 5, ln = tid & 31;
    if (ln == 0) { ws[w] = s; ws2[w] = s2; }
    __syncthreads();
    if (tid == 0) {
        float S = 0.f, S2 = 0.f;
        for (int i = 0; i < 8; i++) { S += ws[i]; S2 += ws2[i]; }
        float mean = S * (1.f / Dc);
        float var = S2 * (1.f / Dc) - mean * mean;
        mean_s = mean;
        rstd_s = rsqrtf(var + 1e-5f);
    }
    __syncthreads();
    float mean = mean_s, rstd = rstd_s;
    float4 gv = *(const float4*)(g + tid * 4);
    float4 bev = *(const float4*)(be + tid * 4);
    float4 o;
    o.x = (v.x - mean) * rstd * gv.x + bev.x;
    o.y = (v.y - mean) * rstd * gv.y + bev.y;
    o.z = (v.z - mean) * rstd * gv.z + bev.z;
    o.w = (v.w - mean) * rstd * gv.w + bev.w;
    *(float4*)(out + base) = o;
}

// ---------------- launch ----------------
extern "C" void kernel_launch(void* const* d_in, const int* in_sizes, int n_in,
                              void* d_out, int out_size)
{
    const float* x       = (const float*)d_in[0];
    const float* premix1 = (const float*)d_in[1];
    const float* e1w1    = (const float*)d_in[2];
    const float* e1b1    = (const float*)d_in[3];
    const float* e1w2    = (const float*)d_in[4];
    const float* e1b2    = (const float*)d_in[5];
    const float* premix2 = (const float*)d_in[6];
    const float* e2w1    = (const float*)d_in[7];
    const float* e2b1    = (const float*)d_in[8];
    const float* e2w2    = (const float*)d_in[9];
    const float* e2b2    = (const float*)d_in[10];
    const float* wqkv    = (const float*)d_in[11];
    const float* bqkv    = (const float*)d_in[12];
    const float* wo      = (const float*)d_in[13];
    const float* bo      = (const float*)d_in[14];
    const float* rot     = (const float*)d_in[15];
    const float* ln1g    = (const float*)d_in[16];
    const float* ln1b    = (const float*)d_in[17];
    const float* ln2g    = (const float*)d_in[18];
    const float* ln2b    = (const float*)d_in[19];
    const float* emb     = (const float*)d_in[20];
    const float* mw1     = (const float*)d_in[21];
    const float* mb1     = (const float*)d_in[22];
    const float* mw2     = (const float*)d_in[23];
    const float* mb2     = (const float*)d_in[24];
    const int*   ph      = (const int*)d_in[25];
    float* out = (float*)d_out;

    float *pH, *pE, *pG, *pXA, *pQKV, *pT, *pX1;
    int *pBk, *pIdx, *pBs;
    __nv_bfloat16 *aH, *aL, *eH, *eL, *fH, *fL, *wH, *wL;
    cudaGetSymbolAddress((void**)&pH, g_bufH);
    cudaGetSymbolAddress((void**)&pE, g_bufE);
    cudaGetSymbolAddress((void**)&pG, g_bufG);
    cudaGetSymbolAddress((void**)&pXA, g_bufXA);
    cudaGetSymbolAddress((void**)&pQKV, g_bufQKV);
    cudaGetSymbolAddress((void**)&pT, g_bufT);
    cudaGetSymbolAddress((void**)&pX1, g_bufX1);
    cudaGetSymbolAddress((void**)&pBk, g_buckets);
    cudaGetSymbolAddress((void**)&pIdx, g_idx);
    cudaGetSymbolAddress((void**)&pBs, g_bsort);
    cudaGetSymbolAddress((void**)&aH, g_a16h);
    cudaGetSymbolAddress((void**)&aL, g_a16l);
    cudaGetSymbolAddress((void**)&eH, g_e16h);
    cudaGetSymbolAddress((void**)&eL, g_e16l);
    cudaGetSymbolAddress((void**)&fH, g_f16h);
    cudaGetSymbolAddress((void**)&fL, g_f16l);
    cudaGetSymbolAddress((void**)&wH, g_wth);
    cudaGetSymbolAddress((void**)&wL, g_wtl);

    cudaFuncSetAttribute(bgemm2_kernel<ACT_NONE, 0>, cudaFuncAttributeMaxDynamicSharedMemorySize, BG_DSM);
    cudaFuncSetAttribute(bgemm2_kernel<ACT_SILU, 1>, cudaFuncAttributeMaxDynamicSharedMemorySize, BG_DSM);
    cudaFuncSetAttribute(bgemm2_kernel<ACT_SIGMOID, 0>, cudaFuncAttributeMaxDynamicSharedMemorySize, BG_DSM);
    cudaFuncSetAttribute(bgemm2_kernel<ACT_GELU, 1>, cudaFuncAttributeMaxDynamicSharedMemorySize, BG_DSM);

    // ---- side stream + events (host infra, created once outside capture) ----
    static cudaStream_t s_side = nullptr;
    static cudaEvent_t s_ev_fork = nullptr, s_ev_join = nullptr;
    static cudaEvent_t s_ev_fork2 = nullptr, s_ev_join2 = nullptr;
    if (s_side == nullptr) {
        cudaStreamCreateWithFlags(&s_side, cudaStreamNonBlocking);
        cudaEventCreateWithFlags(&s_ev_fork, cudaEventDisableTiming);
        cudaEventCreateWithFlags(&s_ev_join, cudaEventDisableTiming);
        cudaEventCreateWithFlags(&s_ev_fork2, cudaEventDisableTiming);
        cudaEventCreateWithFlags(&s_ev_join2, cudaEventDisableTiming);
    }

    const int ew_blocks = Mrows * Dc / (256 * 4);
    dim3 tsb(32, 8);

    // ---- fork #1: weight transpose/split on side stream, overlapped with elapsic1 ----
    cudaEventRecord(s_ev_fork, 0);
    cudaStreamWaitEvent(s_side, s_ev_fork, 0);
    tsplit_kernel<<<dim3(QKVW / 32, Dc / 32), tsb, 0, s_side>>>(wqkv, wH + OFF_QKV, wL + OFF_QKV, Dc, QKVW);
    tsplit_kernel<<<dim3(Dc / 32, Dc / 32), tsb, 0, s_side>>>(wo, wH + OFF_WO, wL + OFF_WO, Dc, Dc);
    tsplit_kernel<<<dim3(Ec / 32, Dc / 32), tsb, 0, s_side>>>(e2w1, wH + OFF_E2W1, wL + OFF_E2W1, Dc, Ec);
    tsplit_kernel<<<dim3(Dc / 32, Ec / 32), tsb, 0, s_side>>>(e2w2, wH + OFF_E2W2, wL + OFF_E2W2, Ec, Dc);
    tsplit_kernel<<<dim3(Fc / 32, Dc / 32), tsb, 0, s_side>>>(mw1, wH + OFF_MW1, wL + OFF_MW1, Dc, Fc);
    tsplit_kernel<<<dim3(Dc / 32, Fc / 32), tsb, 0, s_side>>>(mw2, wH + OFF_MW2, wL + OFF_MW2, Fc, Dc);
    cudaEventRecord(s_ev_join, s_side);

    // ---- time_elapsic 1 (fp32 exact: feeds the LSH bucket path) [main stream] ----
    build_h_kernel<<<ew_blocks, 256>>>(x, premix1, pH, nullptr, nullptr);
    sgemm_kernel<ACT_SILU><<<dim3(Ec / 128, Mrows / 128), 256>>>(pH, e1w1, e1b1, pE, Mrows, Ec, Dc, Ec, Ec);
    sgemm_kernel<ACT_SIGMOID><<<dim3(Dc / 128, Mrows / 128), 256>>>(pE, e1w2, e1b2, pG, Mrows, Dc, Ec, Dc, Dc);
    combine_kernel<<<ew_blocks, 256>>>(x, pG, pXA, aH, aL);

    // main stream must see split weights before Q/V bgemm
    cudaStreamWaitEvent(0, s_ev_join, 0);

    // ---- fork #2: fp32 K-projection + hash + sort on side stream, overlapped with Q/V bgemms ----
    cudaEventRecord(s_ev_fork2, 0);
    cudaStreamWaitEvent(s_side, s_ev_fork2, 0);
    sgemm_kernel<ACT_NONE><<<dim3(8, Mrows / 128), 256, 0, s_side>>>(pXA, wqkv + 1024, bqkv + 1024, pQKV + 1024, Mrows, 1024, Dc, QKVW, QKVW);
    hash_kernel<<<dim3(Sc / 128, Bc * Hc), 128, 0, s_side>>>(pQKV, rot, pBk);
    sort_kernel<<<Bc * Hc, 64, 0, s_side>>>(pBk, pIdx, pBs);
    cudaEventRecord(s_ev_join2, s_side);

    bgemm2_kernel<ACT_NONE, 0><<<dim3(8, 128), 256, BG_DSM>>>(aH, aL, Dc, wH + OFF_QKV, wL + OFF_QKV, bqkv, pQKV, nullptr, nullptr, Dc, QKVW);
    bgemm2_kernel<ACT_NONE, 0><<<dim3(8, 128), 256, BG_DSM>>>(aH, aL, Dc, wH + OFF_QKV + (size_t)2048 * Dc, wL + OFF_QKV + (size_t)2048 * Dc, bqkv + 2048, pQKV + 2048, nullptr, nullptr, Dc, QKVW);

    // join: attn needs K cols + idx/bsort written by the side stream
    cudaStreamWaitEvent(0, s_ev_join2, 0);

    attn_kernel<<<dim3(NCHUNK, Bc * Hc), 128>>>(pQKV, pIdx, pBs, aH, aL);  // ATT planes overwrite XA planes
    bgemm2_kernel<ACT_NONE, 0><<<dim3(8, 128), 256, BG_DSM>>>(aH, aL, Dc, wH + OFF_WO, wL + OFF_WO, bo, pT, nullptr, nullptr, Dc, Dc);
    ln_add_kernel<<<Mrows, 256>>>(x, pT, ln1g, ln1b, pX1);

    // ---- time_elapsic 2 (tensor) ----
    build_h_kernel<<<ew_blocks, 256>>>(pX1, premix2, pH, aH, aL);
    bgemm2_kernel<ACT_SILU, 1><<<dim3(2, 128), 256, BG_DSM>>>(aH, aL, Dc, wH + OFF_E2W1, wL + OFF_E2W1, e2b1, nullptr, eH, eL, Dc, Ec);
    bgemm2_kernel<ACT_SIGMOID, 0><<<dim3(8, 128), 256, BG_DSM>>>(eH, eL, Ec, wH + OFF_E2W2, wL + OFF_E2W2, e2b2, pG, nullptr, nullptr, Ec, Dc);
    combine_kernel<<<ew_blocks, 256>>>(pX1, pG, pXA, aH, aL);

    // ---- MLP + deepembed + LN2 (tensor; F kept bf16-planes only) ----
    bgemm2_kernel<ACT_GELU, 1><<<dim3(32, 128), 256, BG_DSM>>>(aH, aL, Dc, wH + OFF_MW1, wL + OFF_MW1, mb1, nullptr, fH, fL, Dc, Fc);
    bgemm2_kernel<ACT_NONE, 0><<<dim3(8, 128), 256, BG_DSM>>>(fH, fL, Fc, wH + OFF_MW2, wL + OFF_MW2, mb2, pT, nullptr, nullptr, Fc, Dc);
    ln_emb_kernel<<<Mrows, 256>>>(pX1, pT, emb, ph, ln2g, ln2b, out);
}

// round 12
// speedup vs baseline: 2.6956x; 1.3054x over previous
#include <cuda_runtime.h>
#include <cuda_bf16.h>
#include <cuda_fp16.h>
#include <math.h>
#include <stdint.h>

// ---------------- problem constants ----------------
#define Bc 4
#define Sc 4096
#define Dc 1024
#define Hc 16
#define Dhc 64
#define Ec 256
#define Fc 4096
#define CHUNKc 128
#define Mrows (Bc * Sc)          // 16384
#define QKVW (3 * Hc * Dhc)      // 3072
#define NCHUNK (Sc / CHUNKc)     // 32

// weight-plane offsets (elements) inside g_wt
#define OFF_QKV  0
#define OFF_WO   3145728
#define OFF_E2W1 4194304
#define OFF_E2W2 4456448
#define OFF_MW1  4718592
#define OFF_MW2  8912896
#define WT_TOT   13107200

// ---------------- scratch (device globals; no allocations allowed) ----------------
__device__ float g_bufH[(size_t)Mrows * Dc];
__device__ float g_bufE[(size_t)Mrows * Ec];
__device__ float g_bufG[(size_t)Mrows * Dc];
__device__ float g_bufXA[(size_t)Mrows * Dc];
__device__ float g_bufQKV[(size_t)Mrows * QKVW];
__device__ float g_bufT[(size_t)Mrows * Dc];
__device__ float g_bufX1[(size_t)Mrows * Dc];
__device__ int g_buckets[Bc * Hc * Sc];
__device__ int g_idx[Bc * Hc * Sc];
__device__ int g_bsort[Bc * Hc * Sc];
// 16-bit planes (bf16 hi/lo or fp16 storage, reinterpreted as needed)
__device__ __nv_bfloat16 g_a16h[(size_t)Mrows * Dc];
__device__ __nv_bfloat16 g_a16l[(size_t)Mrows * Dc];
__device__ __nv_bfloat16 g_e16h[(size_t)Mrows * Ec];
__device__ __nv_bfloat16 g_e16l[(size_t)Mrows * Ec];
__device__ __nv_bfloat16 g_f16h[(size_t)Mrows * Fc];
__device__ __nv_bfloat16 g_wth[WT_TOT];
__device__ __nv_bfloat16 g_wtl[WT_TOT];

// ---------------- activations ----------------
enum { ACT_NONE = 0, ACT_SILU = 1, ACT_GELU = 2, ACT_SIGMOID = 3 };

template <int ACT>
__device__ __forceinline__ float apply_act(float x) {
    if (ACT == ACT_SILU) return x / (1.f + __expf(-x));
    if (ACT == ACT_GELU) {
        float t = tanhf(0.7978845608028654f * (x + 0.044715f * x * x * x));
        return 0.5f * x * (1.f + t);
    }
    if (ACT == ACT_SIGMOID) return 1.f / (1.f + __expf(-x));
    return x;
}

__device__ __forceinline__ uint32_t smem_u32(const void* p) {
    uint32_t a;
    asm("{ .reg .u64 t; cvta.to.shared.u64 t, %1; cvt.u32.u64 %0, t; }" : "=r"(a) : "l"(p));
    return a;
}
__device__ __forceinline__ uint32_t pack_bf2(__nv_bfloat16 a, __nv_bfloat16 b) {
    __nv_bfloat162 t; t.x = a; t.y = b;
    return *(uint32_t*)&t;
}
__device__ __forceinline__ uint32_t pack_h2(__half a, __half b) {
    __half2 t; t.x = a; t.y = b;
    return *(uint32_t*)&t;
}
__device__ __forceinline__ void split2(float v, __nv_bfloat16& h, __nv_bfloat16& l) {
    h = __float2bfloat16(v);
    l = __float2bfloat16(v - __bfloat162float(h));
}
__device__ __forceinline__ void cpa16(uint32_t dst, const void* src) {
    asm volatile("cp.async.cg.shared.global [%0], [%1], 16;" :: "r"(dst), "l"(src));
}
__device__ __forceinline__ void mma16816(float* c, const uint32_t* a, const uint32_t* b) {
    asm volatile(
        "mma.sync.aligned.m16n8k16.row.col.f32.bf16.bf16.f32 "
        "{%0,%1,%2,%3}, {%4,%5,%6,%7}, {%8,%9}, {%0,%1,%2,%3};"
        : "+f"(c[0]), "+f"(c[1]), "+f"(c[2]), "+f"(c[3])
        : "r"(a[0]), "r"(a[1]), "r"(a[2]), "r"(a[3]), "r"(b[0]), "r"(b[1]));
}
__device__ __forceinline__ void mma16816h(float* c, const uint32_t* a, const uint32_t* b) {
    asm volatile(
        "mma.sync.aligned.m16n8k16.row.col.f32.f16.f16.f32 "
        "{%0,%1,%2,%3}, {%4,%5,%6,%7}, {%8,%9}, {%0,%1,%2,%3};"
        : "+f"(c[0]), "+f"(c[1]), "+f"(c[2]), "+f"(c[3])
        : "r"(a[0]), "r"(a[1]), "r"(a[2]), "r"(a[3]), "r"(b[0]), "r"(b[1]));
}
__device__ __forceinline__ void ldm4(uint32_t* d, uint32_t addr) {
    asm volatile("ldmatrix.sync.aligned.m8n8.x4.shared.b16 {%0,%1,%2,%3}, [%4];"
                 : "=r"(d[0]), "=r"(d[1]), "=r"(d[2]), "=r"(d[3]) : "r"(addr));
}

// ---------------- weight transpose+split: W[K,N] -> Wt hi/lo [N,K] (bf16) ----------------
__global__ void tsplit_kernel(const float* __restrict__ W,
                              __nv_bfloat16* __restrict__ tH, __nv_bfloat16* __restrict__ tL,
                              int K, int N)
{
    __shared__ float t[32][33];
    int n0 = blockIdx.x * 32, k0 = blockIdx.y * 32;
    int tx = threadIdx.x, ty = threadIdx.y;
#pragma unroll
    for (int i = 0; i < 4; i++) {
        int k = k0 + ty + i * 8;
        t[ty + i * 8][tx] = W[(size_t)k * N + n0 + tx];
    }
    __syncthreads();
#pragma unroll
    for (int i = 0; i < 4; i++) {
        int n = n0 + ty + i * 8;
        float v = t[tx][ty + i * 8];
        __nv_bfloat16 h, l;
        split2(v, h, l);
        tH[(size_t)n * K + k0 + tx] = h;
        tL[(size_t)n * K + k0 + tx] = l;
    }
}

// ---------------- weight transpose, single fp16 plane: W[K,N] -> [N,K] ----------------
__global__ void tsplit16_kernel(const float* __restrict__ W,
                                __half* __restrict__ T, int K, int N)
{
    __shared__ float t[32][33];
    int n0 = blockIdx.x * 32, k0 = blockIdx.y * 32;
    int tx = threadIdx.x, ty = threadIdx.y;
#pragma unroll
    for (int i = 0; i < 4; i++) {
        int k = k0 + ty + i * 8;
        t[ty + i * 8][tx] = W[(size_t)k * N + n0 + tx];
    }
    __syncthreads();
#pragma unroll
    for (int i = 0; i < 4; i++) {
        int n = n0 + ty + i * 8;
        T[(size_t)n * K + k0 + tx] = __float2half(t[tx][ty + i * 8]);
    }
}

// ============ bf16x3 HMMA GEMM: cp.async double buffering + ldmatrix frags ============
#define ST_EL 5120      // elems per plane per stage (128*40)
#define STAGE_EL 20480  // 4 planes
#define BG_DSM (2 * STAGE_EL * 2)  // bytes = 81920

__device__ __forceinline__ void bg_stage(
    uint32_t sbase, int s, int c, int tid, int row0, int n0,
    const __nv_bfloat16* __restrict__ aHi, const __nv_bfloat16* __restrict__ aLo, int lda,
    const __nv_bfloat16* __restrict__ btHi, const __nv_bfloat16* __restrict__ btLo, int K)
{
    int k0 = c * 32;
#pragma unroll
    for (int j = 0; j < 2; j++) {
        int c2 = tid + j * 256;
        int row = c2 >> 2, seg = (c2 & 3) << 3;
        uint32_t off = sbase + (uint32_t)(s * STAGE_EL + row * 40 + seg) * 2;
        size_t ga = (size_t)(row0 + row) * lda + k0 + seg;
        size_t gb = (size_t)(n0 + row) * K + k0 + seg;
        cpa16(off,                 aHi + ga);
        cpa16(off + ST_EL * 2,     aLo + ga);
        cpa16(off + 2 * ST_EL * 2, btHi + gb);
        cpa16(off + 3 * ST_EL * 2, btLo + gb);
    }
}

template <int ACT, int OUT16>
__global__ __launch_bounds__(256, 2) void bgemm2_kernel(
    const __nv_bfloat16* __restrict__ aHi, const __nv_bfloat16* __restrict__ aLo, int lda,
    const __nv_bfloat16* __restrict__ btHi, const __nv_bfloat16* __restrict__ btLo,
    const float* __restrict__ bias, float* __restrict__ C,
    __nv_bfloat16* __restrict__ cH, __nv_bfloat16* __restrict__ cL,
    int K, int ldc)
{
    extern __shared__ __align__(16) char dsm[];
    uint32_t sbase = smem_u32(dsm);

    int tid = threadIdx.x;
    int wid = tid >> 5, lane = tid & 31;
    int n0 = blockIdx.x * 128;
    int row0 = blockIdx.y * 128;
    int wm = (wid & 1) * 64;
    int wn = (wid >> 1) * 32;
    int lr = lane >> 2;
    int lc = (lane & 3) * 2;

    int a_row_off = (lane & 15);
    int a_col_off = (lane >> 4) * 8;
    int b_row_off = (lane & 7) + (lane >> 4) * 8;
    int b_col_off = ((lane >> 3) & 1) * 8;

    float acc[4][4][4];
#pragma unroll
    for (int mt = 0; mt < 4; mt++)
#pragma unroll
        for (int nt = 0; nt < 4; nt++)
#pragma unroll
            for (int e = 0; e < 4; e++) acc[mt][nt][e] = 0.f;

    int nch = K >> 5;
    bg_stage(sbase, 0, 0, tid, row0, n0, aHi, aLo, lda, btHi, btLo, K);
    asm volatile("cp.async.commit_group;");

    for (int c = 0; c < nch; c++) {
        if (c + 1 < nch) {
            bg_stage(sbase, (c + 1) & 1, c + 1, tid, row0, n0, aHi, aLo, lda, btHi, btLo, K);
            asm volatile("cp.async.commit_group;");
            asm volatile("cp.async.wait_group 1;");
        } else {
            asm volatile("cp.async.wait_group 0;");
        }
        __syncthreads();

        int s = c & 1;
        uint32_t pAh = sbase + (uint32_t)(s * STAGE_EL) * 2;
        uint32_t pAl = pAh + ST_EL * 2;
        uint32_t pBh = pAh + 2 * ST_EL * 2;
        uint32_t pBl = pAh + 3 * ST_EL * 2;

#pragma unroll
        for (int kt = 0; kt < 32; kt += 16) {
            uint32_t bh[4][2], bl[4][2];
#pragma unroll
            for (int np = 0; np < 2; np++) {
                uint32_t off = (uint32_t)((wn + np * 16 + b_row_off) * 40 + kt + b_col_off) * 2;
                uint32_t d[4];
                ldm4(d, pBh + off);
                bh[np * 2][0] = d[0]; bh[np * 2][1] = d[1];
                bh[np * 2 + 1][0] = d[2]; bh[np * 2 + 1][1] = d[3];
                ldm4(d, pBl + off);
                bl[np * 2][0] = d[0]; bl[np * 2][1] = d[1];
                bl[np * 2 + 1][0] = d[2]; bl[np * 2 + 1][1] = d[3];
            }
#pragma unroll
            for (int mt = 0; mt < 4; mt++) {
                uint32_t off = (uint32_t)((wm + mt * 16 + a_row_off) * 40 + kt + a_col_off) * 2;
                uint32_t ah[4], al[4];
                ldm4(ah, pAh + off);
                ldm4(al, pAl + off);
#pragma unroll
                for (int nt = 0; nt < 4; nt++) {
                    mma16816(acc[mt][nt], ah, bh[nt]);
                    mma16816(acc[mt][nt], ah, bl[nt]);
                    mma16816(acc[mt][nt], al, bh[nt]);
                }
            }
        }
        __syncthreads();
    }

    // ---- epilogue ----
#pragma unroll
    for (int mt = 0; mt < 4; mt++) {
        int row = row0 + wm + mt * 16 + lr;
#pragma unroll
        for (int nt = 0; nt < 4; nt++) {
            int col = n0 + wn + nt * 8 + lc;
            float b0 = bias[col], b1 = bias[col + 1];
            float v00 = apply_act<ACT>(acc[mt][nt][0] + b0);
            float v01 = apply_act<ACT>(acc[mt][nt][1] + b1);
            float v10 = apply_act<ACT>(acc[mt][nt][2] + b0);
            float v11 = apply_act<ACT>(acc[mt][nt][3] + b1);
            if (OUT16) {
                __nv_bfloat16 h0, l0, h1, l1;
                split2(v00, h0, l0); split2(v01, h1, l1);
                *(uint32_t*)&cH[(size_t)row * ldc + col] = pack_bf2(h0, h1);
                *(uint32_t*)&cL[(size_t)row * ldc + col] = pack_bf2(l0, l1);
                split2(v10, h0, l0); split2(v11, h1, l1);
                *(uint32_t*)&cH[(size_t)(row + 8) * ldc + col] = pack_bf2(h0, h1);
                *(uint32_t*)&cL[(size_t)(row + 8) * ldc + col] = pack_bf2(l0, l1);
            } else {
                *(float2*)(C + (size_t)row * ldc + col) = make_float2(v00, v01);
                *(float2*)(C + (size_t)(row + 8) * ldc + col) = make_float2(v10, v11);
            }
        }
    }
}

// ============ fp16 x1 HMMA GEMM (smooth MLP path): cp.async + ldmatrix ============
#define BH_ST 5120       // elems per plane per stage (128*40)
#define BH_STAGE 10240   // 2 planes (A, B)
#define BH_DSM (2 * BH_STAGE * 2)  // 40960 bytes

__device__ __forceinline__ void bh_stage(
    uint32_t sbase, int s, int c, int tid, int row0, int n0,
    const __half* __restrict__ A, int lda, const __half* __restrict__ Bt, int K)
{
    int k0 = c * 32;
#pragma unroll
    for (int j = 0; j < 2; j++) {
        int c2 = tid + j * 256;
        int row = c2 >> 2, seg = (c2 & 3) << 3;
        uint32_t off = sbase + (uint32_t)(s * BH_STAGE + row * 40 + seg) * 2;
        cpa16(off,             A + (size_t)(row0 + row) * lda + k0 + seg);
        cpa16(off + BH_ST * 2, Bt + (size_t)(n0 + row) * K + k0 + seg);
    }
}

// OMODE: 0 = fp32 out, 2 = fp16 out
template <int ACT, int OMODE>
__global__ __launch_bounds__(256, 2) void bgemmh_kernel(
    const __half* __restrict__ A, int lda, const __half* __restrict__ Bt,
    const float* __restrict__ bias, float* __restrict__ C, __half* __restrict__ C16,
    int K, int ldc)
{
    extern __shared__ __align__(16) char dsm[];
    uint32_t sbase = smem_u32(dsm);

    int tid = threadIdx.x;
    int wid = tid >> 5, lane = tid & 31;
    int n0 = blockIdx.x * 128;
    int row0 = blockIdx.y * 128;
    int wm = (wid & 1) * 64;
    int wn = (wid >> 1) * 32;
    int lr = lane >> 2;
    int lc = (lane & 3) * 2;

    int a_row_off = (lane & 15);
    int a_col_off = (lane >> 4) * 8;
    int b_row_off = (lane & 7) + (lane >> 4) * 8;
    int b_col_off = ((lane >> 3) & 1) * 8;

    float acc[4][4][4];
#pragma unroll
    for (int mt = 0; mt < 4; mt++)
#pragma unroll
        for (int nt = 0; nt < 4; nt++)
#pragma unroll
            for (int e = 0; e < 4; e++) acc[mt][nt][e] = 0.f;

    int nch = K >> 5;
    bh_stage(sbase, 0, 0, tid, row0, n0, A, lda, Bt, K);
    asm volatile("cp.async.commit_group;");

    for (int c = 0; c < nch; c++) {
        if (c + 1 < nch) {
            bh_stage(sbase, (c + 1) & 1, c + 1, tid, row0, n0, A, lda, Bt, K);
            asm volatile("cp.async.commit_group;");
            asm volatile("cp.async.wait_group 1;");
        } else {
            asm volatile("cp.async.wait_group 0;");
        }
        __syncthreads();

        int s = c & 1;
        uint32_t pA = sbase + (uint32_t)(s * BH_STAGE) * 2;
        uint32_t pB = pA + BH_ST * 2;

#pragma unroll
        for (int kt = 0; kt < 32; kt += 16) {
            uint32_t bfr[4][2];
#pragma unroll
            for (int np = 0; np < 2; np++) {
                uint32_t off = (uint32_t)((wn + np * 16 + b_row_off) * 40 + kt + b_col_off) * 2;
                uint32_t d[4];
                ldm4(d, pB + off);
                bfr[np * 2][0] = d[0]; bfr[np * 2][1] = d[1];
                bfr[np * 2 + 1][0] = d[2]; bfr[np * 2 + 1][1] = d[3];
            }
#pragma unroll
            for (int mt = 0; mt < 4; mt++) {
                uint32_t off = (uint32_t)((wm + mt * 16 + a_row_off) * 40 + kt + a_col_off) * 2;
                uint32_t afr[4];
                ldm4(afr, pA + off);
#pragma unroll
                for (int nt = 0; nt < 4; nt++) {
                    mma16816h(acc[mt][nt], afr, bfr[nt]);
                }
            }
        }
        __syncthreads();
    }

    // ---- epilogue ----
#pragma unroll
    for (int mt = 0; mt < 4; mt++) {
        int row = row0 + wm + mt * 16 + lr;
#pragma unroll
        for (int nt = 0; nt < 4; nt++) {
            int col = n0 + wn + nt * 8 + lc;
            float b0 = bias[col], b1 = bias[col + 1];
            float v00 = apply_act<ACT>(acc[mt][nt][0] + b0);
            float v01 = apply_act<ACT>(acc[mt][nt][1] + b1);
            float v10 = apply_act<ACT>(acc[mt][nt][2] + b0);
            float v11 = apply_act<ACT>(acc[mt][nt][3] + b1);
            if (OMODE == 2) {
                *(uint32_t*)&C16[(size_t)row * ldc + col] =
                    pack_h2(__float2half(v00), __float2half(v01));
                *(uint32_t*)&C16[(size_t)(row + 8) * ldc + col] =
                    pack_h2(__float2half(v10), __float2half(v11));
            } else {
                *(float2*)(C + (size_t)row * ldc + col) = make_float2(v00, v01);
                *(float2*)(C + (size_t)(row + 8) * ldc + col) = make_float2(v10, v11);
            }
        }
    }
}

// ---------------- fp32 SGEMM (bucket-exact path) ----------------
template <int ACT>
__global__ __launch_bounds__(256, 2) void sgemm_kernel(
    const float* __restrict__ A, const float* __restrict__ B,
    const float* __restrict__ bias, float* __restrict__ C,
    int M, int N, int K, int ldb, int ldc)
{
    __shared__ __align__(16) float As[2][128][20];
    __shared__ __align__(16) float Bs[2][16][128];
    int tid = threadIdx.x;
    int col0 = blockIdx.x * 128;
    int row0 = blockIdx.y * 128;
    int ty = tid >> 4, tx = tid & 15;

    float acc[8][8];
#pragma unroll
    for (int i = 0; i < 8; i++)
#pragma unroll
        for (int j = 0; j < 8; j++) acc[i][j] = 0.f;

    const float* Ablk = A + (size_t)row0 * K;
    const float* Bblk = B + col0;
    int nch = K >> 4;

    auto stage = [&](int s, int c) {
        int k0 = c << 4;
#pragma unroll
        for (int j = 0; j < 2; j++) {
            int idx = tid + j * 256;
            int ar = idx >> 2, ac4 = (idx & 3) << 2;
            cpa16(smem_u32(&As[s][ar][ac4]), Ablk + (size_t)ar * K + k0 + ac4);
            int br = idx >> 5, bc = (idx & 31) << 2;
            cpa16(smem_u32(&Bs[s][br][bc]), Bblk + (size_t)(k0 + br) * ldb + bc);
        }
    };

    stage(0, 0);
    asm volatile("cp.async.commit_group;");

    for (int c = 0; c < nch; c++) {
        if (c + 1 < nch) {
            stage((c + 1) & 1, c + 1);
            asm volatile("cp.async.commit_group;");
            asm volatile("cp.async.wait_group 1;");
        } else {
            asm volatile("cp.async.wait_group 0;");
        }
        __syncthreads();
        int s = c & 1;
#pragma unroll
        for (int kk = 0; kk < 16; kk++) {
            float ra[8], rb[8];
#pragma unroll
            for (int i = 0; i < 8; i++) ra[i] = As[s][ty * 8 + i][kk];
            *(float4*)(rb) = *(const float4*)&Bs[s][kk][tx * 8];
            *(float4*)(rb + 4) = *(const float4*)&Bs[s][kk][tx * 8 + 4];
#pragma unroll
            for (int i = 0; i < 8; i++)
#pragma unroll
                for (int j = 0; j < 8; j++) acc[i][j] += ra[i] * rb[j];
        }
        __syncthreads();
    }

#pragma unroll
    for (int i = 0; i < 8; i++) {
        size_t r = (size_t)row0 + ty * 8 + i;
#pragma unroll
        for (int j = 0; j < 8; j += 4) {
            int c = col0 + tx * 8 + j;
            float4 o;
            o.x = apply_act<ACT>(acc[i][j + 0] + bias[c + 0]);
            o.y = apply_act<ACT>(acc[i][j + 1] + bias[c + 1]);
            o.z = apply_act<ACT>(acc[i][j + 2] + bias[c + 2]);
            o.w = apply_act<ACT>(acc[i][j + 3] + bias[c + 3]);
            *(float4*)(C + r * ldc + c) = o;
        }
    }
}

// ---------------- time_elapsic helpers (optionally emit 16-bit planes) ----------------
__global__ void build_h_kernel(const float* __restrict__ x,
                               const float* __restrict__ premix,
                               float* __restrict__ out,
                               __nv_bfloat16* __restrict__ oH,
                               __nv_bfloat16* __restrict__ oL)
{
    size_t i4 = (size_t)blockIdx.x * blockDim.x + threadIdx.x;
    size_t base = i4 * 4;
    int d = (int)(base & (Dc - 1));
    int row = (int)(base >> 10);
    int s = row & (Sc - 1);
    float4 xv = *(const float4*)(x + base);
    float4 pv = (s > 0) ? *(const float4*)(x + base - Dc) : make_float4(0.f, 0.f, 0.f, 0.f);
    float4 pm = *(const float4*)(premix + d);
    float4 o;
    o.x = xv.x + (pv.x - xv.x) * pm.x;
    o.y = xv.y + (pv.y - xv.y) * pm.y;
    o.z = xv.z + (pv.z - xv.z) * pm.z;
    o.w = xv.w + (pv.w - xv.w) * pm.w;
    *(float4*)(out + base) = o;
    if (oH) {
        __nv_bfloat16 h0, l0, h1, l1, h2, l2, h3, l3;
        split2(o.x, h0, l0); split2(o.y, h1, l1);
        split2(o.z, h2, l2); split2(o.w, h3, l3);
        *(uint2*)&oH[base] = make_uint2(pack_bf2(h0, h1), pack_bf2(h2, h3));
        *(uint2*)&oL[base] = make_uint2(pack_bf2(l0, l1), pack_bf2(l2, l3));
    }
}

__global__ void combine_kernel(const float* __restrict__ x,
                               const float* __restrict__ gate,
                               float* __restrict__ out,
                               __nv_bfloat16* __restrict__ oH,
                               __nv_bfloat16* __restrict__ oL,
                               __half* __restrict__ oF)
{
    size_t i4 = (size_t)blockIdx.x * blockDim.x + threadIdx.x;
    size_t base = i4 * 4;
    int row = (int)(base >> 10);
    int s = row & (Sc - 1);
    float4 xv = *(const float4*)(x + base);
    float4 pv = (s > 0) ? *(const float4*)(x + base - Dc) : make_float4(0.f, 0.f, 0.f, 0.f);
    float4 gv = *(const float4*)(gate + base);
    float4 o;
    o.x = xv.x + (pv.x - xv.x) * gv.x;
    o.y = xv.y + (pv.y - xv.y) * gv.y;
    o.z = xv.z + (pv.z - xv.z) * gv.z;
    o.w = xv.w + (pv.w - xv.w) * gv.w;
    *(float4*)(out + base) = o;
    if (oH) {
        __nv_bfloat16 h0, l0, h1, l1, h2, l2, h3, l3;
        split2(o.x, h0, l0); split2(o.y, h1, l1);
        split2(o.z, h2, l2); split2(o.w, h3, l3);
        *(uint2*)&oH[base] = make_uint2(pack_bf2(h0, h1), pack_bf2(h2, h3));
        *(uint2*)&oL[base] = make_uint2(pack_bf2(l0, l1), pack_bf2(l2, l3));
    }
    if (oF) {
        *(uint2*)&oF[base] = make_uint2(
            pack_h2(__float2half(o.x), __float2half(o.y)),
            pack_h2(__float2half(o.z), __float2half(o.w)));
    }
}

// ---------------- LSH hashing ----------------
__global__ void hash_kernel(const float* __restrict__ qkv,
                            const float* __restrict__ rot,
                            int* __restrict__ buckets)
{
    int bh = blockIdx.y;
    int b = bh >> 4, h = bh & 15;
    int s = blockIdx.x * 128 + threadIdx.x;
    __shared__ float rotS[Dhc * 32];
    for (int i = threadIdx.x; i < Dhc * 32; i += 128) rotS[i] = rot[h * (Dhc * 32) + i];
    __syncthreads();
    const float* kp = qkv + ((size_t)(b * Sc + s) * QKVW) + (Hc + h) * Dhc;
    float r[32];
#pragma unroll
    for (int n = 0; n < 32; n++) r[n] = 0.f;
    for (int d = 0; d < Dhc; d++) {
        float kd = kp[d];
#pragma unroll
        for (int n = 0; n < 32; n++) r[n] += kd * rotS[d * 32 + n];
    }
    float best = r[0];
    int bi = 0;
#pragma unroll
    for (int n = 1; n < 32; n++)
        if (r[n] > best) { best = r[n]; bi = n; }
#pragma unroll
    for (int n = 0; n < 32; n++)
        if (-r[n] > best) { best = -r[n]; bi = 32 + n; }
    buckets[(size_t)bh * Sc + s] = bi;
}

// ---------------- stable counting sort per (b,h) row ----------------
__global__ void sort_kernel(const int* __restrict__ buckets,
                            int* __restrict__ idx, int* __restrict__ bsort)
{
    int bh = blockIdx.x;
    int t = threadIdx.x;
    __shared__ int sb[Sc];
    __shared__ int cnt[64][64];
    __shared__ int base[64];
    const int* row = buckets + (size_t)bh * Sc;
    for (int i = t; i < Sc; i += 64) sb[i] = row[i];
    for (int v = 0; v < 64; v++) cnt[t][v] = 0;
    __syncthreads();
    for (int i = t * 64; i < t * 64 + 64; i++) cnt[t][sb[i]]++;
    __syncthreads();
    {
        int run = 0;
        for (int seg = 0; seg < 64; seg++) {
            int c = cnt[seg][t];
            cnt[seg][t] = run;
            run += c;
        }
        base[t] = run;
    }
    __syncthreads();
    if (t == 0) {
        int acc = 0;
        for (int v = 0; v < 64; v++) { int c = base[v]; base[v] = acc; acc += c; }
    }
    __syncthreads();
    int* idxrow = idx + (size_t)bh * Sc;
    int* bsrow = bsort + (size_t)bh * Sc;
    for (int i = t * 64; i < t * 64 + 64; i++) {
        int v = sb[i];
        int p = base[v] + cnt[t][v]++;
        idxrow[p] = i;
        bsrow[p] = v;
    }
}

// ---------------- chunked bucket-masked attention (writes bf16 hi/lo planes) ----------------
__global__ __launch_bounds__(128) void attn_kernel(
    const float* __restrict__ qkv, const int* __restrict__ idx,
    const int* __restrict__ bsort,
    __nv_bfloat16* __restrict__ yH, __nv_bfloat16* __restrict__ yL)
{
    int n = blockIdx.x;
    int bh = blockIdx.y;
    int b = bh >> 4, h = bh & 15;
    int tid = threadIdx.x;
    const int* idxrow = idx + (size_t)bh * Sc;
    const int* bsrow = bsort + (size_t)bh * Sc;

    int pq = n * CHUNKc + tid;
    int orig_q = idxrow[pq];
    int bq = bsrow[pq];
    const float* qptr = qkv + ((size_t)(b * Sc + orig_q) * QKVW) + h * Dhc;
    float4 qreg[16];
#pragma unroll
    for (int f = 0; f < 16; f++) qreg[f] = *(const float4*)(qptr + f * 4);

    float4 acc[16];
#pragma unroll
    for (int f = 0; f < 16; f++) acc[f] = make_float4(0.f, 0.f, 0.f, 0.f);
    float m = -1e30f, l = 0.f;

    __shared__ float4 KS[64 * 16];
    __shared__ float4 VS[64 * 16];
    __shared__ int BK[64];

    for (int tile = 0; tile < 4; tile++) {
        int t0 = tile * 64;
        for (int w = tid; w < 64 * 16; w += 128) {
            int slot = w >> 4, f = w & 15;
            int kslot = t0 + slot;
            int spos;
            bool ok;
            if (kslot < CHUNKc) { ok = (n > 0); spos = (n - 1) * CHUNKc + kslot; }
            else                { ok = true;    spos = n * CHUNKc + (kslot - CHUNKc); }
            if (ok) {
                int og = idxrow[spos];
                const float* kp = qkv + ((size_t)(b * Sc + og) * QKVW) + (Hc + h) * Dhc;
                KS[slot * 16 + f] = *(const float4*)(kp + f * 4);
                VS[slot * 16 + f] = *(const float4*)(kp + Hc * Dhc + f * 4);
                if (f == 0) BK[slot] = bsrow[spos];
            } else if (f == 0) {
                BK[slot] = -1;
            }
        }
        __syncthreads();
        for (int s = 0; s < 64; s++) {
            if (BK[s] != bq) continue;
            const float4* kp4 = &KS[s * 16];
            float dot = 0.f;
#pragma unroll
            for (int f = 0; f < 16; f++) {
                float4 kv = kp4[f];
                dot += qreg[f].x * kv.x + qreg[f].y * kv.y + qreg[f].z * kv.z + qreg[f].w * kv.w;
            }
            dot *= 0.125f;
            float p;
            if (dot > m) {
                float sc = __expf(m - dot);
                l *= sc;
#pragma unroll
                for (int f = 0; f < 16; f++) {
                    acc[f].x *= sc; acc[f].y *= sc; acc[f].z *= sc; acc[f].w *= sc;
                }
                m = dot;
                p = 1.f;
            } else {
                p = __expf(dot - m);
            }
            l += p;
            const float4* vp4 = &VS[s * 16];
#pragma unroll
            for (int f = 0; f < 16; f++) {
                float4 vv = vp4[f];
                acc[f].x += p * vv.x; acc[f].y += p * vv.y;
                acc[f].z += p * vv.z; acc[f].w += p * vv.w;
            }
        }
        __syncthreads();
    }
    float inv = 1.f / l;
    size_t ybase = ((size_t)(b * Sc + orig_q)) * Dc + h * Dhc;
#pragma unroll
    for (int f = 0; f < 16; f++) {
        float4 o = acc[f];
        o.x *= inv; o.y *= inv; o.z *= inv; o.w *= inv;
        __nv_bfloat16 h0, l0, h1, l1, h2, l2, h3, l3;
        split2(o.x, h0, l0); split2(o.y, h1, l1);
        split2(o.z, h2, l2); split2(o.w, h3, l3);
        *(uint2*)&yH[ybase + f * 4] = make_uint2(pack_bf2(h0, h1), pack_bf2(h2, h3));
        *(uint2*)&yL[ybase + f * 4] = make_uint2(pack_bf2(l0, l1), pack_bf2(l2, l3));
    }
}

// ---------------- LayerNorm(a + b) ----------------
__global__ void ln_add_kernel(const float* __restrict__ a, const float* __restrict__ bsum,
                              const float* __restrict__ g, const float* __restrict__ be,
                              float* __restrict__ out)
{
    int r = blockIdx.x, tid = threadIdx.x;
    size_t base = (size_t)r * Dc + tid * 4;
    float4 av = *(const float4*)(a + base);
    float4 bv = *(const float4*)(bsum + base);
    float4 v = make_float4(av.x + bv.x, av.y + bv.y, av.z + bv.z, av.w + bv.w);
    float s = v.x + v.y + v.z + v.w;
    float s2 = v.x * v.x + v.y * v.y + v.z * v.z + v.w * v.w;
    for (int o = 16; o > 0; o >>= 1) {
        s += __shfl_down_sync(~0u, s, o);
        s2 += __shfl_down_sync(~0u, s2, o);
    }
    __shared__ float ws[8], ws2[8];
    __shared__ float mean_s, rstd_s;
    int w = tid >> 5, ln = tid & 31;
    if (ln == 0) { ws[w] = s; ws2[w] = s2; }
    __syncthreads();
    if (tid == 0) {
        float S = 0.f, S2 = 0.f;
        for (int i = 0; i < 8; i++) { S += ws[i]; S2 += ws2[i]; }
        float mean = S * (1.f / Dc);
        float var = S2 * (1.f / Dc) - mean * mean;
        mean_s = mean;
        rstd_s = rsqrtf(var + 1e-5f);
    }
    __syncthreads();
    float mean = mean_s, rstd = rstd_s;
    float4 gv = *(const float4*)(g + tid * 4);
    float4 bev = *(const float4*)(be + tid * 4);
    float4 o;
    o.x = (v.x - mean) * rstd * gv.x + bev.x;
    o.y = (v.y - mean) * rstd * gv.y + bev.y;
    o.z = (v.z - mean) * rstd * gv.z + bev.z;
    o.w = (v.w - mean) * rstd * gv.w + bev.w;
    *(float4*)(out + base) = o;
}

// ---------------- LayerNorm(x1 + t * emb[ph]) ----------------
__global__ void ln_emb_kernel(const float* __restrict__ x1, const float* __restrict__ tin,
                              const float* __restrict__ emb, const int* __restrict__ ph,
                              const float* __restrict__ g, const float* __restrict__ be,
                              float* __restrict__ out)
{
    int r = blockIdx.x, tid = threadIdx.x;
    size_t base = (size_t)r * Dc + tid * 4;
    const float* er = emb + (size_t)ph[r] * Dc;
    float4 av = *(const float4*)(x1 + base);
    float4 tv = *(const float4*)(tin + base);
    float4 ev = *(const float4*)(er + tid * 4);
    float4 v = make_float4(av.x + tv.x * ev.x, av.y + tv.y * ev.y,
                           av.z + tv.z * ev.z, av.w + tv.w * ev.w);
    float s = v.x + v.y + v.z + v.w;
    float s2 = v.x * v.x + v.y * v.y + v.z * v.z + v.w * v.w;
    for (int o = 16; o > 0; o >>= 1) {
        s += __shfl_down_sync(~0u, s, o);
        s2 += __shfl_down_sync(~0u, s2, o);
    }
    __shared__ float ws[8], ws2[8];
    __shared__ float mean_s, rstd_s;
    int w = tid >> 5, ln = tid & 31;
    if (ln == 0) { ws[w] = s; ws2[w] = s2; }
    __syncthreads();
    if (tid == 0) {
        float S = 0.f, S2 = 0.f;
        for (int i = 0; i < 8; i++) { S += ws[i]; S2 += ws2[i]; }
        float mean = S * (1.f / Dc);
        float var = S2 * (1.f / Dc) - mean * mean;
        mean_s = mean;
        rstd_s = rsqrtf(var + 1e-5f);
    }
    __syncthreads();
    float mean = mean_s, rstd = rstd_s;
    float4 gv = *(const float4*)(g + tid * 4);
    float4 bev = *(const float4*)(be + tid * 4);
    float4 o;
    o.x = (v.x - mean) * rstd * gv.x + bev.x;
    o.y = (v.y - mean) * rstd * gv.y + bev.y;
    o.z = (v.z - mean) * rstd * gv.z + bev.z;
    o.w = (v.w - mean) * rstd * gv.w + bev.w;
    *(float4*)(out + base) = o;
}

// ---------------- launch ----------------
extern "C" void kernel_launch(void* const* d_in, const int* in_sizes, int n_in,
                              void* d_out, int out_size)
{
    const float* x       = (const float*)d_in[0];
    const float* premix1 = (const float*)d_in[1];
    const float* e1w1    = (const float*)d_in[2];
    const float* e1b1    = (const float*)d_in[3];
    const float* e1w2    = (const float*)d_in[4];
    const float* e1b2    = (const float*)d_in[5];
    const float* premix2 = (const float*)d_in[6];
    const float* e2w1    = (const float*)d_in[7];
    const float* e2b1    = (const float*)d_in[8];
    const float* e2w2    = (const float*)d_in[9];
    const float* e2b2    = (const float*)d_in[10];
    const float* wqkv    = (const float*)d_in[11];
    const float* bqkv    = (const float*)d_in[12];
    const float* wo      = (const float*)d_in[13];
    const float* bo      = (const float*)d_in[14];
    const float* rot     = (const float*)d_in[15];
    const float* ln1g    = (const float*)d_in[16];
    const float* ln1b    = (const float*)d_in[17];
    const float* ln2g    = (const float*)d_in[18];
    const float* ln2b    = (const float*)d_in[19];
    const float* emb     = (const float*)d_in[20];
    const float* mw1     = (const float*)d_in[21];
    const float* mb1     = (const float*)d_in[22];
    const float* mw2     = (const float*)d_in[23];
    const float* mb2     = (const float*)d_in[24];
    const int*   ph      = (const int*)d_in[25];
    float* out = (float*)d_out;

    float *pH, *pE, *pG, *pXA, *pQKV, *pT, *pX1;
    int *pBk, *pIdx, *pBs;
    __nv_bfloat16 *aH, *aL, *eH, *eL, *fH, *wH, *wL;
    cudaGetSymbolAddress((void**)&pH, g_bufH);
    cudaGetSymbolAddress((void**)&pE, g_bufE);
    cudaGetSymbolAddress((void**)&pG, g_bufG);
    cudaGetSymbolAddress((void**)&pXA, g_bufXA);
    cudaGetSymbolAddress((void**)&pQKV, g_bufQKV);
    cudaGetSymbolAddress((void**)&pT, g_bufT);
    cudaGetSymbolAddress((void**)&pX1, g_bufX1);
    cudaGetSymbolAddress((void**)&pBk, g_buckets);
    cudaGetSymbolAddress((void**)&pIdx, g_idx);
    cudaGetSymbolAddress((void**)&pBs, g_bsort);
    cudaGetSymbolAddress((void**)&aH, g_a16h);
    cudaGetSymbolAddress((void**)&aL, g_a16l);
    cudaGetSymbolAddress((void**)&eH, g_e16h);
    cudaGetSymbolAddress((void**)&eL, g_e16l);
    cudaGetSymbolAddress((void**)&fH, g_f16h);
    cudaGetSymbolAddress((void**)&wH, g_wth);
    cudaGetSymbolAddress((void**)&wL, g_wtl);

    cudaFuncSetAttribute(bgemm2_kernel<ACT_NONE, 0>, cudaFuncAttributeMaxDynamicSharedMemorySize, BG_DSM);
    cudaFuncSetAttribute(bgemm2_kernel<ACT_SILU, 1>, cudaFuncAttributeMaxDynamicSharedMemorySize, BG_DSM);
    cudaFuncSetAttribute(bgemm2_kernel<ACT_SIGMOID, 0>, cudaFuncAttributeMaxDynamicSharedMemorySize, BG_DSM);
    cudaFuncSetAttribute(bgemmh_kernel<ACT_GELU, 2>, cudaFuncAttributeMaxDynamicSharedMemorySize, BH_DSM);
    cudaFuncSetAttribute(bgemmh_kernel<ACT_NONE, 0>, cudaFuncAttributeMaxDynamicSharedMemorySize, BH_DSM);

    // ---- side stream + events (host infra, created once outside capture) ----
    static cudaStream_t s_side = nullptr;
    static cudaEvent_t s_ev_fork = nullptr, s_ev_join = nullptr;
    static cudaEvent_t s_ev_fork2 = nullptr, s_ev_join2 = nullptr;
    if (s_side == nullptr) {
        cudaStreamCreateWithFlags(&s_side, cudaStreamNonBlocking);
        cudaEventCreateWithFlags(&s_ev_fork, cudaEventDisableTiming);
        cudaEventCreateWithFlags(&s_ev_join, cudaEventDisableTiming);
        cudaEventCreateWithFlags(&s_ev_fork2, cudaEventDisableTiming);
        cudaEventCreateWithFlags(&s_ev_join2, cudaEventDisableTiming);
    }

    const int ew_blocks = Mrows * Dc / (256 * 4);
    dim3 tsb(32, 8);

    // ---- fork #1: weight transpose/split on side stream, overlapped with elapsic1 ----
    cudaEventRecord(s_ev_fork, 0);
    cudaStreamWaitEvent(s_side, s_ev_fork, 0);
    tsplit_kernel<<<dim3(QKVW / 32, Dc / 32), tsb, 0, s_side>>>(wqkv, wH + OFF_QKV, wL + OFF_QKV, Dc, QKVW);
    tsplit_kernel<<<dim3(Dc / 32, Dc / 32), tsb, 0, s_side>>>(wo, wH + OFF_WO, wL + OFF_WO, Dc, Dc);
    tsplit_kernel<<<dim3(Ec / 32, Dc / 32), tsb, 0, s_side>>>(e2w1, wH + OFF_E2W1, wL + OFF_E2W1, Dc, Ec);
    tsplit_kernel<<<dim3(Dc / 32, Ec / 32), tsb, 0, s_side>>>(e2w2, wH + OFF_E2W2, wL + OFF_E2W2, Ec, Dc);
    tsplit16_kernel<<<dim3(Fc / 32, Dc / 32), tsb, 0, s_side>>>(mw1, (__half*)(wH + OFF_MW1), Dc, Fc);
    tsplit16_kernel<<<dim3(Dc / 32, Fc / 32), tsb, 0, s_side>>>(mw2, (__half*)(wH + OFF_MW2), Fc, Dc);
    cudaEventRecord(s_ev_join, s_side);

    // ---- time_elapsic 1 (fp32 exact: feeds the LSH bucket path) [main stream] ----
    build_h_kernel<<<ew_blocks, 256>>>(x, premix1, pH, nullptr, nullptr);
    sgemm_kernel<ACT_SILU><<<dim3(Ec / 128, Mrows / 128), 256>>>(pH, e1w1, e1b1, pE, Mrows, Ec, Dc, Ec, Ec);
    sgemm_kernel<ACT_SIGMOID><<<dim3(Dc / 128, Mrows / 128), 256>>>(pE, e1w2, e1b2, pG, Mrows, Dc, Ec, Dc, Dc);
    combine_kernel<<<ew_blocks, 256>>>(x, pG, pXA, aH, aL, nullptr);

    // main stream must see split weights before Q/V bgemm
    cudaStreamWaitEvent(0, s_ev_join, 0);

    // ---- fork #2: fp32 K-projection + hash + sort on side stream, overlapped with Q/V bgemms ----
    cudaEventRecord(s_ev_fork2, 0);
    cudaStreamWaitEvent(s_side, s_ev_fork2, 0);
    sgemm_kernel<ACT_NONE><<<dim3(8, Mrows / 128), 256, 0, s_side>>>(pXA, wqkv + 1024, bqkv + 1024, pQKV + 1024, Mrows, 1024, Dc, QKVW, QKVW);
    hash_kernel<<<dim3(Sc / 128, Bc * Hc), 128, 0, s_side>>>(pQKV, rot, pBk);
    sort_kernel<<<Bc * Hc, 64, 0, s_side>>>(pBk, pIdx, pBs);
    cudaEventRecord(s_ev_join2, s_side);

    bgemm2_kernel<ACT_NONE, 0><<<dim3(8, 128), 256, BG_DSM>>>(aH, aL, Dc, wH + OFF_QKV, wL + OFF_QKV, bqkv, pQKV, nullptr, nullptr, Dc, QKVW);
    bgemm2_kernel<ACT_NONE, 0><<<dim3(8, 128), 256, BG_DSM>>>(aH, aL, Dc, wH + OFF_QKV + (size_t)2048 * Dc, wL + OFF_QKV + (size_t)2048 * Dc, bqkv + 2048, pQKV + 2048, nullptr, nullptr, Dc, QKVW);

    // join: attn needs K cols + idx/bsort written by the side stream
    cudaStreamWaitEvent(0, s_ev_join2, 0);

    attn_kernel<<<dim3(NCHUNK, Bc * Hc), 128>>>(pQKV, pIdx, pBs, aH, aL);  // ATT planes overwrite XA planes
    bgemm2_kernel<ACT_NONE, 0><<<dim3(8, 128), 256, BG_DSM>>>(aH, aL, Dc, wH + OFF_WO, wL + OFF_WO, bo, pT, nullptr, nullptr, Dc, Dc);
    ln_add_kernel<<<Mrows, 256>>>(x, pT, ln1g, ln1b, pX1);

    // ---- time_elapsic 2 (tensor bf16x3) ----
    build_h_kernel<<<ew_blocks, 256>>>(pX1, premix2, pH, aH, aL);
    bgemm2_kernel<ACT_SILU, 1><<<dim3(2, 128), 256, BG_DSM>>>(aH, aL, Dc, wH + OFF_E2W1, wL + OFF_E2W1, e2b1, nullptr, eH, eL, Dc, Ec);
    bgemm2_kernel<ACT_SIGMOID, 0><<<dim3(8, 128), 256, BG_DSM>>>(eH, eL, Ec, wH + OFF_E2W2, wL + OFF_E2W2, e2b2, pG, nullptr, nullptr, Ec, Dc);
    combine_kernel<<<ew_blocks, 256>>>(pX1, pG, pXA, nullptr, nullptr, (__half*)aH);

    // ---- MLP fp16 x1 + deepembed + LN2 ----
    bgemmh_kernel<ACT_GELU, 2><<<dim3(32, 128), 256, BH_DSM>>>((const __half*)aH, Dc, (const __half*)(wH + OFF_MW1), mb1, nullptr, (__half*)fH, Dc, Fc);
    bgemmh_kernel<ACT_NONE, 0><<<dim3(8, 128), 256, BH_DSM>>>((const __half*)fH, Fc, (const __half*)(wH + OFF_MW2), mb2, pT, nullptr, Fc, Dc);
    ln_emb_kernel<<<Mrows, 256>>>(pX1, pT, emb, ph, ln2g, ln2b, out);
}

// round 17
// speedup vs baseline: 3.1233x; 1.1587x over previous
#include <cuda_runtime.h>
#include <cuda_bf16.h>
#include <cuda_fp16.h>
#include <math.h>
#include <stdint.h>

// ---------------- problem constants ----------------
#define Bc 4
#define Sc 4096
#define Dc 1024
#define Hc 16
#define Dhc 64
#define Ec 256
#define Fc 4096
#define CHUNKc 128
#define Mrows (Bc * Sc)          // 16384
#define QKVW (3 * Hc * Dhc)      // 3072
#define NCHUNK (Sc / CHUNKc)     // 32

// weight-plane offsets (elements) inside g_wt16
#define OFF_QKV  0
#define OFF_WO   3145728
#define OFF_E2W1 4194304
#define OFF_E2W2 4456448
#define OFF_MW1  4718592
#define OFF_MW2  8912896
#define WT_TOT   13107200

// ---------------- scratch (device globals; no allocations allowed) ----------------
__device__ float g_bufH[(size_t)Mrows * Dc];
__device__ float g_bufE[(size_t)Mrows * Ec];
__device__ float g_bufG[(size_t)Mrows * Dc];
__device__ float g_bufXA[(size_t)Mrows * Dc];
__device__ float g_bufQKV[(size_t)Mrows * QKVW];
__device__ float g_bufT[(size_t)Mrows * Dc];
__device__ float g_bufX1[(size_t)Mrows * Dc];
__device__ int g_buckets[Bc * Hc * Sc];
__device__ int g_idx[Bc * Hc * Sc];
__device__ int g_bsort[Bc * Hc * Sc];
// fp16 planes
__device__ __half g_a16[(size_t)Mrows * Dc];
__device__ __half g_e16[(size_t)Mrows * Ec];
__device__ __half g_f16[(size_t)Mrows * Fc];
__device__ __half g_wt16[WT_TOT];

// ---------------- activations ----------------
enum { ACT_NONE = 0, ACT_SILU = 1, ACT_GELU = 2, ACT_SIGMOID = 3 };

template <int ACT>
__device__ __forceinline__ float apply_act(float x) {
    if (ACT == ACT_SILU) return x / (1.f + __expf(-x));
    if (ACT == ACT_GELU) {
        float t = tanhf(0.7978845608028654f * (x + 0.044715f * x * x * x));
        return 0.5f * x * (1.f + t);
    }
    if (ACT == ACT_SIGMOID) return 1.f / (1.f + __expf(-x));
    return x;
}

__device__ __forceinline__ uint32_t smem_u32(const void* p) {
    uint32_t a;
    asm("{ .reg .u64 t; cvta.to.shared.u64 t, %1; cvt.u32.u64 %0, t; }" : "=r"(a) : "l"(p));
    return a;
}
__device__ __forceinline__ uint32_t pack_h2(__half a, __half b) {
    __half2 t; t.x = a; t.y = b;
    return *(uint32_t*)&t;
}
__device__ __forceinline__ void cpa16(uint32_t dst, const void* src) {
    asm volatile("cp.async.cg.shared.global [%0], [%1], 16;" :: "r"(dst), "l"(src));
}
__device__ __forceinline__ void mma16816h(float* c, const uint32_t* a, const uint32_t* b) {
    asm volatile(
        "mma.sync.aligned.m16n8k16.row.col.f32.f16.f16.f32 "
        "{%0,%1,%2,%3}, {%4,%5,%6,%7}, {%8,%9}, {%0,%1,%2,%3};"
        : "+f"(c[0]), "+f"(c[1]), "+f"(c[2]), "+f"(c[3])
        : "r"(a[0]), "r"(a[1]), "r"(a[2]), "r"(a[3]), "r"(b[0]), "r"(b[1]));
}
__device__ __forceinline__ void ldm4(uint32_t* d, uint32_t addr) {
    asm volatile("ldmatrix.sync.aligned.m8n8.x4.shared.b16 {%0,%1,%2,%3}, [%4];"
                 : "=r"(d[0]), "=r"(d[1]), "=r"(d[2]), "=r"(d[3]) : "r"(addr));
}

// ---------------- weight transpose fp16: W[K,N] -> [N,K] ----------------
__global__ void tsplit16_kernel(const float* __restrict__ W,
                                __half* __restrict__ T, int K, int N)
{
    __shared__ float t[32][33];
    int n0 = blockIdx.x * 32, k0 = blockIdx.y * 32;
    int tx = threadIdx.x, ty = threadIdx.y;
#pragma unroll
    for (int i = 0; i < 4; i++) {
        int k = k0 + ty + i * 8;
        t[ty + i * 8][tx] = W[(size_t)k * N + n0 + tx];
    }
    __syncthreads();
#pragma unroll
    for (int i = 0; i < 4; i++) {
        int n = n0 + ty + i * 8;
        T[(size_t)n * K + k0 + tx] = __float2half(t[tx][ty + i * 8]);
    }
}

// ============ fp16 x1 HMMA GEMM: cp.async double buffering + ldmatrix ============
#define BH_ST 5120       // elems per plane per stage (128*40)
#define BH_STAGE 10240   // 2 planes (A, B)
#define BH_DSM (2 * BH_STAGE * 2)  // 40960 bytes

__device__ __forceinline__ void bh_stage(
    uint32_t sbase, int s, int c, int tid, int row0, int n0,
    const __half* __restrict__ A, int lda, const __half* __restrict__ Bt, int K)
{
    int k0 = c * 32;
#pragma unroll
    for (int j = 0; j < 2; j++) {
        int c2 = tid + j * 256;
        int row = c2 >> 2, seg = (c2 & 3) << 3;
        uint32_t off = sbase + (uint32_t)(s * BH_STAGE + row * 40 + seg) * 2;
        cpa16(off,             A + (size_t)(row0 + row) * lda + k0 + seg);
        cpa16(off + BH_ST * 2, Bt + (size_t)(n0 + row) * K + k0 + seg);
    }
}

// OMODE: 0 = fp32 out, 2 = fp16 out
template <int ACT, int OMODE>
__global__ __launch_bounds__(256, 2) void bgemmh_kernel(
    const __half* __restrict__ A, int lda, const __half* __restrict__ Bt,
    const float* __restrict__ bias, float* __restrict__ C, __half* __restrict__ C16,
    int K, int ldc)
{
    extern __shared__ __align__(16) char dsm[];
    uint32_t sbase = smem_u32(dsm);

    int tid = threadIdx.x;
    int wid = tid >> 5, lane = tid & 31;
    int n0 = blockIdx.x * 128;
    int row0 = blockIdx.y * 128;
    int wm = (wid & 1) * 64;
    int wn = (wid >> 1) * 32;
    int lr = lane >> 2;
    int lc = (lane & 3) * 2;

    int a_row_off = (lane & 15);
    int a_col_off = (lane >> 4) * 8;
    int b_row_off = (lane & 7) + (lane >> 4) * 8;
    int b_col_off = ((lane >> 3) & 1) * 8;

    float acc[4][4][4];
#pragma unroll
    for (int mt = 0; mt < 4; mt++)
#pragma unroll
        for (int nt = 0; nt < 4; nt++)
#pragma unroll
            for (int e = 0; e < 4; e++) acc[mt][nt][e] = 0.f;

    int nch = K >> 5;
    bh_stage(sbase, 0, 0, tid, row0, n0, A, lda, Bt, K);
    asm volatile("cp.async.commit_group;");

    for (int c = 0; c < nch; c++) {
        if (c + 1 < nch) {
            bh_stage(sbase, (c + 1) & 1, c + 1, tid, row0, n0, A, lda, Bt, K);
            asm volatile("cp.async.commit_group;");
            asm volatile("cp.async.wait_group 1;");
        } else {
            asm volatile("cp.async.wait_group 0;");
        }
        __syncthreads();

        int s = c & 1;
        uint32_t pA = sbase + (uint32_t)(s * BH_STAGE) * 2;
        uint32_t pB = pA + BH_ST * 2;

#pragma unroll
        for (int kt = 0; kt < 32; kt += 16) {
            uint32_t bfr[4][2];
#pragma unroll
            for (int np = 0; np < 2; np++) {
                uint32_t off = (uint32_t)((wn + np * 16 + b_row_off) * 40 + kt + b_col_off) * 2;
                uint32_t d[4];
                ldm4(d, pB + off);
                bfr[np * 2][0] = d[0]; bfr[np * 2][1] = d[1];
                bfr[np * 2 + 1][0] = d[2]; bfr[np * 2 + 1][1] = d[3];
            }
#pragma unroll
            for (int mt = 0; mt < 4; mt++) {
                uint32_t off = (uint32_t)((wm + mt * 16 + a_row_off) * 40 + kt + a_col_off) * 2;
                uint32_t afr[4];
                ldm4(afr, pA + off);
#pragma unroll
                for (int nt = 0; nt < 4; nt++) {
                    mma16816h(acc[mt][nt], afr, bfr[nt]);
                }
            }
        }
        __syncthreads();
    }

    // ---- epilogue ----
#pragma unroll
    for (int mt = 0; mt < 4; mt++) {
        int row = row0 + wm + mt * 16 + lr;
#pragma unroll
        for (int nt = 0; nt < 4; nt++) {
            int col = n0 + wn + nt * 8 + lc;
            float b0 = bias[col], b1 = bias[col + 1];
            float v00 = apply_act<ACT>(acc[mt][nt][0] + b0);
            float v01 = apply_act<ACT>(acc[mt][nt][1] + b1);
            float v10 = apply_act<ACT>(acc[mt][nt][2] + b0);
            float v11 = apply_act<ACT>(acc[mt][nt][3] + b1);
            if (OMODE == 2) {
                *(uint32_t*)&C16[(size_t)row * ldc + col] =
                    pack_h2(__float2half(v00), __float2half(v01));
                *(uint32_t*)&C16[(size_t)(row + 8) * ldc + col] =
                    pack_h2(__float2half(v10), __float2half(v11));
            } else {
                *(float2*)(C + (size_t)row * ldc + col) = make_float2(v00, v01);
                *(float2*)(C + (size_t)(row + 8) * ldc + col) = make_float2(v10, v11);
            }
        }
    }
}

// ---------------- fp32 SGEMM (bucket-exact path) ----------------
template <int ACT>
__global__ __launch_bounds__(256, 2) void sgemm_kernel(
    const float* __restrict__ A, const float* __restrict__ B,
    const float* __restrict__ bias, float* __restrict__ C,
    int M, int N, int K, int ldb, int ldc)
{
    __shared__ __align__(16) float As[2][128][20];
    __shared__ __align__(16) float Bs[2][16][128];
    int tid = threadIdx.x;
    int col0 = blockIdx.x * 128;
    int row0 = blockIdx.y * 128;
    int ty = tid >> 4, tx = tid & 15;

    float acc[8][8];
#pragma unroll
    for (int i = 0; i < 8; i++)
#pragma unroll
        for (int j = 0; j < 8; j++) acc[i][j] = 0.f;

    const float* Ablk = A + (size_t)row0 * K;
    const float* Bblk = B + col0;
    int nch = K >> 4;

    auto stage = [&](int s, int c) {
        int k0 = c << 4;
#pragma unroll
        for (int j = 0; j < 2; j++) {
            int idx = tid + j * 256;
            int ar = idx >> 2, ac4 = (idx & 3) << 2;
            cpa16(smem_u32(&As[s][ar][ac4]), Ablk + (size_t)ar * K + k0 + ac4);
            int br = idx >> 5, bc = (idx & 31) << 2;
            cpa16(smem_u32(&Bs[s][br][bc]), Bblk + (size_t)(k0 + br) * ldb + bc);
        }
    };

    stage(0, 0);
    asm volatile("cp.async.commit_group;");

    for (int c = 0; c < nch; c++) {
        if (c + 1 < nch) {
            stage((c + 1) & 1, c + 1);
            asm volatile("cp.async.commit_group;");
            asm volatile("cp.async.wait_group 1;");
        } else {
            asm volatile("cp.async.wait_group 0;");
        }
        __syncthreads();
        int s = c & 1;
#pragma unroll
        for (int kk = 0; kk < 16; kk++) {
            float ra[8], rb[8];
#pragma unroll
            for (int i = 0; i < 8; i++) ra[i] = As[s][ty * 8 + i][kk];
            *(float4*)(rb) = *(const float4*)&Bs[s][kk][tx * 8];
            *(float4*)(rb + 4) = *(const float4*)&Bs[s][kk][tx * 8 + 4];
#pragma unroll
            for (int i = 0; i < 8; i++)
#pragma unroll
                for (int j = 0; j < 8; j++) acc[i][j] += ra[i] * rb[j];
        }
        __syncthreads();
    }

#pragma unroll
    for (int i = 0; i < 8; i++) {
        size_t r = (size_t)row0 + ty * 8 + i;
#pragma unroll
        for (int j = 0; j < 8; j += 4) {
            int c = col0 + tx * 8 + j;
            float4 o;
            o.x = apply_act<ACT>(acc[i][j + 0] + bias[c + 0]);
            o.y = apply_act<ACT>(acc[i][j + 1] + bias[c + 1]);
            o.z = apply_act<ACT>(acc[i][j + 2] + bias[c + 2]);
            o.w = apply_act<ACT>(acc[i][j + 3] + bias[c + 3]);
            *(float4*)(C + r * ldc + c) = o;
        }
    }
}

// ---------------- time_elapsic helpers (optionally emit fp16 plane) ----------------
__global__ void build_h_kernel(const float* __restrict__ x,
                               const float* __restrict__ premix,
                               float* __restrict__ out,
                               __half* __restrict__ oF)
{
    size_t i4 = (size_t)blockIdx.x * blockDim.x + threadIdx.x;
    size_t base = i4 * 4;
    int d = (int)(base & (Dc - 1));
    int row = (int)(base >> 10);
    int s = row & (Sc - 1);
    float4 xv = *(const float4*)(x + base);
    float4 pv = (s > 0) ? *(const float4*)(x + base - Dc) : make_float4(0.f, 0.f, 0.f, 0.f);
    float4 pm = *(const float4*)(premix + d);
    float4 o;
    o.x = xv.x + (pv.x - xv.x) * pm.x;
    o.y = xv.y + (pv.y - xv.y) * pm.y;
    o.z = xv.z + (pv.z - xv.z) * pm.z;
    o.w = xv.w + (pv.w - xv.w) * pm.w;
    *(float4*)(out + base) = o;
    if (oF) {
        *(uint2*)&oF[base] = make_uint2(
            pack_h2(__float2half(o.x), __float2half(o.y)),
            pack_h2(__float2half(o.z), __float2half(o.w)));
    }
}

__global__ void combine_kernel(const float* __restrict__ x,
                               const float* __restrict__ gate,
                               float* __restrict__ out,
                               __half* __restrict__ oF)
{
    size_t i4 = (size_t)blockIdx.x * blockDim.x + threadIdx.x;
    size_t base = i4 * 4;
    int row = (int)(base >> 10);
    int s = row & (Sc - 1);
    float4 xv = *(const float4*)(x + base);
    float4 pv = (s > 0) ? *(const float4*)(x + base - Dc) : make_float4(0.f, 0.f, 0.f, 0.f);
    float4 gv = *(const float4*)(gate + base);
    float4 o;
    o.x = xv.x + (pv.x - xv.x) * gv.x;
    o.y = xv.y + (pv.y - xv.y) * gv.y;
    o.z = xv.z + (pv.z - xv.z) * gv.z;
    o.w = xv.w + (pv.w - xv.w) * gv.w;
    *(float4*)(out + base) = o;
    if (oF) {
        *(uint2*)&oF[base] = make_uint2(
            pack_h2(__float2half(o.x), __float2half(o.y)),
            pack_h2(__float2half(o.z), __float2half(o.w)));
    }
}

// ---------------- LSH hashing ----------------
__global__ void hash_kernel(const float* __restrict__ qkv,
                            const float* __restrict__ rot,
                            int* __restrict__ buckets)
{
    int bh = blockIdx.y;
    int b = bh >> 4, h = bh & 15;
    int s = blockIdx.x * 128 + threadIdx.x;
    __shared__ float rotS[Dhc * 32];
    for (int i = threadIdx.x; i < Dhc * 32; i += 128) rotS[i] = rot[h * (Dhc * 32) + i];
    __syncthreads();
    const float* kp = qkv + ((size_t)(b * Sc + s) * QKVW) + (Hc + h) * Dhc;
    float r[32];
#pragma unroll
    for (int n = 0; n < 32; n++) r[n] = 0.f;
    for (int d = 0; d < Dhc; d++) {
        float kd = kp[d];
#pragma unroll
        for (int n = 0; n < 32; n++) r[n] += kd * rotS[d * 32 + n];
    }
    float best = r[0];
    int bi = 0;
#pragma unroll
    for (int n = 1; n < 32; n++)
        if (r[n] > best) { best = r[n]; bi = n; }
#pragma unroll
    for (int n = 0; n < 32; n++)
        if (-r[n] > best) { best = -r[n]; bi = 32 + n; }
    buckets[(size_t)bh * Sc + s] = bi;
}

// ---------------- stable counting sort per (b,h) row ----------------
__global__ void sort_kernel(const int* __restrict__ buckets,
                            int* __restrict__ idx, int* __restrict__ bsort)
{
    int bh = blockIdx.x;
    int t = threadIdx.x;
    __shared__ int sb[Sc];
    __shared__ int cnt[64][64];
    __shared__ int base[64];
    const int* row = buckets + (size_t)bh * Sc;
    for (int i = t; i < Sc; i += 64) sb[i] = row[i];
    for (int v = 0; v < 64; v++) cnt[t][v] = 0;
    __syncthreads();
    for (int i = t * 64; i < t * 64 + 64; i++) cnt[t][sb[i]]++;
    __syncthreads();
    {
        int run = 0;
        for (int seg = 0; seg < 64; seg++) {
            int c = cnt[seg][t];
            cnt[seg][t] = run;
            run += c;
        }
        base[t] = run;
    }
    __syncthreads();
    if (t == 0) {
        int acc = 0;
        for (int v = 0; v < 64; v++) { int c = base[v]; base[v] = acc; acc += c; }
    }
    __syncthreads();
    int* idxrow = idx + (size_t)bh * Sc;
    int* bsrow = bsort + (size_t)bh * Sc;
    for (int i = t * 64; i < t * 64 + 64; i++) {
        int v = sb[i];
        int p = base[v] + cnt[t][v]++;
        idxrow[p] = i;
        bsrow[p] = v;
    }
}

// ---------------- chunked bucket-masked attention (writes fp16 plane) ----------------
__global__ __launch_bounds__(128) void attn_kernel(
    const float* __restrict__ qkv, const int* __restrict__ idx,
    const int* __restrict__ bsort, __half* __restrict__ yF)
{
    int n = blockIdx.x;
    int bh = blockIdx.y;
    int b = bh >> 4, h = bh & 15;
    int tid = threadIdx.x;
    const int* idxrow = idx + (size_t)bh * Sc;
    const int* bsrow = bsort + (size_t)bh * Sc;

    int pq = n * CHUNKc + tid;
    int orig_q = idxrow[pq];
    int bq = bsrow[pq];
    const float* qptr = qkv + ((size_t)(b * Sc + orig_q) * QKVW) + h * Dhc;
    float4 qreg[16];
#pragma unroll
    for (int f = 0; f < 16; f++) qreg[f] = *(const float4*)(qptr + f * 4);

    float4 acc[16];
#pragma unroll
    for (int f = 0; f < 16; f++) acc[f] = make_float4(0.f, 0.f, 0.f, 0.f);
    float m = -1e30f, l = 0.f;

    __shared__ float4 KS[64 * 16];
    __shared__ float4 VS[64 * 16];
    __shared__ int BK[64];

    for (int tile = 0; tile < 4; tile++) {
        int t0 = tile * 64;
        for (int w = tid; w < 64 * 16; w += 128) {
            int slot = w >> 4, f = w & 15;
            int kslot = t0 + slot;
            int spos;
            bool ok;
            if (kslot < CHUNKc) { ok = (n > 0); spos = (n - 1) * CHUNKc + kslot; }
            else                { ok = true;    spos = n * CHUNKc + (kslot - CHUNKc); }
            if (ok) {
                int og = idxrow[spos];
                const float* kp = qkv + ((size_t)(b * Sc + og) * QKVW) + (Hc + h) * Dhc;
                KS[slot * 16 + f] = *(const float4*)(kp + f * 4);
                VS[slot * 16 + f] = *(const float4*)(kp + Hc * Dhc + f * 4);
                if (f == 0) BK[slot] = bsrow[spos];
            } else if (f == 0) {
                BK[slot] = -1;
            }
        }
        __syncthreads();
        for (int s = 0; s < 64; s++) {
            if (BK[s] != bq) continue;
            const float4* kp4 = &KS[s * 16];
            float dot = 0.f;
#pragma unroll
            for (int f = 0; f < 16; f++) {
                float4 kv = kp4[f];
                dot += qreg[f].x * kv.x + qreg[f].y * kv.y + qreg[f].z * kv.z + qreg[f].w * kv.w;
            }
            dot *= 0.125f;
            float p;
            if (dot > m) {
                float sc = __expf(m - dot);
                l *= sc;
#pragma unroll
                for (int f = 0; f < 16; f++) {
                    acc[f].x *= sc; acc[f].y *= sc; acc[f].z *= sc; acc[f].w *= sc;
                }
                m = dot;
                p = 1.f;
            } else {
                p = __expf(dot - m);
            }
            l += p;
            const float4* vp4 = &VS[s * 16];
#pragma unroll
            for (int f = 0; f < 16; f++) {
                float4 vv = vp4[f];
                acc[f].x += p * vv.x; acc[f].y += p * vv.y;
                acc[f].z += p * vv.z; acc[f].w += p * vv.w;
            }
        }
        __syncthreads();
    }
    float inv = 1.f / l;
    size_t ybase = ((size_t)(b * Sc + orig_q)) * Dc + h * Dhc;
#pragma unroll
    for (int f = 0; f < 16; f++) {
        float4 o = acc[f];
        o.x *= inv; o.y *= inv; o.z *= inv; o.w *= inv;
        *(uint2*)&yF[ybase + f * 4] = make_uint2(
            pack_h2(__float2half(o.x), __float2half(o.y)),
            pack_h2(__float2half(o.z), __float2half(o.w)));
    }
}

// ---------------- LayerNorm(a + b) ----------------
__global__ void ln_add_kernel(const float* __restrict__ a, const float* __restrict__ bsum,
                              const float* __restrict__ g, const float* __restrict__ be,
                              float* __restrict__ out)
{
    int r = blockIdx.x, tid = threadIdx.x;
    size_t base = (size_t)r * Dc + tid * 4;
    float4 av = *(const float4*)(a + base);
    float4 bv = *(const float4*)(bsum + base);
    float4 v = make_float4(av.x + bv.x, av.y + bv.y, av.z + bv.z, av.w + bv.w);
    float s = v.x + v.y + v.z + v.w;
    float s2 = v.x * v.x + v.y * v.y + v.z * v.z + v.w * v.w;
    for (int o = 16; o > 0; o >>= 1) {
        s += __shfl_down_sync(~0u, s, o);
        s2 += __shfl_down_sync(~0u, s2, o);
    }
    __shared__ float ws[8], ws2[8];
    __shared__ float mean_s, rstd_s;
    int w = tid >> 5, ln = tid & 31;
    if (ln == 0) { ws[w] = s; ws2[w] = s2; }
    __syncthreads();
    if (tid == 0) {
        float S = 0.f, S2 = 0.f;
        for (int i = 0; i < 8; i++) { S += ws[i]; S2 += ws2[i]; }
        float mean = S * (1.f / Dc);
        float var = S2 * (1.f / Dc) - mean * mean;
        mean_s = mean;
        rstd_s = rsqrtf(var + 1e-5f);
    }
    __syncthreads();
    float mean = mean_s, rstd = rstd_s;
    float4 gv = *(const float4*)(g + tid * 4);
    float4 bev = *(const float4*)(be + tid * 4);
    float4 o;
    o.x = (v.x - mean) * rstd * gv.x + bev.x;
    o.y = (v.y - mean) * rstd * gv.y + bev.y;
    o.z = (v.z - mean) * rstd * gv.z + bev.z;
    o.w = (v.w - mean) * rstd * gv.w + bev.w;
    *(float4*)(out + base) = o;
}

// ---------------- LayerNorm(x1 + t * emb[ph]) ----------------
__global__ void ln_emb_kernel(const float* __restrict__ x1, const float* __restrict__ tin,
                              const float* __restrict__ emb, const int* __restrict__ ph,
                              const float* __restrict__ g, const float* __restrict__ be,
                              float* __restrict__ out)
{
    int r = blockIdx.x, tid = threadIdx.x;
    size_t base = (size_t)r * Dc + tid * 4;
    const float* er = emb + (size_t)ph[r] * Dc;
    float4 av = *(const float4*)(x1 + base);
    float4 tv = *(const float4*)(tin + base);
    float4 ev = *(const float4*)(er + tid * 4);
    float4 v = make_float4(av.x + tv.x * ev.x, av.y + tv.y * ev.y,
                           av.z + tv.z * ev.z, av.w + tv.w * ev.w);
    float s = v.x + v.y + v.z + v.w;
    float s2 = v.x * v.x + v.y * v.y + v.z * v.z + v.w * v.w;
    for (int o = 16; o > 0; o >>= 1) {
        s += __shfl_down_sync(~0u, s, o);
        s2 += __shfl_down_sync(~0u, s2, o);
    }
    __shared__ float ws[8], ws2[8];
    __shared__ float mean_s, rstd_s;
    int w = tid >> 5, ln = tid & 31;
    if (ln == 0) { ws[w] = s; ws2[w] = s2; }
    __syncthreads();
    if (tid == 0) {
        float S = 0.f, S2 = 0.f;
        for (int i = 0; i < 8; i++) { S += ws[i]; S2 += ws2[i]; }
        float mean = S * (1.f / Dc);
        float var = S2 * (1.f / Dc) - mean * mean;
        mean_s = mean;
        rstd_s = rsqrtf(var + 1e-5f);
    }
    __syncthreads();
    float mean = mean_s, rstd = rstd_s;
    float4 gv = *(const float4*)(g + tid * 4);
    float4 bev = *(const float4*)(be + tid * 4);
    float4 o;
    o.x = (v.x - mean) * rstd * gv.x + bev.x;
    o.y = (v.y - mean) * rstd * gv.y + bev.y;
    o.z = (v.z - mean) * rstd * gv.z + bev.z;
    o.w = (v.w - mean) * rstd * gv.w + bev.w;
    *(float4*)(out + base) = o;
}

// ---------------- launch ----------------
extern "C" void kernel_launch(void* const* d_in, const int* in_sizes, int n_in,
                              void* d_out, int out_size)
{
    const float* x       = (const float*)d_in[0];
    const float* premix1 = (const float*)d_in[1];
    const float* e1w1    = (const float*)d_in[2];
    const float* e1b1    = (const float*)d_in[3];
    const float* e1w2    = (const float*)d_in[4];
    const float* e1b2    = (const float*)d_in[5];
    const float* premix2 = (const float*)d_in[6];
    const float* e2w1    = (const float*)d_in[7];
    const float* e2b1    = (const float*)d_in[8];
    const float* e2w2    = (const float*)d_in[9];
    const float* e2b2    = (const float*)d_in[10];
    const float* wqkv    = (const float*)d_in[11];
    const float* bqkv    = (const float*)d_in[12];
    const float* wo      = (const float*)d_in[13];
    const float* bo      = (const float*)d_in[14];
    const float* rot     = (const float*)d_in[15];
    const float* ln1g    = (const float*)d_in[16];
    const float* ln1b    = (const float*)d_in[17];
    const float* ln2g    = (const float*)d_in[18];
    const float* ln2b    = (const float*)d_in[19];
    const float* emb     = (const float*)d_in[20];
    const float* mw1     = (const float*)d_in[21];
    const float* mb1     = (const float*)d_in[22];
    const float* mw2     = (const float*)d_in[23];
    const float* mb2     = (const float*)d_in[24];
    const int*   ph      = (const int*)d_in[25];
    float* out = (float*)d_out;

    float *pH, *pE, *pG, *pXA, *pQKV, *pT, *pX1;
    int *pBk, *pIdx, *pBs;
    __half *aF, *eF, *fF, *wF;
    cudaGetSymbolAddress((void**)&pH, g_bufH);
    cudaGetSymbolAddress((void**)&pE, g_bufE);
    cudaGetSymbolAddress((void**)&pG, g_bufG);
    cudaGetSymbolAddress((void**)&pXA, g_bufXA);
    cudaGetSymbolAddress((void**)&pQKV, g_bufQKV);
    cudaGetSymbolAddress((void**)&pT, g_bufT);
    cudaGetSymbolAddress((void**)&pX1, g_bufX1);
    cudaGetSymbolAddress((void**)&pBk, g_buckets);
    cudaGetSymbolAddress((void**)&pIdx, g_idx);
    cudaGetSymbolAddress((void**)&pBs, g_bsort);
    cudaGetSymbolAddress((void**)&aF, g_a16);
    cudaGetSymbolAddress((void**)&eF, g_e16);
    cudaGetSymbolAddress((void**)&fF, g_f16);
    cudaGetSymbolAddress((void**)&wF, g_wt16);

    cudaFuncSetAttribute(bgemmh_kernel<ACT_NONE, 0>, cudaFuncAttributeMaxDynamicSharedMemorySize, BH_DSM);
    cudaFuncSetAttribute(bgemmh_kernel<ACT_SILU, 2>, cudaFuncAttributeMaxDynamicSharedMemorySize, BH_DSM);
    cudaFuncSetAttribute(bgemmh_kernel<ACT_SIGMOID, 0>, cudaFuncAttributeMaxDynamicSharedMemorySize, BH_DSM);
    cudaFuncSetAttribute(bgemmh_kernel<ACT_GELU, 2>, cudaFuncAttributeMaxDynamicSharedMemorySize, BH_DSM);

    // ---- side stream + events (host infra, created once outside capture) ----
    static cudaStream_t s_side = nullptr;
    static cudaEvent_t s_ev_fork = nullptr, s_ev_join = nullptr;
    static cudaEvent_t s_ev_fork2 = nullptr, s_ev_join2 = nullptr;
    if (s_side == nullptr) {
        cudaStreamCreateWithFlags(&s_side, cudaStreamNonBlocking);
        cudaEventCreateWithFlags(&s_ev_fork, cudaEventDisableTiming);
        cudaEventCreateWithFlags(&s_ev_join, cudaEventDisableTiming);
        cudaEventCreateWithFlags(&s_ev_fork2, cudaEventDisableTiming);
        cudaEventCreateWithFlags(&s_ev_join2, cudaEventDisableTiming);
    }

    const int ew_blocks = Mrows * Dc / (256 * 4);
    dim3 tsb(32, 8);

    // ---- fork #1: weight transpose (fp16) on side stream, overlapped with elapsic1 ----
    cudaEventRecord(s_ev_fork, 0);
    cudaStreamWaitEvent(s_side, s_ev_fork, 0);
    tsplit16_kernel<<<dim3(QKVW / 32, Dc / 32), tsb, 0, s_side>>>(wqkv, wF + OFF_QKV, Dc, QKVW);
    tsplit16_kernel<<<dim3(Dc / 32, Dc / 32), tsb, 0, s_side>>>(wo, wF + OFF_WO, Dc, Dc);
    tsplit16_kernel<<<dim3(Ec / 32, Dc / 32), tsb, 0, s_side>>>(e2w1, wF + OFF_E2W1, Dc, Ec);
    tsplit16_kernel<<<dim3(Dc / 32, Ec / 32), tsb, 0, s_side>>>(e2w2, wF + OFF_E2W2, Ec, Dc);
    tsplit16_kernel<<<dim3(Fc / 32, Dc / 32), tsb, 0, s_side>>>(mw1, wF + OFF_MW1, Dc, Fc);
    tsplit16_kernel<<<dim3(Dc / 32, Fc / 32), tsb, 0, s_side>>>(mw2, wF + OFF_MW2, Fc, Dc);
    cudaEventRecord(s_ev_join, s_side);

    // ---- time_elapsic 1 (fp32 exact: feeds the LSH bucket path) [main stream] ----
    build_h_kernel<<<ew_blocks, 256>>>(x, premix1, pH, nullptr);
    sgemm_kernel<ACT_SILU><<<dim3(Ec / 128, Mrows / 128), 256>>>(pH, e1w1, e1b1, pE, Mrows, Ec, Dc, Ec, Ec);
    sgemm_kernel<ACT_SIGMOID><<<dim3(Dc / 128, Mrows / 128), 256>>>(pE, e1w2, e1b2, pG, Mrows, Dc, Ec, Dc, Dc);
    combine_kernel<<<ew_blocks, 256>>>(x, pG, pXA, aF);

    // main stream must see fp16 weights before Q/V gemm
    cudaStreamWaitEvent(0, s_ev_join, 0);

    // ---- fork #2: fp32 K-projection + hash + sort on side stream, overlapped with Q/V ----
    cudaEventRecord(s_ev_fork2, 0);
    cudaStreamWaitEvent(s_side, s_ev_fork2, 0);
    sgemm_kernel<ACT_NONE><<<dim3(8, Mrows / 128), 256, 0, s_side>>>(pXA, wqkv + 1024, bqkv + 1024, pQKV + 1024, Mrows, 1024, Dc, QKVW, QKVW);
    hash_kernel<<<dim3(Sc / 128, Bc * Hc), 128, 0, s_side>>>(pQKV, rot, pBk);
    sort_kernel<<<Bc * Hc, 64, 0, s_side>>>(pBk, pIdx, pBs);
    cudaEventRecord(s_ev_join2, s_side);

    bgemmh_kernel<ACT_NONE, 0><<<dim3(8, 128), 256, BH_DSM>>>(aF, Dc, wF + OFF_QKV, bqkv, pQKV, nullptr, Dc, QKVW);
    bgemmh_kernel<ACT_NONE, 0><<<dim3(8, 128), 256, BH_DSM>>>(aF, Dc, wF + OFF_QKV + (size_t)2048 * Dc, bqkv + 2048, pQKV + 2048, nullptr, Dc, QKVW);

    // join: attn needs K cols + idx/bsort written by the side stream
    cudaStreamWaitEvent(0, s_ev_join2, 0);

    attn_kernel<<<dim3(NCHUNK, Bc * Hc), 128>>>(pQKV, pIdx, pBs, aF);  // ATT fp16 plane overwrites XA plane
    bgemmh_kernel<ACT_NONE, 0><<<dim3(8, 128), 256, BH_DSM>>>(aF, Dc, wF + OFF_WO, bo, pT, nullptr, Dc, Dc);
    ln_add_kernel<<<Mrows, 256>>>(x, pT, ln1g, ln1b, pX1);

    // ---- time_elapsic 2 (fp16 tensor) ----
    build_h_kernel<<<ew_blocks, 256>>>(pX1, premix2, pH, aF);
    bgemmh_kernel<ACT_SILU, 2><<<dim3(2, 128), 256, BH_DSM>>>(aF, Dc, wF + OFF_E2W1, e2b1, nullptr, eF, Dc, Ec);
    bgemmh_kernel<ACT_SIGMOID, 0><<<dim3(8, 128), 256, BH_DSM>>>(eF, Ec, wF + OFF_E2W2, e2b2, pG, nullptr, Ec, Dc);
    combine_kernel<<<ew_blocks, 256>>>(pX1, pG, pXA, aF);

    // ---- MLP fp16 + deepembed + LN2 ----
    bgemmh_kernel<ACT_GELU, 2><<<dim3(32, 128), 256, BH_DSM>>>(aF, Dc, wF + OFF_MW1, mb1, nullptr, fF, Dc, Fc);
    bgemmh_kernel<ACT_NONE, 0><<<dim3(8, 128), 256, BH_DSM>>>(fF, Fc, wF + OFF_MW2, mb2, pT, nullptr, Fc, Dc);
    ln_emb_kernel<<<Mrows, 256>>>(pX1, pT, emb, ph, ln2g, ln2b, out);
}